// round 11
// baseline (speedup 1.0000x reference)
#include <cuda_runtime.h>
#include <cuda_bf16.h>
#include <math.h>
#include <stdint.h>

#define LL 2
#define DD 1024
#define HH 16
#define DHH 64
#define DFF 4096
#define BB 2
#define TT 2048
#define OV 4096
#define BT (BB*TT)   // 4096

// ---------------- scratch (device globals; no runtime allocation) ----------------
__device__ float g_x  [BT*DD];
__device__ float g_qkv[(size_t)BT*3*DD];
__device__ float g_b3 [3*DD];
__device__ float g_cos[TT*32];
__device__ float g_sin[TT*32];
// bf16 split operands (16B-aligned for vector access)
__device__ __align__(16) __nv_bfloat16 g_ah[(size_t)BT*DD];    // activation hi [BT,DD]
__device__ __align__(16) __nv_bfloat16 g_al[(size_t)BT*DD];
__device__ __align__(16) __nv_bfloat16 g_fh[(size_t)BT*DFF];   // ff hi [BT,DFF]
__device__ __align__(16) __nv_bfloat16 g_fl[(size_t)BT*DFF];
__device__ __align__(16) __nv_bfloat16 g_bh[(size_t)DFF*DD];   // B^T hi [N,K] (max 4096x1024)
__device__ __align__(16) __nv_bfloat16 g_bl[(size_t)DFF*DD];
// attention split operands
__device__ __align__(16) __nv_bfloat16 g_qh[(size_t)BB*HH*TT*DHH];  // [bh][t][d]
__device__ __align__(16) __nv_bfloat16 g_ql[(size_t)BB*HH*TT*DHH];
__device__ __align__(16) __nv_bfloat16 g_kh[(size_t)BB*HH*TT*DHH];
__device__ __align__(16) __nv_bfloat16 g_kl[(size_t)BB*HH*TT*DHH];
__device__ __align__(16) __nv_bfloat16 g_vh[(size_t)BB*HH*DHH*TT];  // [bh][d][t]
__device__ __align__(16) __nv_bfloat16 g_vl[(size_t)BB*HH*DHH*TT];

// ---------------- warp-MMA primitives (baseline PTX; no sm_103a features) ----------
__device__ __forceinline__ uint32_t smem_u32(const void* p) {
    uint32_t a;
    asm("{ .reg .u64 t; cvta.to.shared.u64 t, %1; cvt.u32.u64 %0, t; }" : "=r"(a) : "l"(p));
    return a;
}
__device__ __forceinline__ void ldm4(uint32_t* r, uint32_t addr) {
    asm volatile("ldmatrix.sync.aligned.m8n8.x4.shared.b16 {%0,%1,%2,%3}, [%4];"
                 : "=r"(r[0]), "=r"(r[1]), "=r"(r[2]), "=r"(r[3]) : "r"(addr));
}
__device__ __forceinline__ void mma16816(float* d, const uint32_t* a, const uint32_t* b) {
    asm volatile("mma.sync.aligned.m16n8k16.row.col.f32.bf16.bf16.f32 "
                 "{%0,%1,%2,%3}, {%4,%5,%6,%7}, {%8,%9}, {%0,%1,%2,%3};"
                 : "+f"(d[0]), "+f"(d[1]), "+f"(d[2]), "+f"(d[3])
                 : "r"(a[0]), "r"(a[1]), "r"(a[2]), "r"(a[3]), "r"(b[0]), "r"(b[1]));
}
#define CPA(dst, src) asm volatile("cp.async.cg.shared.global [%0], [%1], 16;" :: "r"(dst), "l"(src))
#define CPC()         asm volatile("cp.async.commit_group;")
#define CPW(n)        asm volatile("cp.async.wait_group %0;" :: "n"(n))

__device__ __forceinline__ uint32_t bfpack(float x, float y) {
    __nv_bfloat162 t;
    t.x = __float2bfloat16_rn(x);
    t.y = __float2bfloat16_rn(y);
    return *(uint32_t*)&t;
}
__device__ __forceinline__ void bfsplit2(float x, float y, uint32_t& hi, uint32_t& lo) {
    __nv_bfloat16 hx = __float2bfloat16_rn(x), hy = __float2bfloat16_rn(y);
    __nv_bfloat162 H; H.x = hx; H.y = hy;
    hi = *(uint32_t*)&H;
    lo = bfpack(x - __bfloat162float(hx), y - __bfloat162float(hy));
}

// ---------------- split + transpose: W[K,N] -> Bt[N,K] hi/lo ----------------
__global__ void convT_kernel(const float* __restrict__ W, __nv_bfloat16* __restrict__ ht,
                             __nv_bfloat16* __restrict__ lt, int K, int N) {
    __shared__ float t[64][33];
    int n0 = blockIdx.x * 32, k0 = blockIdx.y * 64;
    int tx = threadIdx.x & 31, ty = threadIdx.x >> 5;
#pragma unroll
    for (int ky = 0; ky < 64; ky += 8)
        t[ky + ty][tx] = W[(size_t)(k0 + ky + ty) * N + n0 + tx];
    __syncthreads();
    int kl = threadIdx.x & 63, nb = threadIdx.x >> 6;
#pragma unroll
    for (int n = nb; n < 32; n += 4) {
        float v = t[kl][n];
        __nv_bfloat16 h = __float2bfloat16_rn(v);
        size_t o = (size_t)(n0 + n) * K + k0 + kl;
        ht[o] = h;
        lt[o] = __float2bfloat16_rn(v - __bfloat162float(h));
    }
}

// ---------------- HMMA split-bf16 GEMM: K-chunk 32, 2-stage, 2 CTAs/SM ----------------
// EPI: 0 = bias -> fp32 C; 1 = bias+GELU -> split (Chi, Clo); 2 = bias+residual -> fp32 C
#define TROW 40                  // bf16 per row (80 B pitch; 5 x 16B units -> conflict-free)
#define TBYTES (128*80)          // 10240 per tile
#define GSMEM (2*4*TBYTES)       // 81920 -> 2 CTAs/SM

template <int EPI>
__global__ __launch_bounds__(256, 2)
void gemm_mma(const __nv_bfloat16* __restrict__ Ahi, const __nv_bfloat16* __restrict__ Alo,
              const __nv_bfloat16* __restrict__ Bhi, const __nv_bfloat16* __restrict__ Blo,
              const float* __restrict__ bias, const float* __restrict__ R,
              float* __restrict__ C, __nv_bfloat16* __restrict__ Chi,
              __nv_bfloat16* __restrict__ Clo, int M, int N, int K) {
    extern __shared__ __align__(16) char smem[];
    const uint32_t sb = smem_u32(smem);
    int tid = threadIdx.x, lane = tid & 31, w = tid >> 5;
    int wm = w >> 2, wn = w & 3;
    int bm = blockIdx.y << 7, bn = blockIdx.x << 7;

    float acc[4][4][4];
#pragma unroll
    for (int i = 0; i < 4; i++)
#pragma unroll
        for (int j = 0; j < 4; j++)
#pragma unroll
            for (int z = 0; z < 4; z++) acc[i][j][z] = 0.f;

    int lrow = tid >> 1, lsg0 = (tid & 1) * 2;
    auto issue = [&](int kc, int st) {
        int kb = kc << 5;
        uint32_t base = sb + st * 4 * TBYTES;
#pragma unroll
        for (int s = 0; s < 2; s++) {
            int seg = lsg0 + s;
            uint32_t so = base + (uint32_t)(lrow * 80 + seg * 16);
            size_t ga = (size_t)(bm + lrow) * K + kb + seg * 8;
            size_t gb = (size_t)(bn + lrow) * K + kb + seg * 8;
            CPA(so,              Ahi + ga);
            CPA(so + TBYTES,     Alo + ga);
            CPA(so + 2*TBYTES,   Bhi + gb);
            CPA(so + 3*TBYTES,   Blo + gb);
        }
        CPC();
    };

    const int nch = K >> 5;
    issue(0, 0);
    issue(1, 1);

    int a_row = wm * 64 + (lane & 15), a_col = (lane >> 4) << 3;
    int b_row = wn * 32 + ((lane >> 4) << 3) + (lane & 7), b_col = ((lane >> 3) & 1) << 3;
    uint32_t aoff = (uint32_t)(a_row * TROW + a_col) * 2;
    uint32_t boff = (uint32_t)(b_row * TROW + b_col) * 2 + 2 * TBYTES;

    for (int kc = 0; kc < nch; kc++) {
        if (kc + 1 < nch) { CPW(1); }
        else              { CPW(0); }
        __syncthreads();
        uint32_t base = sb + (uint32_t)((kc & 1) * 4 * TBYTES);
        uint32_t aoff_h = base + aoff, aoff_l = aoff_h + TBYTES;
        uint32_t boff_h = base + boff, boff_l = boff_h + TBYTES;
#pragma unroll
        for (int ks = 0; ks < 2; ks++) {
            uint32_t kso = (uint32_t)(ks * 32);
            uint32_t ah[4][4], bh[8];
#pragma unroll
            for (int mi = 0; mi < 4; mi++)
                ldm4(ah[mi], aoff_h + (uint32_t)(mi * 16 * TROW * 2) + kso);
            ldm4(&bh[0], boff_h + kso);
            ldm4(&bh[4], boff_h + (uint32_t)(16 * TROW * 2) + kso);
#pragma unroll
            for (int mi = 0; mi < 4; mi++)
#pragma unroll
                for (int ni = 0; ni < 4; ni++)
                    mma16816(acc[mi][ni], ah[mi], &bh[ni * 2]);
            uint32_t al[4][4];
#pragma unroll
            for (int mi = 0; mi < 4; mi++)
                ldm4(al[mi], aoff_l + (uint32_t)(mi * 16 * TROW * 2) + kso);
#pragma unroll
            for (int mi = 0; mi < 4; mi++)
#pragma unroll
                for (int ni = 0; ni < 4; ni++)
                    mma16816(acc[mi][ni], al[mi], &bh[ni * 2]);
            uint32_t bl[8];
            ldm4(&bl[0], boff_l + kso);
            ldm4(&bl[4], boff_l + (uint32_t)(16 * TROW * 2) + kso);
#pragma unroll
            for (int mi = 0; mi < 4; mi++)
#pragma unroll
                for (int ni = 0; ni < 4; ni++)
                    mma16816(acc[mi][ni], ah[mi], &bl[ni * 2]);
        }
        __syncthreads();
        if (kc + 2 < nch) issue(kc + 2, kc & 1);
    }

    // ---- epilogue ----
#pragma unroll
    for (int mi = 0; mi < 4; mi++) {
#pragma unroll
        for (int ni = 0; ni < 4; ni++) {
            int r0 = bm + wm * 64 + mi * 16 + (lane >> 2);
            int c0 = bn + wn * 32 + ni * 8 + ((lane & 3) << 1);
#pragma unroll
            for (int half = 0; half < 2; half++) {
                int gm = r0 + half * 8;
                float v0 = acc[mi][ni][half * 2]     + bias[c0];
                float v1 = acc[mi][ni][half * 2 + 1] + bias[c0 + 1];
                if (EPI == 1) {
                    v0 *= normcdff(v0); v1 *= normcdff(v1);
                    uint32_t hi, lo;
                    bfsplit2(v0, v1, hi, lo);
                    *(uint32_t*)&Chi[(size_t)gm * N + c0] = hi;
                    *(uint32_t*)&Clo[(size_t)gm * N + c0] = lo;
                } else {
                    if (EPI == 2) {
                        v0 += R[(size_t)gm * N + c0];
                        v1 += R[(size_t)gm * N + c0 + 1];
                    }
                    float2 o; o.x = v0; o.y = v1;
                    *(float2*)&C[(size_t)gm * N + c0] = o;
                }
            }
        }
    }
}

// ---------------- RoPE trig tables (double precision; fast-math-proof) ----------------
__global__ void trig_kernel(float* __restrict__ ct, float* __restrict__ st) {
    int i = blockIdx.x * 256 + threadIdx.x;
    if (i >= TT * 32) return;
    int t = i >> 5, p = i & 31;
    double inv = exp2(-13.287712379549449 * ((double)(2 * p) * (1.0 / 64.0)));
    float invf = (float)inv;
    float angf = (float)((double)t * (double)invf);
    double c, s;
    sincos((double)angf, &s, &c);
    ct[i] = (float)c;
    st[i] = (float)s;
}

// ---------------- embedding ----------------
__global__ void embed_kernel(const int* __restrict__ act, const int* __restrict__ obs,
                             const float* __restrict__ aemb, const float* __restrict__ oemb,
                             const float* __restrict__ temb, float* __restrict__ x) {
    int idx = blockIdx.x * blockDim.x + threadIdx.x;
    if (idx >= BT * DD) return;
    int r = idx / DD, d = idx % DD;
    x[idx] = aemb[(size_t)act[r] * DD + d] + temb[d]
           + oemb[(size_t)obs[r] * DD + d] + temb[DD + d];
}

// ---------------- layernorm -> split bf16 hi/lo directly ----------------
__global__ void ln_kernel(const float* __restrict__ x, const float* __restrict__ g,
                          const float* __restrict__ b, __nv_bfloat16* __restrict__ yh,
                          __nv_bfloat16* __restrict__ yl) {
    int r = blockIdx.x;
    const float* xr = x + (size_t)r * DD;
    float v[4];
    float s = 0.f, ss = 0.f;
#pragma unroll
    for (int i = 0; i < 4; i++) {
        float t = xr[threadIdx.x + i * 256];
        v[i] = t; s += t; ss += t * t;
    }
#pragma unroll
    for (int o = 16; o > 0; o >>= 1) {
        s  += __shfl_xor_sync(0xffffffffu, s,  o);
        ss += __shfl_xor_sync(0xffffffffu, ss, o);
    }
    __shared__ float rs[8], rss[8];
    int w = threadIdx.x >> 5;
    if ((threadIdx.x & 31) == 0) { rs[w] = s; rss[w] = ss; }
    __syncthreads();
    if (threadIdx.x == 0) {
        float a = 0.f, c = 0.f;
#pragma unroll
        for (int i = 0; i < 8; i++) { a += rs[i]; c += rss[i]; }
        rs[0] = a; rss[0] = c;
    }
    __syncthreads();
    float mean = rs[0] * (1.f / DD);
    float var  = rss[0] * (1.f / DD) - mean * mean;
    float inv  = rsqrtf(var + 1e-5f);
#pragma unroll
    for (int i = 0; i < 4; i++) {
        int d = threadIdx.x + i * 256;
        float val = (v[i] - mean) * inv * g[d] + b[d];
        __nv_bfloat16 h = __float2bfloat16_rn(val);
        yh[(size_t)r * DD + d] = h;
        yl[(size_t)r * DD + d] = __float2bfloat16_rn(val - __bfloat162float(h));
    }
}

// ---------------- RoPE + hi/lo split from fused QKV buffer [BT,3072] ----------------
__global__ void rope_split_kernel(const float* __restrict__ QKV,
                                  const float* __restrict__ ct, const float* __restrict__ st,
                                  __nv_bfloat16* __restrict__ qh, __nv_bfloat16* __restrict__ ql,
                                  __nv_bfloat16* __restrict__ kh, __nv_bfloat16* __restrict__ kl) {
    int idx = blockIdx.x * 256 + threadIdx.x;
    if (idx >= BT * (DD / 2)) return;
    int r  = idx >> 9;
    int c2 = idx & 511;
    int hh = c2 >> 5, p = c2 & 31;
    int b = r >> 11, t = r & (TT - 1);
    float c = ct[t * 32 + p];
    float s = st[t * 32 + p];
    size_t ib = (size_t)r * (3 * DD) + hh * 64 + 2 * p;
    size_t ob = ((size_t)(b * HH + hh) * TT + t) * 64 + 2 * p;

    float q0 = QKV[ib], q1 = QKV[ib + 1];
    float o0 = q0 * c - q1 * s, o1 = q0 * s + q1 * c;
    __nv_bfloat16 h0 = __float2bfloat16_rn(o0), h1 = __float2bfloat16_rn(o1);
    qh[ob] = h0; qh[ob + 1] = h1;
    ql[ob]     = __float2bfloat16_rn(o0 - __bfloat162float(h0));
    ql[ob + 1] = __float2bfloat16_rn(o1 - __bfloat162float(h1));

    float k0 = QKV[ib + DD], k1 = QKV[ib + DD + 1];
    float e0 = k0 * c - k1 * s, e1 = k0 * s + k1 * c;
    __nv_bfloat16 g0 = __float2bfloat16_rn(e0), g1 = __float2bfloat16_rn(e1);
    kh[ob] = g0; kh[ob + 1] = g1;
    kl[ob]     = __float2bfloat16_rn(e0 - __bfloat162float(g0));
    kl[ob + 1] = __float2bfloat16_rn(e1 - __bfloat162float(g1));
}

// ---------------- V split + transpose into [bh][d][t] (from fused QKV) ----------------
__global__ void vsplit_kernel(const float* __restrict__ QKV,
                              __nv_bfloat16* __restrict__ vh, __nv_bfloat16* __restrict__ vl) {
    __shared__ float ts[32][33];
    int t0 = blockIdx.x * 32, d0 = blockIdx.y * 32, b = blockIdx.z;
    int tx = threadIdx.x & 31, ty = threadIdx.x >> 5;
#pragma unroll
    for (int i = ty; i < 32; i += 8)
        ts[i][tx] = QKV[((size_t)b * TT + t0 + i) * (3 * DD) + 2 * DD + d0 + tx];
    __syncthreads();
    int hh = d0 >> 6, dl0 = d0 & 63;
#pragma unroll
    for (int i = ty; i < 32; i += 8) {
        float v = ts[tx][i];
        size_t o = ((size_t)(b * HH + hh) * 64 + dl0 + i) * TT + t0 + tx;
        __nv_bfloat16 h = __float2bfloat16_rn(v);
        vh[o] = h;
        vl[o] = __float2bfloat16_rn(v - __bfloat162float(h));
    }
}

// ================= fused flash attention =================
#define FQ_H 0
#define FQ_L 18432
#define FK_H(st) (36864 + (st)*36864)
#define FK_L(st) (FK_H(st) + 18432)
#define FV_H(st) (110592 + (st)*34816)
#define FV_L(st) (FV_H(st) + 17408)
#define FSMEM 180224

__global__ __launch_bounds__(256)
void flash_attn(const __nv_bfloat16* __restrict__ Qh, const __nv_bfloat16* __restrict__ Ql,
                const __nv_bfloat16* __restrict__ Kh, const __nv_bfloat16* __restrict__ Kl,
                const __nv_bfloat16* __restrict__ Vh, const __nv_bfloat16* __restrict__ Vl,
                __nv_bfloat16* __restrict__ Oh, __nv_bfloat16* __restrict__ Ol) {
    int qt = gridDim.x - 1 - blockIdx.x;
    int bh = blockIdx.y;
    int b = bh >> 4, hh = bh & 15;
    extern __shared__ __align__(16) char smem[];
    const uint32_t sb = smem_u32(smem);
    int tid = threadIdx.x, lane = tid & 31, w = tid >> 5;

    {
        int row = tid >> 1, segb = (tid & 1) * 4;
        size_t qg = ((size_t)bh * TT + qt * 128 + row) * 64 + segb * 8;
#pragma unroll
        for (int s = 0; s < 4; s++) {
            uint32_t so = (uint32_t)(row * 144 + (segb + s) * 16);
            *(uint4*)(smem + FQ_H + so) = *(const uint4*)(Qh + qg + s * 8);
            *(uint4*)(smem + FQ_L + so) = *(const uint4*)(Ql + qg + s * 8);
        }
    }

    auto issueKV = [&](int kt, int st) {
        int row = tid >> 1, segb = (tid & 1) * 4;
        size_t kg = ((size_t)bh * TT + kt * 128 + row) * 64 + segb * 8;
#pragma unroll
        for (int s = 0; s < 4; s++) {
            uint32_t so = (uint32_t)(row * 144 + (segb + s) * 16);
            CPA(sb + FK_H(st) + so, Kh + kg + s * 8);
            CPA(sb + FK_L(st) + so, Kl + kg + s * 8);
        }
        int vrow = tid >> 2, vsegb = (tid & 3) * 4;
        size_t vg = ((size_t)bh * 64 + vrow) * TT + kt * 128 + vsegb * 8;
#pragma unroll
        for (int s = 0; s < 4; s++) {
            uint32_t so = (uint32_t)(vrow * 272 + (vsegb + s) * 16);
            CPA(sb + FV_H(st) + so, Vh + vg + s * 8);
            CPA(sb + FV_L(st) + so, Vl + vg + s * 8);
        }
        CPC();
    };
    issueKV(0, 0);
    __syncthreads();

    uint32_t qfh[4][4], qfl[4][4];
    {
        int a_row = w * 16 + (lane & 15), a_col = (lane >> 4) << 3;
        uint32_t qa = (uint32_t)(a_row * 144 + a_col * 2);
#pragma unroll
        for (int ks = 0; ks < 4; ks++) {
            ldm4(qfh[ks], sb + FQ_H + qa + ks * 32);
            ldm4(qfl[ks], sb + FQ_L + qa + ks * 32);
        }
    }

    float m0 = -3.0e38f, m1 = -3.0e38f, l0 = 0.f, l1 = 0.f;
    float O[8][4];
#pragma unroll
    for (int i = 0; i < 8; i++)
#pragma unroll
        for (int z = 0; z < 4; z++) O[i][z] = 0.f;

    int b_rowi = ((lane >> 4) << 3) + (lane & 7);
    int b_colb = (((lane >> 3) & 1) << 3) * 2;

    for (int kt = 0; kt <= qt; kt++) {
        if (kt < qt) { issueKV(kt + 1, (kt + 1) & 1); CPW(1); }
        else         { CPW(0); }
        __syncthreads();
        uint32_t kb_h = sb + FK_H(kt & 1), kb_l = sb + FK_L(kt & 1);
        uint32_t vb_h = sb + FV_H(kt & 1), vb_l = sb + FV_L(kt & 1);

        float P[16][4];
#pragma unroll
        for (int i = 0; i < 16; i++)
#pragma unroll
            for (int z = 0; z < 4; z++) P[i][z] = 0.f;
#pragma unroll
        for (int ks = 0; ks < 4; ks++) {
            uint32_t kso = (uint32_t)(ks * 32);
#pragma unroll
            for (int nb = 0; nb < 8; nb++) {
                uint32_t addr = (uint32_t)((nb * 16 + b_rowi) * 144) + b_colb + kso;
                uint32_t kf[4], kfl[4];
                ldm4(kf, kb_h + addr);
                mma16816(P[2*nb],   qfh[ks], &kf[0]);
                mma16816(P[2*nb+1], qfh[ks], &kf[2]);
                mma16816(P[2*nb],   qfl[ks], &kf[0]);
                mma16816(P[2*nb+1], qfl[ks], &kf[2]);
                ldm4(kfl, kb_l + addr);
                mma16816(P[2*nb],   qfh[ks], &kfl[0]);
                mma16816(P[2*nb+1], qfh[ks], &kfl[2]);
            }
        }
#pragma unroll
        for (int i = 0; i < 16; i++)
#pragma unroll
            for (int z = 0; z < 4; z++) P[i][z] *= 0.125f;
        if (kt == qt) {
            int r0 = w * 16 + (lane >> 2);
#pragma unroll
            for (int i = 0; i < 16; i++) {
#pragma unroll
                for (int z = 0; z < 4; z++) {
                    int col = i * 8 + ((lane & 3) << 1) + (z & 1);
                    int row = r0 + ((z >> 1) << 3);
                    if (col > row) P[i][z] = -3.0e38f;
                }
            }
        }
        float mx0 = -3.0e38f, mx1 = -3.0e38f;
#pragma unroll
        for (int i = 0; i < 16; i++) {
            mx0 = fmaxf(mx0, fmaxf(P[i][0], P[i][1]));
            mx1 = fmaxf(mx1, fmaxf(P[i][2], P[i][3]));
        }
        mx0 = fmaxf(mx0, __shfl_xor_sync(0xffffffffu, mx0, 1));
        mx0 = fmaxf(mx0, __shfl_xor_sync(0xffffffffu, mx0, 2));
        mx1 = fmaxf(mx1, __shfl_xor_sync(0xffffffffu, mx1, 1));
        mx1 = fmaxf(mx1, __shfl_xor_sync(0xffffffffu, mx1, 2));
        float mn0 = fmaxf(m0, mx0), mn1 = fmaxf(m1, mx1);
        float al0 = expf(m0 - mn0), al1 = expf(m1 - mn1);
        m0 = mn0; m1 = mn1;
        float s0 = 0.f, s1 = 0.f;
#pragma unroll
        for (int i = 0; i < 16; i++) {
            P[i][0] = expf(P[i][0] - m0); s0 += P[i][0];
            P[i][1] = expf(P[i][1] - m0); s0 += P[i][1];
            P[i][2] = expf(P[i][2] - m1); s1 += P[i][2];
            P[i][3] = expf(P[i][3] - m1); s1 += P[i][3];
        }
        s0 += __shfl_xor_sync(0xffffffffu, s0, 1);
        s0 += __shfl_xor_sync(0xffffffffu, s0, 2);
        s1 += __shfl_xor_sync(0xffffffffu, s1, 1);
        s1 += __shfl_xor_sync(0xffffffffu, s1, 2);
        l0 = l0 * al0 + s0;
        l1 = l1 * al1 + s1;
#pragma unroll
        for (int i = 0; i < 8; i++) {
            O[i][0] *= al0; O[i][1] *= al0;
            O[i][2] *= al1; O[i][3] *= al1;
        }
#pragma unroll
        for (int ks = 0; ks < 8; ks++) {
            uint32_t pah[4], pal[4];
            bfsplit2(P[2*ks][0],   P[2*ks][1],   pah[0], pal[0]);
            bfsplit2(P[2*ks][2],   P[2*ks][3],   pah[1], pal[1]);
            bfsplit2(P[2*ks+1][0], P[2*ks+1][1], pah[2], pal[2]);
            bfsplit2(P[2*ks+1][2], P[2*ks+1][3], pah[3], pal[3]);
            uint32_t kso = (uint32_t)(ks * 32);
#pragma unroll
            for (int nb = 0; nb < 4; nb++) {
                uint32_t addr = (uint32_t)((nb * 16 + b_rowi) * 272) + b_colb + kso;
                uint32_t vf[4], vfl[4];
                ldm4(vf, vb_h + addr);
                mma16816(O[2*nb],   pah, &vf[0]);
                mma16816(O[2*nb+1], pah, &vf[2]);
                mma16816(O[2*nb],   pal, &vf[0]);
                mma16816(O[2*nb+1], pal, &vf[2]);
                ldm4(vfl, vb_l + addr);
                mma16816(O[2*nb],   pah, &vfl[0]);
                mma16816(O[2*nb+1], pah, &vfl[2]);
            }
        }
        __syncthreads();
    }

    float i0 = 1.f / l0, i1 = 1.f / l1;
    int r0 = qt * 128 + w * 16 + (lane >> 2);
    int c0 = hh * 64 + ((lane & 3) << 1);
#pragma unroll
    for (int nj = 0; nj < 8; nj++) {
        int cc = c0 + nj * 8;
        uint32_t hi, lo;
        bfsplit2(O[nj][0] * i0, O[nj][1] * i0, hi, lo);
        size_t o0 = ((size_t)b * TT + r0) * DD + cc;
        *(uint32_t*)&Oh[o0] = hi;
        *(uint32_t*)&Ol[o0] = lo;
        bfsplit2(O[nj][2] * i1, O[nj][3] * i1, hi, lo);
        size_t o1 = ((size_t)b * TT + r0 + 8) * DD + cc;
        *(uint32_t*)&Oh[o1] = hi;
        *(uint32_t*)&Ol[o1] = lo;
    }
}

// ---------------- host-side helpers ----------------
static void conv_B(const float* W, __nv_bfloat16* bh, __nv_bfloat16* bl, int K, int N) {
    convT_kernel<<<dim3(N / 32, K / 64), 256>>>(W, bh, bl, K, N);
}
template <int EPI>
static void gemm(const __nv_bfloat16* ah, const __nv_bfloat16* al,
                 const __nv_bfloat16* bh, const __nv_bfloat16* bl,
                 const float* bias, const float* R, float* C,
                 __nv_bfloat16* Chi, __nv_bfloat16* Clo, int M, int N, int K) {
    static bool cfg = false;
    if (!cfg) {
        cudaFuncSetAttribute(gemm_mma<EPI>, cudaFuncAttributeMaxDynamicSharedMemorySize, GSMEM);
        cfg = true;
    }
    gemm_mma<EPI><<<dim3(N / 128, M / 128), 256, GSMEM>>>(ah, al, bh, bl, bias, R, C, Chi, Clo, M, N, K);
}

// ---------------- launch sequence ----------------
extern "C" void kernel_launch(void* const* d_in, const int* in_sizes, int n_in,
                              void* d_out, int out_size) {
    const int*   actions = (const int*)d_in[0];
    const int*   observ  = (const int*)d_in[1];
    const float* aemb    = (const float*)d_in[2];
    const float* oemb    = (const float*)d_in[3];
    const float* temb    = (const float*)d_in[4];
    const float* Wq      = (const float*)d_in[5];
    const float* bq      = (const float*)d_in[6];
    const float* Wk      = (const float*)d_in[7];
    const float* bk      = (const float*)d_in[8];
    const float* Wv      = (const float*)d_in[9];
    const float* bv      = (const float*)d_in[10];
    const float* Wo      = (const float*)d_in[11];
    const float* bo      = (const float*)d_in[12];
    const float* ln1_g   = (const float*)d_in[13];
    const float* ln1_b   = (const float*)d_in[14];
    const float* ln2_g   = (const float*)d_in[15];
    const float* ln2_b   = (const float*)d_in[16];
    const float* W1      = (const float*)d_in[17];
    const float* b1      = (const float*)d_in[18];
    const float* W2      = (const float*)d_in[19];
    const float* b2      = (const float*)d_in[20];
    const float* out_g   = (const float*)d_in[21];
    const float* out_b   = (const float*)d_in[22];
    const float* Wout    = (const float*)d_in[23];
    const float* bout    = (const float*)d_in[24];

    float *x, *qkv, *b3, *ct, *st;
    __nv_bfloat16 *ah, *al, *fh, *fl, *bh, *bl, *qh, *ql, *kh, *kl, *vh, *vl;
    cudaGetSymbolAddress((void**)&x,   g_x);
    cudaGetSymbolAddress((void**)&qkv, g_qkv);
    cudaGetSymbolAddress((void**)&b3,  g_b3);
    cudaGetSymbolAddress((void**)&ct,  g_cos);
    cudaGetSymbolAddress((void**)&st,  g_sin);
    cudaGetSymbolAddress((void**)&ah,  g_ah);
    cudaGetSymbolAddress((void**)&al,  g_al);
    cudaGetSymbolAddress((void**)&fh,  g_fh);
    cudaGetSymbolAddress((void**)&fl,  g_fl);
    cudaGetSymbolAddress((void**)&bh,  g_bh);
    cudaGetSymbolAddress((void**)&bl,  g_bl);
    cudaGetSymbolAddress((void**)&qh,  g_qh);
    cudaGetSymbolAddress((void**)&ql,  g_ql);
    cudaGetSymbolAddress((void**)&kh,  g_kh);
    cudaGetSymbolAddress((void**)&kl,  g_kl);
    cudaGetSymbolAddress((void**)&vh,  g_vh);
    cudaGetSymbolAddress((void**)&vl,  g_vl);

    static bool fcfg = false;
    if (!fcfg) {
        cudaFuncSetAttribute(flash_attn, cudaFuncAttributeMaxDynamicSharedMemorySize, FSMEM);
        fcfg = true;
    }

    trig_kernel<<<(TT * 32 + 255) / 256, 256>>>(ct, st);
    embed_kernel<<<(BT * DD + 255) / 256, 256>>>(actions, observ, aemb, oemb, temb, x);

    for (int i = 0; i < LL; i++) {
        ln_kernel<<<BT, 256>>>(x, ln1_g + (size_t)i * DD, ln1_b + (size_t)i * DD, ah, al);

        // fused QKV: Bt rows [0,1024)=Wq^T, [1024,2048)=Wk^T, [2048,3072)=Wv^T
        conv_B(Wq + (size_t)i * DD * DD, bh,                        bl,                        DD, DD);
        conv_B(Wk + (size_t)i * DD * DD, bh + (size_t)DD * DD,      bl + (size_t)DD * DD,      DD, DD);
        conv_B(Wv + (size_t)i * DD * DD, bh + (size_t)2 * DD * DD,  bl + (size_t)2 * DD * DD,  DD, DD);
        cudaMemcpyAsync(b3,            bq + (size_t)i * DD, DD * 4, cudaMemcpyDeviceToDevice);
        cudaMemcpyAsync(b3 + DD,       bk + (size_t)i * DD, DD * 4, cudaMemcpyDeviceToDevice);
        cudaMemcpyAsync(b3 + 2 * DD,   bv + (size_t)i * DD, DD * 4, cudaMemcpyDeviceToDevice);
        gemm<0>(ah, al, bh, bl, b3, nullptr, qkv, nullptr, nullptr, BT, 3 * DD, DD);

        rope_split_kernel<<<(BT * (DD / 2) + 255) / 256, 256>>>(qkv, ct, st, qh, ql, kh, kl);
        vsplit_kernel<<<dim3(TT / 32, DD / 32, BB), 256>>>(qkv, vh, vl);

        flash_attn<<<dim3(TT / 128, BB * HH), 256, FSMEM>>>(qh, ql, kh, kl, vh, vl, ah, al);

        conv_B(Wo + (size_t)i * DD * DD, bh, bl, DD, DD);
        gemm<2>(ah, al, bh, bl, bo + (size_t)i * DD, x, x, nullptr, nullptr, BT, DD, DD);

        ln_kernel<<<BT, 256>>>(x, ln2_g + (size_t)i * DD, ln2_b + (size_t)i * DD, ah, al);
        conv_B(W1 + (size_t)i * DD * DFF, bh, bl, DD, DFF);
        gemm<1>(ah, al, bh, bl, b1 + (size_t)i * DFF, nullptr, nullptr, fh, fl, BT, DFF, DD);

        conv_B(W2 + (size_t)i * DFF * DD, bh, bl, DFF, DD);
        gemm<2>(fh, fl, bh, bl, b2 + (size_t)i * DD, x, x, nullptr, nullptr, BT, DD, DFF);
    }

    ln_kernel<<<BT, 256>>>(x, out_g, out_b, ah, al);
    conv_B(Wout, bh, bl, DD, OV);
    gemm<0>(ah, al, bh, bl, bout, nullptr, (float*)d_out, nullptr, nullptr, BT, OV, DD);
}

// round 12
// speedup vs baseline: 1.0710x; 1.0710x over previous
#include <cuda_runtime.h>
#include <cuda_bf16.h>
#include <math.h>
#include <stdint.h>

#define LL 2
#define DD 1024
#define HH 16
#define DHH 64
#define DFF 4096
#define BB 2
#define TT 2048
#define OV 4096
#define BT (BB*TT)   // 4096

// ---------------- scratch (device globals; no runtime allocation) ----------------
__device__ float g_x  [BT*DD];
__device__ float g_qkv[(size_t)BT*3*DD];
__device__ float g_b3 [3*DD];
__device__ float g_cos[TT*32];
__device__ float g_sin[TT*32];
// bf16 split operands (16B-aligned for vector access)
__device__ __align__(16) __nv_bfloat16 g_ah[(size_t)BT*DD];    // activation hi [BT,DD]
__device__ __align__(16) __nv_bfloat16 g_al[(size_t)BT*DD];
__device__ __align__(16) __nv_bfloat16 g_fh[(size_t)BT*DFF];   // ff hi [BT,DFF]
__device__ __align__(16) __nv_bfloat16 g_fl[(size_t)BT*DFF];
__device__ __align__(16) __nv_bfloat16 g_bh[(size_t)DFF*DD];   // B^T hi [N,K] (max 4096x1024)
__device__ __align__(16) __nv_bfloat16 g_bl[(size_t)DFF*DD];
// attention split operands
__device__ __align__(16) __nv_bfloat16 g_qh[(size_t)BB*HH*TT*DHH];  // [bh][t][d]
__device__ __align__(16) __nv_bfloat16 g_ql[(size_t)BB*HH*TT*DHH];
__device__ __align__(16) __nv_bfloat16 g_kh[(size_t)BB*HH*TT*DHH];
__device__ __align__(16) __nv_bfloat16 g_kl[(size_t)BB*HH*TT*DHH];
__device__ __align__(16) __nv_bfloat16 g_vh[(size_t)BB*HH*DHH*TT];  // [bh][d][t]
__device__ __align__(16) __nv_bfloat16 g_vl[(size_t)BB*HH*DHH*TT];

// ---------------- warp-MMA primitives (baseline PTX; no sm_103a features) ----------
__device__ __forceinline__ uint32_t smem_u32(const void* p) {
    uint32_t a;
    asm("{ .reg .u64 t; cvta.to.shared.u64 t, %1; cvt.u32.u64 %0, t; }" : "=r"(a) : "l"(p));
    return a;
}
__device__ __forceinline__ void ldm4(uint32_t* r, uint32_t addr) {
    asm volatile("ldmatrix.sync.aligned.m8n8.x4.shared.b16 {%0,%1,%2,%3}, [%4];"
                 : "=r"(r[0]), "=r"(r[1]), "=r"(r[2]), "=r"(r[3]) : "r"(addr));
}
__device__ __forceinline__ void mma16816(float* d, const uint32_t* a, const uint32_t* b) {
    asm volatile("mma.sync.aligned.m16n8k16.row.col.f32.bf16.bf16.f32 "
                 "{%0,%1,%2,%3}, {%4,%5,%6,%7}, {%8,%9}, {%0,%1,%2,%3};"
                 : "+f"(d[0]), "+f"(d[1]), "+f"(d[2]), "+f"(d[3])
                 : "r"(a[0]), "r"(a[1]), "r"(a[2]), "r"(a[3]), "r"(b[0]), "r"(b[1]));
}
#define CPA(dst, src) asm volatile("cp.async.cg.shared.global [%0], [%1], 16;" :: "r"(dst), "l"(src))
#define CPC()         asm volatile("cp.async.commit_group;")
#define CPW(n)        asm volatile("cp.async.wait_group %0;" :: "n"(n))

__device__ __forceinline__ uint32_t bfpack(float x, float y) {
    __nv_bfloat162 t;
    t.x = __float2bfloat16_rn(x);
    t.y = __float2bfloat16_rn(y);
    return *(uint32_t*)&t;
}
__device__ __forceinline__ void bfsplit2(float x, float y, uint32_t& hi, uint32_t& lo) {
    __nv_bfloat16 hx = __float2bfloat16_rn(x), hy = __float2bfloat16_rn(y);
    __nv_bfloat162 H; H.x = hx; H.y = hy;
    hi = *(uint32_t*)&H;
    lo = bfpack(x - __bfloat162float(hx), y - __bfloat162float(hy));
}

// ---------------- split + transpose: W[K,N] -> Bt[N,K] hi/lo ----------------
__global__ void convT_kernel(const float* __restrict__ W, __nv_bfloat16* __restrict__ ht,
                             __nv_bfloat16* __restrict__ lt, int K, int N) {
    __shared__ float t[64][33];
    int n0 = blockIdx.x * 32, k0 = blockIdx.y * 64;
    int tx = threadIdx.x & 31, ty = threadIdx.x >> 5;
#pragma unroll
    for (int ky = 0; ky < 64; ky += 8)
        t[ky + ty][tx] = W[(size_t)(k0 + ky + ty) * N + n0 + tx];
    __syncthreads();
    int kl = threadIdx.x & 63, nb = threadIdx.x >> 6;
#pragma unroll
    for (int n = nb; n < 32; n += 4) {
        float v = t[kl][n];
        __nv_bfloat16 h = __float2bfloat16_rn(v);
        size_t o = (size_t)(n0 + n) * K + k0 + kl;
        ht[o] = h;
        lt[o] = __float2bfloat16_rn(v - __bfloat162float(h));
    }
}

// ---------------- HMMA split-bf16 GEMM, cp.async 3-stage pipelined (R10 config) -------
// EPI: 0 = bias -> fp32 C; 1 = bias+GELU -> split (Chi, Clo); 2 = bias+residual -> fp32 C
#define TROW 72
#define TBYTES (128*TROW*2)      // 18432 per tile
#define GSMEM (3*4*TBYTES)       // 221184 (3 stages x 4 tiles)

template <int EPI>
__global__ __launch_bounds__(256)
void gemm_mma(const __nv_bfloat16* __restrict__ Ahi, const __nv_bfloat16* __restrict__ Alo,
              const __nv_bfloat16* __restrict__ Bhi, const __nv_bfloat16* __restrict__ Blo,
              const float* __restrict__ bias, const float* __restrict__ R,
              float* __restrict__ C, __nv_bfloat16* __restrict__ Chi,
              __nv_bfloat16* __restrict__ Clo, int M, int N, int K) {
    extern __shared__ __align__(16) char smem[];
    const uint32_t sb = smem_u32(smem);
    int tid = threadIdx.x, lane = tid & 31, w = tid >> 5;
    int wm = w >> 2, wn = w & 3;
    int bm = blockIdx.y << 7, bn = blockIdx.x << 7;

    float acc[4][4][4];
#pragma unroll
    for (int i = 0; i < 4; i++)
#pragma unroll
        for (int j = 0; j < 4; j++)
#pragma unroll
            for (int z = 0; z < 4; z++) acc[i][j][z] = 0.f;

    int lrow = tid >> 3, lseg = tid & 7;
    auto issue = [&](int kc, int st) {
        int kb = kc << 6;
        uint32_t base = sb + st * 4 * TBYTES;
#pragma unroll
        for (int i = 0; i < 4; i++) {
            int row = lrow + i * 32;
            uint32_t so = base + (uint32_t)(row * 144 + lseg * 16);
            size_t ga = (size_t)(bm + row) * K + kb + lseg * 8;
            size_t gb = (size_t)(bn + row) * K + kb + lseg * 8;
            CPA(so,              Ahi + ga);
            CPA(so + TBYTES,     Alo + ga);
            CPA(so + 2*TBYTES,   Bhi + gb);
            CPA(so + 3*TBYTES,   Blo + gb);
        }
        CPC();
    };

    const int nch = K >> 6;
    issue(0, 0);
    issue(1, 1);

    int a_row = wm * 64 + (lane & 15), a_col = (lane >> 4) << 3;
    int b_row = wn * 32 + ((lane >> 4) << 3) + (lane & 7), b_col = ((lane >> 3) & 1) << 3;
    uint32_t aoff = (uint32_t)(a_row * TROW + a_col) * 2;
    uint32_t boff = (uint32_t)(b_row * TROW + b_col) * 2 + 2 * TBYTES;

    for (int kc = 0; kc < nch; kc++) {
        if (kc + 1 < nch) { CPW(1); }
        else              { CPW(0); }
        __syncthreads();
        if (kc + 2 < nch) issue(kc + 2, (kc + 2) % 3);

        uint32_t base = sb + (uint32_t)((kc % 3) * 4 * TBYTES);
        uint32_t aoff_h = base + aoff, aoff_l = aoff_h + TBYTES;
        uint32_t boff_h = base + boff, boff_l = boff_h + TBYTES;
#pragma unroll
        for (int ks = 0; ks < 4; ks++) {
            uint32_t ah[4][4], al[4][4], bh[8], bl[8];
            uint32_t kso = (uint32_t)(ks * 32);
#pragma unroll
            for (int mi = 0; mi < 4; mi++) {
                ldm4(ah[mi], aoff_h + (uint32_t)(mi * 16 * TROW * 2) + kso);
                ldm4(al[mi], aoff_l + (uint32_t)(mi * 16 * TROW * 2) + kso);
            }
            ldm4(&bh[0], boff_h + kso);
            ldm4(&bh[4], boff_h + (uint32_t)(16 * TROW * 2) + kso);
#pragma unroll
            for (int mi = 0; mi < 4; mi++)
#pragma unroll
                for (int ni = 0; ni < 4; ni++)
                    mma16816(acc[mi][ni], ah[mi], &bh[ni * 2]);
#pragma unroll
            for (int mi = 0; mi < 4; mi++)
#pragma unroll
                for (int ni = 0; ni < 4; ni++)
                    mma16816(acc[mi][ni], al[mi], &bh[ni * 2]);
            ldm4(&bl[0], boff_l + kso);
            ldm4(&bl[4], boff_l + (uint32_t)(16 * TROW * 2) + kso);
#pragma unroll
            for (int mi = 0; mi < 4; mi++)
#pragma unroll
                for (int ni = 0; ni < 4; ni++)
                    mma16816(acc[mi][ni], ah[mi], &bl[ni * 2]);
        }
    }

    // ---- epilogue ----
#pragma unroll
    for (int mi = 0; mi < 4; mi++) {
#pragma unroll
        for (int ni = 0; ni < 4; ni++) {
            int r0 = bm + wm * 64 + mi * 16 + (lane >> 2);
            int c0 = bn + wn * 32 + ni * 8 + ((lane & 3) << 1);
#pragma unroll
            for (int half = 0; half < 2; half++) {
                int gm = r0 + half * 8;
                float v0 = acc[mi][ni][half * 2]     + bias[c0];
                float v1 = acc[mi][ni][half * 2 + 1] + bias[c0 + 1];
                if (EPI == 1) {
                    v0 *= normcdff(v0); v1 *= normcdff(v1);
                    uint32_t hi, lo;
                    bfsplit2(v0, v1, hi, lo);
                    *(uint32_t*)&Chi[(size_t)gm * N + c0] = hi;
                    *(uint32_t*)&Clo[(size_t)gm * N + c0] = lo;
                } else {
                    if (EPI == 2) {
                        v0 += R[(size_t)gm * N + c0];
                        v1 += R[(size_t)gm * N + c0 + 1];
                    }
                    float2 o; o.x = v0; o.y = v1;
                    *(float2*)&C[(size_t)gm * N + c0] = o;
                }
            }
        }
    }
}

// ---------------- RoPE trig tables (double precision; fast-math-proof) ----------------
__global__ void trig_kernel(float* __restrict__ ct, float* __restrict__ st) {
    int i = blockIdx.x * 256 + threadIdx.x;
    if (i >= TT * 32) return;
    int t = i >> 5, p = i & 31;
    double inv = exp2(-13.287712379549449 * ((double)(2 * p) * (1.0 / 64.0)));
    float invf = (float)inv;
    float angf = (float)((double)t * (double)invf);
    double c, s;
    sincos((double)angf, &s, &c);
    ct[i] = (float)c;
    st[i] = (float)s;
}

// ---------------- embedding ----------------
__global__ void embed_kernel(const int* __restrict__ act, const int* __restrict__ obs,
                             const float* __restrict__ aemb, const float* __restrict__ oemb,
                             const float* __restrict__ temb, float* __restrict__ x) {
    int idx = blockIdx.x * blockDim.x + threadIdx.x;
    if (idx >= BT * DD) return;
    int r = idx / DD, d = idx % DD;
    x[idx] = aemb[(size_t)act[r] * DD + d] + temb[d]
           + oemb[(size_t)obs[r] * DD + d] + temb[DD + d];
}

// ---------------- layernorm -> split bf16 hi/lo directly ----------------
__global__ void ln_kernel(const float* __restrict__ x, const float* __restrict__ g,
                          const float* __restrict__ b, __nv_bfloat16* __restrict__ yh,
                          __nv_bfloat16* __restrict__ yl) {
    int r = blockIdx.x;
    const float* xr = x + (size_t)r * DD;
    float v[4];
    float s = 0.f, ss = 0.f;
#pragma unroll
    for (int i = 0; i < 4; i++) {
        float t = xr[threadIdx.x + i * 256];
        v[i] = t; s += t; ss += t * t;
    }
#pragma unroll
    for (int o = 16; o > 0; o >>= 1) {
        s  += __shfl_xor_sync(0xffffffffu, s,  o);
        ss += __shfl_xor_sync(0xffffffffu, ss, o);
    }
    __shared__ float rs[8], rss[8];
    int w = threadIdx.x >> 5;
    if ((threadIdx.x & 31) == 0) { rs[w] = s; rss[w] = ss; }
    __syncthreads();
    if (threadIdx.x == 0) {
        float a = 0.f, c = 0.f;
#pragma unroll
        for (int i = 0; i < 8; i++) { a += rs[i]; c += rss[i]; }
        rs[0] = a; rss[0] = c;
    }
    __syncthreads();
    float mean = rs[0] * (1.f / DD);
    float var  = rss[0] * (1.f / DD) - mean * mean;
    float inv  = rsqrtf(var + 1e-5f);
#pragma unroll
    for (int i = 0; i < 4; i++) {
        int d = threadIdx.x + i * 256;
        float val = (v[i] - mean) * inv * g[d] + b[d];
        __nv_bfloat16 h = __float2bfloat16_rn(val);
        yh[(size_t)r * DD + d] = h;
        yl[(size_t)r * DD + d] = __float2bfloat16_rn(val - __bfloat162float(h));
    }
}

// ---------------- RoPE + hi/lo split from fused QKV buffer [BT,3072] ----------------
__global__ void rope_split_kernel(const float* __restrict__ QKV,
                                  const float* __restrict__ ct, const float* __restrict__ st,
                                  __nv_bfloat16* __restrict__ qh, __nv_bfloat16* __restrict__ ql,
                                  __nv_bfloat16* __restrict__ kh, __nv_bfloat16* __restrict__ kl) {
    int idx = blockIdx.x * 256 + threadIdx.x;
    if (idx >= BT * (DD / 2)) return;
    int r  = idx >> 9;
    int c2 = idx & 511;
    int hh = c2 >> 5, p = c2 & 31;
    int b = r >> 11, t = r & (TT - 1);
    float c = ct[t * 32 + p];
    float s = st[t * 32 + p];
    size_t ib = (size_t)r * (3 * DD) + hh * 64 + 2 * p;
    size_t ob = ((size_t)(b * HH + hh) * TT + t) * 64 + 2 * p;

    float q0 = QKV[ib], q1 = QKV[ib + 1];
    float o0 = q0 * c - q1 * s, o1 = q0 * s + q1 * c;
    __nv_bfloat16 h0 = __float2bfloat16_rn(o0), h1 = __float2bfloat16_rn(o1);
    qh[ob] = h0; qh[ob + 1] = h1;
    ql[ob]     = __float2bfloat16_rn(o0 - __bfloat162float(h0));
    ql[ob + 1] = __float2bfloat16_rn(o1 - __bfloat162float(h1));

    float k0 = QKV[ib + DD], k1 = QKV[ib + DD + 1];
    float e0 = k0 * c - k1 * s, e1 = k0 * s + k1 * c;
    __nv_bfloat16 g0 = __float2bfloat16_rn(e0), g1 = __float2bfloat16_rn(e1);
    kh[ob] = g0; kh[ob + 1] = g1;
    kl[ob]     = __float2bfloat16_rn(e0 - __bfloat162float(g0));
    kl[ob + 1] = __float2bfloat16_rn(e1 - __bfloat162float(g1));
}

// ---------------- V split + transpose into [bh][d][t] (from fused QKV) ----------------
__global__ void vsplit_kernel(const float* __restrict__ QKV,
                              __nv_bfloat16* __restrict__ vh, __nv_bfloat16* __restrict__ vl) {
    __shared__ float ts[32][33];
    int t0 = blockIdx.x * 32, d0 = blockIdx.y * 32, b = blockIdx.z;
    int tx = threadIdx.x & 31, ty = threadIdx.x >> 5;
#pragma unroll
    for (int i = ty; i < 32; i += 8)
        ts[i][tx] = QKV[((size_t)b * TT + t0 + i) * (3 * DD) + 2 * DD + d0 + tx];
    __syncthreads();
    int hh = d0 >> 6, dl0 = d0 & 63;
#pragma unroll
    for (int i = ty; i < 32; i += 8) {
        float v = ts[tx][i];
        size_t o = ((size_t)(b * HH + hh) * 64 + dl0 + i) * TT + t0 + tx;
        __nv_bfloat16 h = __float2bfloat16_rn(v);
        vh[o] = h;
        vl[o] = __float2bfloat16_rn(v - __bfloat162float(h));
    }
}

// ================= fused flash attention =================
#define FQ_H 0
#define FQ_L 18432
#define FK_H(st) (36864 + (st)*36864)
#define FK_L(st) (FK_H(st) + 18432)
#define FV_H(st) (110592 + (st)*34816)
#define FV_L(st) (FV_H(st) + 17408)
#define FSMEM 180224

__global__ __launch_bounds__(256)
void flash_attn(const __nv_bfloat16* __restrict__ Qh, const __nv_bfloat16* __restrict__ Ql,
                const __nv_bfloat16* __restrict__ Kh, const __nv_bfloat16* __restrict__ Kl,
                const __nv_bfloat16* __restrict__ Vh, const __nv_bfloat16* __restrict__ Vl,
                __nv_bfloat16* __restrict__ Oh, __nv_bfloat16* __restrict__ Ol) {
    int qt = gridDim.x - 1 - blockIdx.x;
    int bh = blockIdx.y;
    int b = bh >> 4, hh = bh & 15;
    extern __shared__ __align__(16) char smem[];
    const uint32_t sb = smem_u32(smem);
    int tid = threadIdx.x, lane = tid & 31, w = tid >> 5;

    {
        int row = tid >> 1, segb = (tid & 1) * 4;
        size_t qg = ((size_t)bh * TT + qt * 128 + row) * 64 + segb * 8;
#pragma unroll
        for (int s = 0; s < 4; s++) {
            uint32_t so = (uint32_t)(row * 144 + (segb + s) * 16);
            *(uint4*)(smem + FQ_H + so) = *(const uint4*)(Qh + qg + s * 8);
            *(uint4*)(smem + FQ_L + so) = *(const uint4*)(Ql + qg + s * 8);
        }
    }

    auto issueKV = [&](int kt, int st) {
        int row = tid >> 1, segb = (tid & 1) * 4;
        size_t kg = ((size_t)bh * TT + kt * 128 + row) * 64 + segb * 8;
#pragma unroll
        for (int s = 0; s < 4; s++) {
            uint32_t so = (uint32_t)(row * 144 + (segb + s) * 16);
            CPA(sb + FK_H(st) + so, Kh + kg + s * 8);
            CPA(sb + FK_L(st) + so, Kl + kg + s * 8);
        }
        int vrow = tid >> 2, vsegb = (tid & 3) * 4;
        size_t vg = ((size_t)bh * 64 + vrow) * TT + kt * 128 + vsegb * 8;
#pragma unroll
        for (int s = 0; s < 4; s++) {
            uint32_t so = (uint32_t)(vrow * 272 + (vsegb + s) * 16);
            CPA(sb + FV_H(st) + so, Vh + vg + s * 8);
            CPA(sb + FV_L(st) + so, Vl + vg + s * 8);
        }
        CPC();
    };
    issueKV(0, 0);
    __syncthreads();

    uint32_t qfh[4][4], qfl[4][4];
    {
        int a_row = w * 16 + (lane & 15), a_col = (lane >> 4) << 3;
        uint32_t qa = (uint32_t)(a_row * 144 + a_col * 2);
#pragma unroll
        for (int ks = 0; ks < 4; ks++) {
            ldm4(qfh[ks], sb + FQ_H + qa + ks * 32);
            ldm4(qfl[ks], sb + FQ_L + qa + ks * 32);
        }
    }

    float m0 = -3.0e38f, m1 = -3.0e38f, l0 = 0.f, l1 = 0.f;
    float O[8][4];
#pragma unroll
    for (int i = 0; i < 8; i++)
#pragma unroll
        for (int z = 0; z < 4; z++) O[i][z] = 0.f;

    int b_rowi = ((lane >> 4) << 3) + (lane & 7);
    int b_colb = (((lane >> 3) & 1) << 3) * 2;

    for (int kt = 0; kt <= qt; kt++) {
        if (kt < qt) { issueKV(kt + 1, (kt + 1) & 1); CPW(1); }
        else         { CPW(0); }
        __syncthreads();
        uint32_t kb_h = sb + FK_H(kt & 1), kb_l = sb + FK_L(kt & 1);
        uint32_t vb_h = sb + FV_H(kt & 1), vb_l = sb + FV_L(kt & 1);

        float P[16][4];
#pragma unroll
        for (int i = 0; i < 16; i++)
#pragma unroll
            for (int z = 0; z < 4; z++) P[i][z] = 0.f;
#pragma unroll
        for (int ks = 0; ks < 4; ks++) {
            uint32_t kso = (uint32_t)(ks * 32);
#pragma unroll
            for (int nb = 0; nb < 8; nb++) {
                uint32_t addr = (uint32_t)((nb * 16 + b_rowi) * 144) + b_colb + kso;
                uint32_t kf[4], kfl[4];
                ldm4(kf, kb_h + addr);
                mma16816(P[2*nb],   qfh[ks], &kf[0]);
                mma16816(P[2*nb+1], qfh[ks], &kf[2]);
                mma16816(P[2*nb],   qfl[ks], &kf[0]);
                mma16816(P[2*nb+1], qfl[ks], &kf[2]);
                ldm4(kfl, kb_l + addr);
                mma16816(P[2*nb],   qfh[ks], &kfl[0]);
                mma16816(P[2*nb+1], qfh[ks], &kfl[2]);
            }
        }
#pragma unroll
        for (int i = 0; i < 16; i++)
#pragma unroll
            for (int z = 0; z < 4; z++) P[i][z] *= 0.125f;
        if (kt == qt) {
            int r0 = w * 16 + (lane >> 2);
#pragma unroll
            for (int i = 0; i < 16; i++) {
#pragma unroll
                for (int z = 0; z < 4; z++) {
                    int col = i * 8 + ((lane & 3) << 1) + (z & 1);
                    int row = r0 + ((z >> 1) << 3);
                    if (col > row) P[i][z] = -3.0e38f;
                }
            }
        }
        float mx0 = -3.0e38f, mx1 = -3.0e38f;
#pragma unroll
        for (int i = 0; i < 16; i++) {
            mx0 = fmaxf(mx0, fmaxf(P[i][0], P[i][1]));
            mx1 = fmaxf(mx1, fmaxf(P[i][2], P[i][3]));
        }
        mx0 = fmaxf(mx0, __shfl_xor_sync(0xffffffffu, mx0, 1));
        mx0 = fmaxf(mx0, __shfl_xor_sync(0xffffffffu, mx0, 2));
        mx1 = fmaxf(mx1, __shfl_xor_sync(0xffffffffu, mx1, 1));
        mx1 = fmaxf(mx1, __shfl_xor_sync(0xffffffffu, mx1, 2));
        float mn0 = fmaxf(m0, mx0), mn1 = fmaxf(m1, mx1);
        float al0 = expf(m0 - mn0), al1 = expf(m1 - mn1);
        m0 = mn0; m1 = mn1;
        float s0 = 0.f, s1 = 0.f;
#pragma unroll
        for (int i = 0; i < 16; i++) {
            P[i][0] = expf(P[i][0] - m0); s0 += P[i][0];
            P[i][1] = expf(P[i][1] - m0); s0 += P[i][1];
            P[i][2] = expf(P[i][2] - m1); s1 += P[i][2];
            P[i][3] = expf(P[i][3] - m1); s1 += P[i][3];
        }
        s0 += __shfl_xor_sync(0xffffffffu, s0, 1);
        s0 += __shfl_xor_sync(0xffffffffu, s0, 2);
        s1 += __shfl_xor_sync(0xffffffffu, s1, 1);
        s1 += __shfl_xor_sync(0xffffffffu, s1, 2);
        l0 = l0 * al0 + s0;
        l1 = l1 * al1 + s1;
#pragma unroll
        for (int i = 0; i < 8; i++) {
            O[i][0] *= al0; O[i][1] *= al0;
            O[i][2] *= al1; O[i][3] *= al1;
        }
#pragma unroll
        for (int ks = 0; ks < 8; ks++) {
            uint32_t pah[4], pal[4];
            bfsplit2(P[2*ks][0],   P[2*ks][1],   pah[0], pal[0]);
            bfsplit2(P[2*ks][2],   P[2*ks][3],   pah[1], pal[1]);
            bfsplit2(P[2*ks+1][0], P[2*ks+1][1], pah[2], pal[2]);
            bfsplit2(P[2*ks+1][2], P[2*ks+1][3], pah[3], pal[3]);
            uint32_t kso = (uint32_t)(ks * 32);
#pragma unroll
            for (int nb = 0; nb < 4; nb++) {
                uint32_t addr = (uint32_t)((nb * 16 + b_rowi) * 272) + b_colb + kso;
                uint32_t vf[4], vfl[4];
                ldm4(vf, vb_h + addr);
                mma16816(O[2*nb],   pah, &vf[0]);
                mma16816(O[2*nb+1], pah, &vf[2]);
                mma16816(O[2*nb],   pal, &vf[0]);
                mma16816(O[2*nb+1], pal, &vf[2]);
                ldm4(vfl, vb_l + addr);
                mma16816(O[2*nb],   pah, &vfl[0]);
                mma16816(O[2*nb+1], pah, &vfl[2]);
            }
        }
        __syncthreads();
    }

    float i0 = 1.f / l0, i1 = 1.f / l1;
    int r0 = qt * 128 + w * 16 + (lane >> 2);
    int c0 = hh * 64 + ((lane & 3) << 1);
#pragma unroll
    for (int nj = 0; nj < 8; nj++) {
        int cc = c0 + nj * 8;
        uint32_t hi, lo;
        bfsplit2(O[nj][0] * i0, O[nj][1] * i0, hi, lo);
        size_t o0 = ((size_t)b * TT + r0) * DD + cc;
        *(uint32_t*)&Oh[o0] = hi;
        *(uint32_t*)&Ol[o0] = lo;
        bfsplit2(O[nj][2] * i1, O[nj][3] * i1, hi, lo);
        size_t o1 = ((size_t)b * TT + r0 + 8) * DD + cc;
        *(uint32_t*)&Oh[o1] = hi;
        *(uint32_t*)&Ol[o1] = lo;
    }
}

// ---------------- host-side helpers ----------------
static void conv_B(const float* W, __nv_bfloat16* bh, __nv_bfloat16* bl, int K, int N) {
    convT_kernel<<<dim3(N / 32, K / 64), 256>>>(W, bh, bl, K, N);
}
template <int EPI>
static void gemm(const __nv_bfloat16* ah, const __nv_bfloat16* al,
                 const __nv_bfloat16* bh, const __nv_bfloat16* bl,
                 const float* bias, const float* R, float* C,
                 __nv_bfloat16* Chi, __nv_bfloat16* Clo, int M, int N, int K) {
    static bool cfg = false;
    if (!cfg) {
        cudaFuncSetAttribute(gemm_mma<EPI>, cudaFuncAttributeMaxDynamicSharedMemorySize, GSMEM);
        cfg = true;
    }
    gemm_mma<EPI><<<dim3(N / 128, M / 128), 256, GSMEM>>>(ah, al, bh, bl, bias, R, C, Chi, Clo, M, N, K);
}

// ---------------- launch sequence ----------------
extern "C" void kernel_launch(void* const* d_in, const int* in_sizes, int n_in,
                              void* d_out, int out_size) {
    const int*   actions = (const int*)d_in[0];
    const int*   observ  = (const int*)d_in[1];
    const float* aemb    = (const float*)d_in[2];
    const float* oemb    = (const float*)d_in[3];
    const float* temb    = (const float*)d_in[4];
    const float* Wq      = (const float*)d_in[5];
    const float* bq      = (const float*)d_in[6];
    const float* Wk      = (const float*)d_in[7];
    const float* bk      = (const float*)d_in[8];
    const float* Wv      = (const float*)d_in[9];
    const float* bv      = (const float*)d_in[10];
    const float* Wo      = (const float*)d_in[11];
    const float* bo      = (const float*)d_in[12];
    const float* ln1_g   = (const float*)d_in[13];
    const float* ln1_b   = (const float*)d_in[14];
    const float* ln2_g   = (const float*)d_in[15];
    const float* ln2_b   = (const float*)d_in[16];
    const float* W1      = (const float*)d_in[17];
    const float* b1      = (const float*)d_in[18];
    const float* W2      = (const float*)d_in[19];
    const float* b2      = (const float*)d_in[20];
    const float* out_g   = (const float*)d_in[21];
    const float* out_b   = (const float*)d_in[22];
    const float* Wout    = (const float*)d_in[23];
    const float* bout    = (const float*)d_in[24];

    float *x, *qkv, *b3, *ct, *st;
    __nv_bfloat16 *ah, *al, *fh, *fl, *bh, *bl, *qh, *ql, *kh, *kl, *vh, *vl;
    cudaGetSymbolAddress((void**)&x,   g_x);
    cudaGetSymbolAddress((void**)&qkv, g_qkv);
    cudaGetSymbolAddress((void**)&b3,  g_b3);
    cudaGetSymbolAddress((void**)&ct,  g_cos);
    cudaGetSymbolAddress((void**)&st,  g_sin);
    cudaGetSymbolAddress((void**)&ah,  g_ah);
    cudaGetSymbolAddress((void**)&al,  g_al);
    cudaGetSymbolAddress((void**)&fh,  g_fh);
    cudaGetSymbolAddress((void**)&fl,  g_fl);
    cudaGetSymbolAddress((void**)&bh,  g_bh);
    cudaGetSymbolAddress((void**)&bl,  g_bl);
    cudaGetSymbolAddress((void**)&qh,  g_qh);
    cudaGetSymbolAddress((void**)&ql,  g_ql);
    cudaGetSymbolAddress((void**)&kh,  g_kh);
    cudaGetSymbolAddress((void**)&kl,  g_kl);
    cudaGetSymbolAddress((void**)&vh,  g_vh);
    cudaGetSymbolAddress((void**)&vl,  g_vl);

    static bool fcfg = false;
    if (!fcfg) {
        cudaFuncSetAttribute(flash_attn, cudaFuncAttributeMaxDynamicSharedMemorySize, FSMEM);
        fcfg = true;
    }

    trig_kernel<<<(TT * 32 + 255) / 256, 256>>>(ct, st);
    embed_kernel<<<(BT * DD + 255) / 256, 256>>>(actions, observ, aemb, oemb, temb, x);

    for (int i = 0; i < LL; i++) {
        ln_kernel<<<BT, 256>>>(x, ln1_g + (size_t)i * DD, ln1_b + (size_t)i * DD, ah, al);

        // fused QKV: Bt rows [0,1024)=Wq^T, [1024,2048)=Wk^T, [2048,3072)=Wv^T
        conv_B(Wq + (size_t)i * DD * DD, bh,                        bl,                        DD, DD);
        conv_B(Wk + (size_t)i * DD * DD, bh + (size_t)DD * DD,      bl + (size_t)DD * DD,      DD, DD);
        conv_B(Wv + (size_t)i * DD * DD, bh + (size_t)2 * DD * DD,  bl + (size_t)2 * DD * DD,  DD, DD);
        cudaMemcpyAsync(b3,            bq + (size_t)i * DD, DD * 4, cudaMemcpyDeviceToDevice);
        cudaMemcpyAsync(b3 + DD,       bk + (size_t)i * DD, DD * 4, cudaMemcpyDeviceToDevice);
        cudaMemcpyAsync(b3 + 2 * DD,   bv + (size_t)i * DD, DD * 4, cudaMemcpyDeviceToDevice);
        gemm<0>(ah, al, bh, bl, b3, nullptr, qkv, nullptr, nullptr, BT, 3 * DD, DD);

        rope_split_kernel<<<(BT * (DD / 2) + 255) / 256, 256>>>(qkv, ct, st, qh, ql, kh, kl);
        vsplit_kernel<<<dim3(TT / 32, DD / 32, BB), 256>>>(qkv, vh, vl);

        flash_attn<<<dim3(TT / 128, BB * HH), 256, FSMEM>>>(qh, ql, kh, kl, vh, vl, ah, al);

        conv_B(Wo + (size_t)i * DD * DD, bh, bl, DD, DD);
        gemm<2>(ah, al, bh, bl, bo + (size_t)i * DD, x, x, nullptr, nullptr, BT, DD, DD);

        ln_kernel<<<BT, 256>>>(x, ln2_g + (size_t)i * DD, ln2_b + (size_t)i * DD, ah, al);
        conv_B(W1 + (size_t)i * DD * DFF, bh, bl, DD, DFF);
        gemm<1>(ah, al, bh, bl, b1 + (size_t)i * DFF, nullptr, nullptr, fh, fl, BT, DFF, DD);

        conv_B(W2 + (size_t)i * DFF * DD, bh, bl, DFF, DD);
        gemm<2>(fh, fl, bh, bl, b2 + (size_t)i * DD, x, x, nullptr, nullptr, BT, DD, DFF);
    }

    ln_kernel<<<BT, 256>>>(x, out_g, out_b, ah, al);
    conv_B(Wout, bh, bl, DD, OV);
    gemm<0>(ah, al, bh, bl, bout, nullptr, (float*)d_out, nullptr, nullptr, BT, OV, DD);
}

// round 13
// speedup vs baseline: 1.3560x; 1.2662x over previous
#include <cuda_runtime.h>
#include <cuda_bf16.h>
#include <cuda_fp16.h>
#include <math.h>
#include <stdint.h>

#define LL 2
#define DD 1024
#define HH 16
#define DHH 64
#define DFF 4096
#define BB 2
#define TT 2048
#define OV 4096
#define BT (BB*TT)   // 4096

// ---------------- scratch (device globals; no runtime allocation) ----------------
__device__ float g_x  [BT*DD];
__device__ float g_qkv[(size_t)BT*3*DD];
__device__ float g_b3 [3*DD];
__device__ float g_cos[TT*32];
__device__ float g_sin[TT*32];
// fp16 GEMM operands (16B-aligned)
__device__ __align__(16) __half g_ah[(size_t)BT*DD];    // activation hi [BT,DD]
__device__ __align__(16) __half g_al[(size_t)BT*DD];
__device__ __align__(16) __half g_fh[(size_t)BT*DFF];   // ff hi [BT,DFF]
__device__ __align__(16) __half g_fl[(size_t)BT*DFF];
__device__ __align__(16) __half g_bw[(size_t)DFF*DD];   // B^T fp16 [N,K] (max 4096x1024)
// attention split operands (bf16, unchanged)
__device__ __align__(16) __nv_bfloat16 g_qh[(size_t)BB*HH*TT*DHH];  // [bh][t][d]
__device__ __align__(16) __nv_bfloat16 g_ql[(size_t)BB*HH*TT*DHH];
__device__ __align__(16) __nv_bfloat16 g_kh[(size_t)BB*HH*TT*DHH];
__device__ __align__(16) __nv_bfloat16 g_kl[(size_t)BB*HH*TT*DHH];
__device__ __align__(16) __nv_bfloat16 g_vh[(size_t)BB*HH*DHH*TT];  // [bh][d][t]
__device__ __align__(16) __nv_bfloat16 g_vl[(size_t)BB*HH*DHH*TT];

// ---------------- warp-MMA primitives (baseline PTX; no sm_103a features) ----------
__device__ __forceinline__ uint32_t smem_u32(const void* p) {
    uint32_t a;
    asm("{ .reg .u64 t; cvta.to.shared.u64 t, %1; cvt.u32.u64 %0, t; }" : "=r"(a) : "l"(p));
    return a;
}
__device__ __forceinline__ void ldm4(uint32_t* r, uint32_t addr) {
    asm volatile("ldmatrix.sync.aligned.m8n8.x4.shared.b16 {%0,%1,%2,%3}, [%4];"
                 : "=r"(r[0]), "=r"(r[1]), "=r"(r[2]), "=r"(r[3]) : "r"(addr));
}
// bf16 mma (flash attention)
__device__ __forceinline__ void mma16816(float* d, const uint32_t* a, const uint32_t* b) {
    asm volatile("mma.sync.aligned.m16n8k16.row.col.f32.bf16.bf16.f32 "
                 "{%0,%1,%2,%3}, {%4,%5,%6,%7}, {%8,%9}, {%0,%1,%2,%3};"
                 : "+f"(d[0]), "+f"(d[1]), "+f"(d[2]), "+f"(d[3])
                 : "r"(a[0]), "r"(a[1]), "r"(a[2]), "r"(a[3]), "r"(b[0]), "r"(b[1]));
}
// fp16 mma (GEMMs)
__device__ __forceinline__ void mma16816h(float* d, const uint32_t* a, const uint32_t* b) {
    asm volatile("mma.sync.aligned.m16n8k16.row.col.f32.f16.f16.f32 "
                 "{%0,%1,%2,%3}, {%4,%5,%6,%7}, {%8,%9}, {%0,%1,%2,%3};"
                 : "+f"(d[0]), "+f"(d[1]), "+f"(d[2]), "+f"(d[3])
                 : "r"(a[0]), "r"(a[1]), "r"(a[2]), "r"(a[3]), "r"(b[0]), "r"(b[1]));
}
#define CPA(dst, src) asm volatile("cp.async.cg.shared.global [%0], [%1], 16;" :: "r"(dst), "l"(src))
#define CPC()         asm volatile("cp.async.commit_group;")
#define CPW(n)        asm volatile("cp.async.wait_group %0;" :: "n"(n))

__device__ __forceinline__ uint32_t bfpack(float x, float y) {
    __nv_bfloat162 t;
    t.x = __float2bfloat16_rn(x);
    t.y = __float2bfloat16_rn(y);
    return *(uint32_t*)&t;
}
__device__ __forceinline__ void bfsplit2(float x, float y, uint32_t& hi, uint32_t& lo) {
    __nv_bfloat16 hx = __float2bfloat16_rn(x), hy = __float2bfloat16_rn(y);
    __nv_bfloat162 H; H.x = hx; H.y = hy;
    hi = *(uint32_t*)&H;
    lo = bfpack(x - __bfloat162float(hx), y - __bfloat162float(hy));
}
// fp16 hi/lo split of a float pair
__device__ __forceinline__ void hsplit2(float x, float y, uint32_t& hi, uint32_t& lo) {
    __half hx = __float2half_rn(x), hy = __float2half_rn(y);
    __half2 H; H.x = hx; H.y = hy;
    hi = *(uint32_t*)&H;
    __half2 L;
    L.x = __float2half_rn(x - __half2float(hx));
    L.y = __float2half_rn(y - __half2float(hy));
    lo = *(uint32_t*)&L;
}

// ---------------- transpose + fp16 round: W[K,N] -> Bt[N,K] ----------------
__global__ void convT_kernel(const float* __restrict__ W, __half* __restrict__ ht,
                             int K, int N) {
    __shared__ float t[64][33];
    int n0 = blockIdx.x * 32, k0 = blockIdx.y * 64;
    int tx = threadIdx.x & 31, ty = threadIdx.x >> 5;
#pragma unroll
    for (int ky = 0; ky < 64; ky += 8)
        t[ky + ty][tx] = W[(size_t)(k0 + ky + ty) * N + n0 + tx];
    __syncthreads();
    int kl = threadIdx.x & 63, nb = threadIdx.x >> 6;
#pragma unroll
    for (int n = nb; n < 32; n += 4) {
        float v = t[kl][n];
        ht[(size_t)(n0 + n) * K + k0 + kl] = __float2half_rn(v);
    }
}

// ---------------- fp16 2-pass GEMM: C = (Ah+Al)@B + bias (+epi), 3-stage cp.async -----
// EPI: 0 = bias -> fp32 C; 1 = bias+GELU -> fp16 split (Chi, Clo); 2 = bias+residual -> fp32 C
#define TROW 72
#define TBYTES (128*TROW*2)      // 18432 per tile
#define GSMEM (3*3*TBYTES)       // 165888 (3 stages x 3 tiles)

template <int EPI>
__global__ __launch_bounds__(256)
void gemm_mma(const __half* __restrict__ Ahi, const __half* __restrict__ Alo,
              const __half* __restrict__ Bw,
              const float* __restrict__ bias, const float* __restrict__ R,
              float* __restrict__ C, __half* __restrict__ Chi,
              __half* __restrict__ Clo, int M, int N, int K) {
    extern __shared__ __align__(16) char smem[];
    const uint32_t sb = smem_u32(smem);
    int tid = threadIdx.x, lane = tid & 31, w = tid >> 5;
    int wm = w >> 2, wn = w & 3;
    int bm = blockIdx.y << 7, bn = blockIdx.x << 7;

    float acc[4][4][4];
#pragma unroll
    for (int i = 0; i < 4; i++)
#pragma unroll
        for (int j = 0; j < 4; j++)
#pragma unroll
            for (int z = 0; z < 4; z++) acc[i][j][z] = 0.f;

    int lrow = tid >> 3, lseg = tid & 7;
    auto issue = [&](int kc, int st) {
        int kb = kc << 6;
        uint32_t base = sb + st * 3 * TBYTES;
#pragma unroll
        for (int i = 0; i < 4; i++) {
            int row = lrow + i * 32;
            uint32_t so = base + (uint32_t)(row * 144 + lseg * 16);
            size_t ga = (size_t)(bm + row) * K + kb + lseg * 8;
            size_t gb = (size_t)(bn + row) * K + kb + lseg * 8;
            CPA(so,              Ahi + ga);
            CPA(so + TBYTES,     Alo + ga);
            CPA(so + 2*TBYTES,   Bw  + gb);
        }
        CPC();
    };

    const int nch = K >> 6;
    issue(0, 0);
    issue(1, 1);

    int a_row = wm * 64 + (lane & 15), a_col = (lane >> 4) << 3;
    int b_row = wn * 32 + ((lane >> 4) << 3) + (lane & 7), b_col = ((lane >> 3) & 1) << 3;
    uint32_t aoff = (uint32_t)(a_row * TROW + a_col) * 2;
    uint32_t boff = (uint32_t)(b_row * TROW + b_col) * 2 + 2 * TBYTES;

    for (int kc = 0; kc < nch; kc++) {
        if (kc + 1 < nch) { CPW(1); }
        else              { CPW(0); }
        __syncthreads();
        if (kc + 2 < nch) issue(kc + 2, (kc + 2) % 3);

        uint32_t base = sb + (uint32_t)((kc % 3) * 3 * TBYTES);
        uint32_t aoff_h = base + aoff, aoff_l = aoff_h + TBYTES;
        uint32_t boff_b = base + boff;
#pragma unroll
        for (int ks = 0; ks < 4; ks++) {
            uint32_t ah[4][4], al[4][4], bw[8];
            uint32_t kso = (uint32_t)(ks * 32);
#pragma unroll
            for (int mi = 0; mi < 4; mi++) {
                ldm4(ah[mi], aoff_h + (uint32_t)(mi * 16 * TROW * 2) + kso);
                ldm4(al[mi], aoff_l + (uint32_t)(mi * 16 * TROW * 2) + kso);
            }
            ldm4(&bw[0], boff_b + kso);
            ldm4(&bw[4], boff_b + (uint32_t)(16 * TROW * 2) + kso);
#pragma unroll
            for (int mi = 0; mi < 4; mi++)
#pragma unroll
                for (int ni = 0; ni < 4; ni++)
                    mma16816h(acc[mi][ni], ah[mi], &bw[ni * 2]);
#pragma unroll
            for (int mi = 0; mi < 4; mi++)
#pragma unroll
                for (int ni = 0; ni < 4; ni++)
                    mma16816h(acc[mi][ni], al[mi], &bw[ni * 2]);
        }
    }

    // ---- epilogue ----
#pragma unroll
    for (int mi = 0; mi < 4; mi++) {
#pragma unroll
        for (int ni = 0; ni < 4; ni++) {
            int r0 = bm + wm * 64 + mi * 16 + (lane >> 2);
            int c0 = bn + wn * 32 + ni * 8 + ((lane & 3) << 1);
#pragma unroll
            for (int half = 0; half < 2; half++) {
                int gm = r0 + half * 8;
                float v0 = acc[mi][ni][half * 2]     + bias[c0];
                float v1 = acc[mi][ni][half * 2 + 1] + bias[c0 + 1];
                if (EPI == 1) {
                    v0 *= normcdff(v0); v1 *= normcdff(v1);
                    uint32_t hi, lo;
                    hsplit2(v0, v1, hi, lo);
                    *(uint32_t*)&Chi[(size_t)gm * N + c0] = hi;
                    *(uint32_t*)&Clo[(size_t)gm * N + c0] = lo;
                } else {
                    if (EPI == 2) {
                        v0 += R[(size_t)gm * N + c0];
                        v1 += R[(size_t)gm * N + c0 + 1];
                    }
                    float2 o; o.x = v0; o.y = v1;
                    *(float2*)&C[(size_t)gm * N + c0] = o;
                }
            }
        }
    }
}

// ---------------- RoPE trig tables (double precision; fast-math-proof) ----------------
__global__ void trig_kernel(float* __restrict__ ct, float* __restrict__ st) {
    int i = blockIdx.x * 256 + threadIdx.x;
    if (i >= TT * 32) return;
    int t = i >> 5, p = i & 31;
    double inv = exp2(-13.287712379549449 * ((double)(2 * p) * (1.0 / 64.0)));
    float invf = (float)inv;
    float angf = (float)((double)t * (double)invf);
    double c, s;
    sincos((double)angf, &s, &c);
    ct[i] = (float)c;
    st[i] = (float)s;
}

// ---------------- embedding ----------------
__global__ void embed_kernel(const int* __restrict__ act, const int* __restrict__ obs,
                             const float* __restrict__ aemb, const float* __restrict__ oemb,
                             const float* __restrict__ temb, float* __restrict__ x) {
    int idx = blockIdx.x * blockDim.x + threadIdx.x;
    if (idx >= BT * DD) return;
    int r = idx / DD, d = idx % DD;
    x[idx] = aemb[(size_t)act[r] * DD + d] + temb[d]
           + oemb[(size_t)obs[r] * DD + d] + temb[DD + d];
}

// ---------------- layernorm -> fp16 hi/lo split directly ----------------
__global__ void ln_kernel(const float* __restrict__ x, const float* __restrict__ g,
                          const float* __restrict__ b, __half* __restrict__ yh,
                          __half* __restrict__ yl) {
    int r = blockIdx.x;
    const float* xr = x + (size_t)r * DD;
    float v[4];
    float s = 0.f, ss = 0.f;
#pragma unroll
    for (int i = 0; i < 4; i++) {
        float t = xr[threadIdx.x + i * 256];
        v[i] = t; s += t; ss += t * t;
    }
#pragma unroll
    for (int o = 16; o > 0; o >>= 1) {
        s  += __shfl_xor_sync(0xffffffffu, s,  o);
        ss += __shfl_xor_sync(0xffffffffu, ss, o);
    }
    __shared__ float rs[8], rss[8];
    int w = threadIdx.x >> 5;
    if ((threadIdx.x & 31) == 0) { rs[w] = s; rss[w] = ss; }
    __syncthreads();
    if (threadIdx.x == 0) {
        float a = 0.f, c = 0.f;
#pragma unroll
        for (int i = 0; i < 8; i++) { a += rs[i]; c += rss[i]; }
        rs[0] = a; rss[0] = c;
    }
    __syncthreads();
    float mean = rs[0] * (1.f / DD);
    float var  = rss[0] * (1.f / DD) - mean * mean;
    float inv  = rsqrtf(var + 1e-5f);
#pragma unroll
    for (int i = 0; i < 4; i++) {
        int d = threadIdx.x + i * 256;
        float val = (v[i] - mean) * inv * g[d] + b[d];
        __half h = __float2half_rn(val);
        yh[(size_t)r * DD + d] = h;
        yl[(size_t)r * DD + d] = __float2half_rn(val - __half2float(h));
    }
}

// ---------------- RoPE + bf16 hi/lo split from fused QKV buffer [BT,3072] -------------
__global__ void rope_split_kernel(const float* __restrict__ QKV,
                                  const float* __restrict__ ct, const float* __restrict__ st,
                                  __nv_bfloat16* __restrict__ qh, __nv_bfloat16* __restrict__ ql,
                                  __nv_bfloat16* __restrict__ kh, __nv_bfloat16* __restrict__ kl) {
    int idx = blockIdx.x * 256 + threadIdx.x;
    if (idx >= BT * (DD / 2)) return;
    int r  = idx >> 9;
    int c2 = idx & 511;
    int hh = c2 >> 5, p = c2 & 31;
    int b = r >> 11, t = r & (TT - 1);
    float c = ct[t * 32 + p];
    float s = st[t * 32 + p];
    size_t ib = (size_t)r * (3 * DD) + hh * 64 + 2 * p;
    size_t ob = ((size_t)(b * HH + hh) * TT + t) * 64 + 2 * p;

    float q0 = QKV[ib], q1 = QKV[ib + 1];
    float o0 = q0 * c - q1 * s, o1 = q0 * s + q1 * c;
    __nv_bfloat16 h0 = __float2bfloat16_rn(o0), h1 = __float2bfloat16_rn(o1);
    qh[ob] = h0; qh[ob + 1] = h1;
    ql[ob]     = __float2bfloat16_rn(o0 - __bfloat162float(h0));
    ql[ob + 1] = __float2bfloat16_rn(o1 - __bfloat162float(h1));

    float k0 = QKV[ib + DD], k1 = QKV[ib + DD + 1];
    float e0 = k0 * c - k1 * s, e1 = k0 * s + k1 * c;
    __nv_bfloat16 g0 = __float2bfloat16_rn(e0), g1 = __float2bfloat16_rn(e1);
    kh[ob] = g0; kh[ob + 1] = g1;
    kl[ob]     = __float2bfloat16_rn(e0 - __bfloat162float(g0));
    kl[ob + 1] = __float2bfloat16_rn(e1 - __bfloat162float(g1));
}

// ---------------- V split + transpose into [bh][d][t] (from fused QKV) ----------------
__global__ void vsplit_kernel(const float* __restrict__ QKV,
                              __nv_bfloat16* __restrict__ vh, __nv_bfloat16* __restrict__ vl) {
    __shared__ float ts[32][33];
    int t0 = blockIdx.x * 32, d0 = blockIdx.y * 32, b = blockIdx.z;
    int tx = threadIdx.x & 31, ty = threadIdx.x >> 5;
#pragma unroll
    for (int i = ty; i < 32; i += 8)
        ts[i][tx] = QKV[((size_t)b * TT + t0 + i) * (3 * DD) + 2 * DD + d0 + tx];
    __syncthreads();
    int hh = d0 >> 6, dl0 = d0 & 63;
#pragma unroll
    for (int i = ty; i < 32; i += 8) {
        float v = ts[tx][i];
        size_t o = ((size_t)(b * HH + hh) * 64 + dl0 + i) * TT + t0 + tx;
        __nv_bfloat16 h = __float2bfloat16_rn(v);
        vh[o] = h;
        vl[o] = __float2bfloat16_rn(v - __bfloat162float(h));
    }
}

// ================= fused flash attention (bf16 3-pass internally; fp16 output) ========
#define FQ_H 0
#define FQ_L 18432
#define FK_H(st) (36864 + (st)*36864)
#define FK_L(st) (FK_H(st) + 18432)
#define FV_H(st) (110592 + (st)*34816)
#define FV_L(st) (FV_H(st) + 17408)
#define FSMEM 180224

__global__ __launch_bounds__(256)
void flash_attn(const __nv_bfloat16* __restrict__ Qh, const __nv_bfloat16* __restrict__ Ql,
                const __nv_bfloat16* __restrict__ Kh, const __nv_bfloat16* __restrict__ Kl,
                const __nv_bfloat16* __restrict__ Vh, const __nv_bfloat16* __restrict__ Vl,
                __half* __restrict__ Oh, __half* __restrict__ Ol) {
    int qt = gridDim.x - 1 - blockIdx.x;
    int bh = blockIdx.y;
    int b = bh >> 4, hh = bh & 15;
    extern __shared__ __align__(16) char smem[];
    const uint32_t sb = smem_u32(smem);
    int tid = threadIdx.x, lane = tid & 31, w = tid >> 5;

    {
        int row = tid >> 1, segb = (tid & 1) * 4;
        size_t qg = ((size_t)bh * TT + qt * 128 + row) * 64 + segb * 8;
#pragma unroll
        for (int s = 0; s < 4; s++) {
            uint32_t so = (uint32_t)(row * 144 + (segb + s) * 16);
            *(uint4*)(smem + FQ_H + so) = *(const uint4*)(Qh + qg + s * 8);
            *(uint4*)(smem + FQ_L + so) = *(const uint4*)(Ql + qg + s * 8);
        }
    }

    auto issueKV = [&](int kt, int st) {
        int row = tid >> 1, segb = (tid & 1) * 4;
        size_t kg = ((size_t)bh * TT + kt * 128 + row) * 64 + segb * 8;
#pragma unroll
        for (int s = 0; s < 4; s++) {
            uint32_t so = (uint32_t)(row * 144 + (segb + s) * 16);
            CPA(sb + FK_H(st) + so, Kh + kg + s * 8);
            CPA(sb + FK_L(st) + so, Kl + kg + s * 8);
        }
        int vrow = tid >> 2, vsegb = (tid & 3) * 4;
        size_t vg = ((size_t)bh * 64 + vrow) * TT + kt * 128 + vsegb * 8;
#pragma unroll
        for (int s = 0; s < 4; s++) {
            uint32_t so = (uint32_t)(vrow * 272 + (vsegb + s) * 16);
            CPA(sb + FV_H(st) + so, Vh + vg + s * 8);
            CPA(sb + FV_L(st) + so, Vl + vg + s * 8);
        }
        CPC();
    };
    issueKV(0, 0);
    __syncthreads();

    uint32_t qfh[4][4], qfl[4][4];
    {
        int a_row = w * 16 + (lane & 15), a_col = (lane >> 4) << 3;
        uint32_t qa = (uint32_t)(a_row * 144 + a_col * 2);
#pragma unroll
        for (int ks = 0; ks < 4; ks++) {
            ldm4(qfh[ks], sb + FQ_H + qa + ks * 32);
            ldm4(qfl[ks], sb + FQ_L + qa + ks * 32);
        }
    }

    float m0 = -3.0e38f, m1 = -3.0e38f, l0 = 0.f, l1 = 0.f;
    float O[8][4];
#pragma unroll
    for (int i = 0; i < 8; i++)
#pragma unroll
        for (int z = 0; z < 4; z++) O[i][z] = 0.f;

    int b_rowi = ((lane >> 4) << 3) + (lane & 7);
    int b_colb = (((lane >> 3) & 1) << 3) * 2;

    for (int kt = 0; kt <= qt; kt++) {
        if (kt < qt) { issueKV(kt + 1, (kt + 1) & 1); CPW(1); }
        else         { CPW(0); }
        __syncthreads();
        uint32_t kb_h = sb + FK_H(kt & 1), kb_l = sb + FK_L(kt & 1);
        uint32_t vb_h = sb + FV_H(kt & 1), vb_l = sb + FV_L(kt & 1);

        float P[16][4];
#pragma unroll
        for (int i = 0; i < 16; i++)
#pragma unroll
            for (int z = 0; z < 4; z++) P[i][z] = 0.f;
#pragma unroll
        for (int ks = 0; ks < 4; ks++) {
            uint32_t kso = (uint32_t)(ks * 32);
#pragma unroll
            for (int nb = 0; nb < 8; nb++) {
                uint32_t addr = (uint32_t)((nb * 16 + b_rowi) * 144) + b_colb + kso;
                uint32_t kf[4], kfl[4];
                ldm4(kf, kb_h + addr);
                mma16816(P[2*nb],   qfh[ks], &kf[0]);
                mma16816(P[2*nb+1], qfh[ks], &kf[2]);
                mma16816(P[2*nb],   qfl[ks], &kf[0]);
                mma16816(P[2*nb+1], qfl[ks], &kf[2]);
                ldm4(kfl, kb_l + addr);
                mma16816(P[2*nb],   qfh[ks], &kfl[0]);
                mma16816(P[2*nb+1], qfh[ks], &kfl[2]);
            }
        }
#pragma unroll
        for (int i = 0; i < 16; i++)
#pragma unroll
            for (int z = 0; z < 4; z++) P[i][z] *= 0.125f;
        if (kt == qt) {
            int r0 = w * 16 + (lane >> 2);
#pragma unroll
            for (int i = 0; i < 16; i++) {
#pragma unroll
                for (int z = 0; z < 4; z++) {
                    int col = i * 8 + ((lane & 3) << 1) + (z & 1);
                    int row = r0 + ((z >> 1) << 3);
                    if (col > row) P[i][z] = -3.0e38f;
                }
            }
        }
        float mx0 = -3.0e38f, mx1 = -3.0e38f;
#pragma unroll
        for (int i = 0; i < 16; i++) {
            mx0 = fmaxf(mx0, fmaxf(P[i][0], P[i][1]));
            mx1 = fmaxf(mx1, fmaxf(P[i][2], P[i][3]));
        }
        mx0 = fmaxf(mx0, __shfl_xor_sync(0xffffffffu, mx0, 1));
        mx0 = fmaxf(mx0, __shfl_xor_sync(0xffffffffu, mx0, 2));
        mx1 = fmaxf(mx1, __shfl_xor_sync(0xffffffffu, mx1, 1));
        mx1 = fmaxf(mx1, __shfl_xor_sync(0xffffffffu, mx1, 2));
        float mn0 = fmaxf(m0, mx0), mn1 = fmaxf(m1, mx1);
        float al0 = expf(m0 - mn0), al1 = expf(m1 - mn1);
        m0 = mn0; m1 = mn1;
        float s0 = 0.f, s1 = 0.f;
#pragma unroll
        for (int i = 0; i < 16; i++) {
            P[i][0] = expf(P[i][0] - m0); s0 += P[i][0];
            P[i][1] = expf(P[i][1] - m0); s0 += P[i][1];
            P[i][2] = expf(P[i][2] - m1); s1 += P[i][2];
            P[i][3] = expf(P[i][3] - m1); s1 += P[i][3];
        }
        s0 += __shfl_xor_sync(0xffffffffu, s0, 1);
        s0 += __shfl_xor_sync(0xffffffffu, s0, 2);
        s1 += __shfl_xor_sync(0xffffffffu, s1, 1);
        s1 += __shfl_xor_sync(0xffffffffu, s1, 2);
        l0 = l0 * al0 + s0;
        l1 = l1 * al1 + s1;
#pragma unroll
        for (int i = 0; i < 8; i++) {
            O[i][0] *= al0; O[i][1] *= al0;
            O[i][2] *= al1; O[i][3] *= al1;
        }
#pragma unroll
        for (int ks = 0; ks < 8; ks++) {
            uint32_t pah[4], pal[4];
            bfsplit2(P[2*ks][0],   P[2*ks][1],   pah[0], pal[0]);
            bfsplit2(P[2*ks][2],   P[2*ks][3],   pah[1], pal[1]);
            bfsplit2(P[2*ks+1][0], P[2*ks+1][1], pah[2], pal[2]);
            bfsplit2(P[2*ks+1][2], P[2*ks+1][3], pah[3], pal[3]);
            uint32_t kso = (uint32_t)(ks * 32);
#pragma unroll
            for (int nb = 0; nb < 4; nb++) {
                uint32_t addr = (uint32_t)((nb * 16 + b_rowi) * 272) + b_colb + kso;
                uint32_t vf[4], vfl[4];
                ldm4(vf, vb_h + addr);
                mma16816(O[2*nb],   pah, &vf[0]);
                mma16816(O[2*nb+1], pah, &vf[2]);
                mma16816(O[2*nb],   pal, &vf[0]);
                mma16816(O[2*nb+1], pal, &vf[2]);
                ldm4(vfl, vb_l + addr);
                mma16816(O[2*nb],   pah, &vfl[0]);
                mma16816(O[2*nb+1], pah, &vfl[2]);
            }
        }
        __syncthreads();
    }

    float i0 = 1.f / l0, i1 = 1.f / l1;
    int r0 = qt * 128 + w * 16 + (lane >> 2);
    int c0 = hh * 64 + ((lane & 3) << 1);
#pragma unroll
    for (int nj = 0; nj < 8; nj++) {
        int cc = c0 + nj * 8;
        uint32_t hi, lo;
        hsplit2(O[nj][0] * i0, O[nj][1] * i0, hi, lo);
        size_t o0 = ((size_t)b * TT + r0) * DD + cc;
        *(uint32_t*)&Oh[o0] = hi;
        *(uint32_t*)&Ol[o0] = lo;
        hsplit2(O[nj][2] * i1, O[nj][3] * i1, hi, lo);
        size_t o1 = ((size_t)b * TT + r0 + 8) * DD + cc;
        *(uint32_t*)&Oh[o1] = hi;
        *(uint32_t*)&Ol[o1] = lo;
    }
}

// ---------------- host-side helpers ----------------
static void conv_B(const float* W, __half* bw, int K, int N) {
    convT_kernel<<<dim3(N / 32, K / 64), 256>>>(W, bw, K, N);
}
template <int EPI>
static void gemm(const __half* ah, const __half* al, const __half* bw,
                 const float* bias, const float* R, float* C,
                 __half* Chi, __half* Clo, int M, int N, int K) {
    static bool cfg = false;
    if (!cfg) {
        cudaFuncSetAttribute(gemm_mma<EPI>, cudaFuncAttributeMaxDynamicSharedMemorySize, GSMEM);
        cfg = true;
    }
    gemm_mma<EPI><<<dim3(N / 128, M / 128), 256, GSMEM>>>(ah, al, bw, bias, R, C, Chi, Clo, M, N, K);
}

// ---------------- launch sequence ----------------
extern "C" void kernel_launch(void* const* d_in, const int* in_sizes, int n_in,
                              void* d_out, int out_size) {
    const int*   actions = (const int*)d_in[0];
    const int*   observ  = (const int*)d_in[1];
    const float* aemb    = (const float*)d_in[2];
    const float* oemb    = (const float*)d_in[3];
    const float* temb    = (const float*)d_in[4];
    const float* Wq      = (const float*)d_in[5];
    const float* bq      = (const float*)d_in[6];
    const float* Wk      = (const float*)d_in[7];
    const float* bk      = (const float*)d_in[8];
    const float* Wv      = (const float*)d_in[9];
    const float* bv      = (const float*)d_in[10];
    const float* Wo      = (const float*)d_in[11];
    const float* bo      = (const float*)d_in[12];
    const float* ln1_g   = (const float*)d_in[13];
    const float* ln1_b   = (const float*)d_in[14];
    const float* ln2_g   = (const float*)d_in[15];
    const float* ln2_b   = (const float*)d_in[16];
    const float* W1      = (const float*)d_in[17];
    const float* b1      = (const float*)d_in[18];
    const float* W2      = (const float*)d_in[19];
    const float* b2      = (const float*)d_in[20];
    const float* out_g   = (const float*)d_in[21];
    const float* out_b   = (const float*)d_in[22];
    const float* Wout    = (const float*)d_in[23];
    const float* bout    = (const float*)d_in[24];

    float *x, *qkv, *b3, *ct, *st;
    __half *ah, *al, *fh, *fl, *bw;
    __nv_bfloat16 *qh, *ql, *kh, *kl, *vh, *vl;
    cudaGetSymbolAddress((void**)&x,   g_x);
    cudaGetSymbolAddress((void**)&qkv, g_qkv);
    cudaGetSymbolAddress((void**)&b3,  g_b3);
    cudaGetSymbolAddress((void**)&ct,  g_cos);
    cudaGetSymbolAddress((void**)&st,  g_sin);
    cudaGetSymbolAddress((void**)&ah,  g_ah);
    cudaGetSymbolAddress((void**)&al,  g_al);
    cudaGetSymbolAddress((void**)&fh,  g_fh);
    cudaGetSymbolAddress((void**)&fl,  g_fl);
    cudaGetSymbolAddress((void**)&bw,  g_bw);
    cudaGetSymbolAddress((void**)&qh,  g_qh);
    cudaGetSymbolAddress((void**)&ql,  g_ql);
    cudaGetSymbolAddress((void**)&kh,  g_kh);
    cudaGetSymbolAddress((void**)&kl,  g_kl);
    cudaGetSymbolAddress((void**)&vh,  g_vh);
    cudaGetSymbolAddress((void**)&vl,  g_vl);

    static bool fcfg = false;
    if (!fcfg) {
        cudaFuncSetAttribute(flash_attn, cudaFuncAttributeMaxDynamicSharedMemorySize, FSMEM);
        fcfg = true;
    }

    trig_kernel<<<(TT * 32 + 255) / 256, 256>>>(ct, st);
    embed_kernel<<<(BT * DD + 255) / 256, 256>>>(actions, observ, aemb, oemb, temb, x);

    for (int i = 0; i < LL; i++) {
        ln_kernel<<<BT, 256>>>(x, ln1_g + (size_t)i * DD, ln1_b + (size_t)i * DD, ah, al);

        // fused QKV: Bt rows [0,1024)=Wq^T, [1024,2048)=Wk^T, [2048,3072)=Wv^T
        conv_B(Wq + (size_t)i * DD * DD, bw,                       DD, DD);
        conv_B(Wk + (size_t)i * DD * DD, bw + (size_t)DD * DD,     DD, DD);
        conv_B(Wv + (size_t)i * DD * DD, bw + (size_t)2 * DD * DD, DD, DD);
        cudaMemcpyAsync(b3,            bq + (size_t)i * DD, DD * 4, cudaMemcpyDeviceToDevice);
        cudaMemcpyAsync(b3 + DD,       bk + (size_t)i * DD, DD * 4, cudaMemcpyDeviceToDevice);
        cudaMemcpyAsync(b3 + 2 * DD,   bv + (size_t)i * DD, DD * 4, cudaMemcpyDeviceToDevice);
        gemm<0>(ah, al, bw, b3, nullptr, qkv, nullptr, nullptr, BT, 3 * DD, DD);

        rope_split_kernel<<<(BT * (DD / 2) + 255) / 256, 256>>>(qkv, ct, st, qh, ql, kh, kl);
        vsplit_kernel<<<dim3(TT / 32, DD / 32, BB), 256>>>(qkv, vh, vl);

        flash_attn<<<dim3(TT / 128, BB * HH), 256, FSMEM>>>(qh, ql, kh, kl, vh, vl, ah, al);

        conv_B(Wo + (size_t)i * DD * DD, bw, DD, DD);
        gemm<2>(ah, al, bw, bo + (size_t)i * DD, x, x, nullptr, nullptr, BT, DD, DD);

        ln_kernel<<<BT, 256>>>(x, ln2_g + (size_t)i * DD, ln2_b + (size_t)i * DD, ah, al);
        conv_B(W1 + (size_t)i * DD * DFF, bw, DD, DFF);
        gemm<1>(ah, al, bw, b1 + (size_t)i * DFF, nullptr, nullptr, fh, fl, BT, DFF, DD);

        conv_B(W2 + (size_t)i * DFF * DD, bw, DFF, DD);
        gemm<2>(fh, fl, bw, b2 + (size_t)i * DD, x, x, nullptr, nullptr, BT, DD, DFF);
    }

    ln_kernel<<<BT, 256>>>(x, out_g, out_b, ah, al);
    conv_B(Wout, bw, DD, OV);
    gemm<0>(ah, al, bw, bout, nullptr, (float*)d_out, nullptr, nullptr, BT, OV, DD);
}

// round 14
// speedup vs baseline: 1.4887x; 1.0978x over previous
#include <cuda_runtime.h>
#include <cuda_bf16.h>
#include <cuda_fp16.h>
#include <math.h>
#include <stdint.h>

#define LL 2
#define DD 1024
#define HH 16
#define DHH 64
#define DFF 4096
#define BB 2
#define TT 2048
#define OV 4096
#define BT (BB*TT)   // 4096

// ---------------- scratch (device globals; no runtime allocation) ----------------
__device__ float g_x  [BT*DD];
__device__ float g_qkv[(size_t)BT*3*DD];
__device__ float g_b3 [3*DD];
__device__ float g_cos[TT*32];
__device__ float g_sin[TT*32];
// fp16 GEMM operands (16B-aligned)
__device__ __align__(16) __half g_ah[(size_t)BT*DD];    // activation hi [BT,DD]
__device__ __align__(16) __half g_al[(size_t)BT*DD];
__device__ __align__(16) __half g_fh[(size_t)BT*DFF];   // ff hi [BT,DFF]
__device__ __align__(16) __half g_fl[(size_t)BT*DFF];
__device__ __align__(16) __half g_bw[(size_t)DFF*DD];   // B^T fp16 [N,K] (max 4096x1024)
// attention split operands (bf16, unchanged)
__device__ __align__(16) __nv_bfloat16 g_qh[(size_t)BB*HH*TT*DHH];  // [bh][t][d]
__device__ __align__(16) __nv_bfloat16 g_ql[(size_t)BB*HH*TT*DHH];
__device__ __align__(16) __nv_bfloat16 g_kh[(size_t)BB*HH*TT*DHH];
__device__ __align__(16) __nv_bfloat16 g_kl[(size_t)BB*HH*TT*DHH];
__device__ __align__(16) __nv_bfloat16 g_vh[(size_t)BB*HH*DHH*TT];  // [bh][d][t]
__device__ __align__(16) __nv_bfloat16 g_vl[(size_t)BB*HH*DHH*TT];

// ---------------- warp-MMA primitives (baseline PTX; no sm_103a features) ----------
__device__ __forceinline__ uint32_t smem_u32(const void* p) {
    uint32_t a;
    asm("{ .reg .u64 t; cvta.to.shared.u64 t, %1; cvt.u32.u64 %0, t; }" : "=r"(a) : "l"(p));
    return a;
}
__device__ __forceinline__ void ldm4(uint32_t* r, uint32_t addr) {
    asm volatile("ldmatrix.sync.aligned.m8n8.x4.shared.b16 {%0,%1,%2,%3}, [%4];"
                 : "=r"(r[0]), "=r"(r[1]), "=r"(r[2]), "=r"(r[3]) : "r"(addr));
}
// bf16 mma (flash attention)
__device__ __forceinline__ void mma16816(float* d, const uint32_t* a, const uint32_t* b) {
    asm volatile("mma.sync.aligned.m16n8k16.row.col.f32.bf16.bf16.f32 "
                 "{%0,%1,%2,%3}, {%4,%5,%6,%7}, {%8,%9}, {%0,%1,%2,%3};"
                 : "+f"(d[0]), "+f"(d[1]), "+f"(d[2]), "+f"(d[3])
                 : "r"(a[0]), "r"(a[1]), "r"(a[2]), "r"(a[3]), "r"(b[0]), "r"(b[1]));
}
// fp16 mma (GEMMs)
__device__ __forceinline__ void mma16816h(float* d, const uint32_t* a, const uint32_t* b) {
    asm volatile("mma.sync.aligned.m16n8k16.row.col.f32.f16.f16.f32 "
                 "{%0,%1,%2,%3}, {%4,%5,%6,%7}, {%8,%9}, {%0,%1,%2,%3};"
                 : "+f"(d[0]), "+f"(d[1]), "+f"(d[2]), "+f"(d[3])
                 : "r"(a[0]), "r"(a[1]), "r"(a[2]), "r"(a[3]), "r"(b[0]), "r"(b[1]));
}
#define CPA(dst, src) asm volatile("cp.async.cg.shared.global [%0], [%1], 16;" :: "r"(dst), "l"(src))
#define CPC()         asm volatile("cp.async.commit_group;")
#define CPW(n)        asm volatile("cp.async.wait_group %0;" :: "n"(n))

__device__ __forceinline__ uint32_t bfpack(float x, float y) {
    __nv_bfloat162 t;
    t.x = __float2bfloat16_rn(x);
    t.y = __float2bfloat16_rn(y);
    return *(uint32_t*)&t;
}
__device__ __forceinline__ void bfsplit2(float x, float y, uint32_t& hi, uint32_t& lo) {
    __nv_bfloat16 hx = __float2bfloat16_rn(x), hy = __float2bfloat16_rn(y);
    __nv_bfloat162 H; H.x = hx; H.y = hy;
    hi = *(uint32_t*)&H;
    lo = bfpack(x - __bfloat162float(hx), y - __bfloat162float(hy));
}
// fp16 hi/lo split of a float pair
__device__ __forceinline__ void hsplit2(float x, float y, uint32_t& hi, uint32_t& lo) {
    __half hx = __float2half_rn(x), hy = __float2half_rn(y);
    __half2 H; H.x = hx; H.y = hy;
    hi = *(uint32_t*)&H;
    __half2 L;
    L.x = __float2half_rn(x - __half2float(hx));
    L.y = __float2half_rn(y - __half2float(hy));
    lo = *(uint32_t*)&L;
}

// ---------------- transpose + fp16 round: W[K,N] -> Bt[N,K] ----------------
__global__ void convT_kernel(const float* __restrict__ W, __half* __restrict__ ht,
                             int K, int N) {
    __shared__ float t[64][33];
    int n0 = blockIdx.x * 32, k0 = blockIdx.y * 64;
    int tx = threadIdx.x & 31, ty = threadIdx.x >> 5;
#pragma unroll
    for (int ky = 0; ky < 64; ky += 8)
        t[ky + ty][tx] = W[(size_t)(k0 + ky + ty) * N + n0 + tx];
    __syncthreads();
    int kl = threadIdx.x & 63, nb = threadIdx.x >> 6;
#pragma unroll
    for (int n = nb; n < 32; n += 4) {
        float v = t[kl][n];
        ht[(size_t)(n0 + n) * K + k0 + kl] = __float2half_rn(v);
    }
}

// ---------------- fp16 2-pass GEMM: 2-stage cp.async, 2 CTAs/SM ----------------
// EPI: 0 = bias -> fp32 C; 1 = bias+GELU -> fp16 split (Chi, Clo); 2 = bias+residual -> fp32 C
#define TROW 72
#define TBYTES (128*TROW*2)      // 18432 per tile
#define GSMEM (2*3*TBYTES)       // 110592 (2 stages x 3 tiles) -> 2 CTAs/SM

template <int EPI>
__global__ __launch_bounds__(256, 2)
void gemm_mma(const __half* __restrict__ Ahi, const __half* __restrict__ Alo,
              const __half* __restrict__ Bw,
              const float* __restrict__ bias, const float* __restrict__ R,
              float* __restrict__ C, __half* __restrict__ Chi,
              __half* __restrict__ Clo, int M, int N, int K) {
    extern __shared__ __align__(16) char smem[];
    const uint32_t sb = smem_u32(smem);
    int tid = threadIdx.x, lane = tid & 31, w = tid >> 5;
    int wm = w >> 2, wn = w & 3;
    int bm = blockIdx.y << 7, bn = blockIdx.x << 7;

    float acc[4][4][4];
#pragma unroll
    for (int i = 0; i < 4; i++)
#pragma unroll
        for (int j = 0; j < 4; j++)
#pragma unroll
            for (int z = 0; z < 4; z++) acc[i][j][z] = 0.f;

    int lrow = tid >> 3, lseg = tid & 7;
    auto issue = [&](int kc, int st) {
        int kb = kc << 6;
        uint32_t base = sb + st * 3 * TBYTES;
#pragma unroll
        for (int i = 0; i < 4; i++) {
            int row = lrow + i * 32;
            uint32_t so = base + (uint32_t)(row * 144 + lseg * 16);
            size_t ga = (size_t)(bm + row) * K + kb + lseg * 8;
            size_t gb = (size_t)(bn + row) * K + kb + lseg * 8;
            CPA(so,              Ahi + ga);
            CPA(so + TBYTES,     Alo + ga);
            CPA(so + 2*TBYTES,   Bw  + gb);
        }
        CPC();
    };

    const int nch = K >> 6;
    issue(0, 0);

    int a_row = wm * 64 + (lane & 15), a_col = (lane >> 4) << 3;
    int b_row = wn * 32 + ((lane >> 4) << 3) + (lane & 7), b_col = ((lane >> 3) & 1) << 3;
    uint32_t aoff = (uint32_t)(a_row * TROW + a_col) * 2;
    uint32_t boff = (uint32_t)(b_row * TROW + b_col) * 2 + 2 * TBYTES;

    for (int kc = 0; kc < nch; kc++) {
        if (kc + 1 < nch) { issue(kc + 1, (kc + 1) & 1); CPW(1); }
        else              { CPW(0); }
        __syncthreads();

        uint32_t base = sb + (uint32_t)((kc & 1) * 3 * TBYTES);
        uint32_t aoff_h = base + aoff, aoff_l = aoff_h + TBYTES;
        uint32_t boff_b = base + boff;
#pragma unroll
        for (int ks = 0; ks < 4; ks++) {
            uint32_t ah[4][4], al[4][4], bw[8];
            uint32_t kso = (uint32_t)(ks * 32);
#pragma unroll
            for (int mi = 0; mi < 4; mi++) {
                ldm4(ah[mi], aoff_h + (uint32_t)(mi * 16 * TROW * 2) + kso);
                ldm4(al[mi], aoff_l + (uint32_t)(mi * 16 * TROW * 2) + kso);
            }
            ldm4(&bw[0], boff_b + kso);
            ldm4(&bw[4], boff_b + (uint32_t)(16 * TROW * 2) + kso);
#pragma unroll
            for (int mi = 0; mi < 4; mi++)
#pragma unroll
                for (int ni = 0; ni < 4; ni++)
                    mma16816h(acc[mi][ni], ah[mi], &bw[ni * 2]);
#pragma unroll
            for (int mi = 0; mi < 4; mi++)
#pragma unroll
                for (int ni = 0; ni < 4; ni++)
                    mma16816h(acc[mi][ni], al[mi], &bw[ni * 2]);
        }
        __syncthreads();
    }

    // ---- epilogue ----
#pragma unroll
    for (int mi = 0; mi < 4; mi++) {
#pragma unroll
        for (int ni = 0; ni < 4; ni++) {
            int r0 = bm + wm * 64 + mi * 16 + (lane >> 2);
            int c0 = bn + wn * 32 + ni * 8 + ((lane & 3) << 1);
#pragma unroll
            for (int half = 0; half < 2; half++) {
                int gm = r0 + half * 8;
                float v0 = acc[mi][ni][half * 2]     + bias[c0];
                float v1 = acc[mi][ni][half * 2 + 1] + bias[c0 + 1];
                if (EPI == 1) {
                    v0 *= normcdff(v0); v1 *= normcdff(v1);
                    uint32_t hi, lo;
                    hsplit2(v0, v1, hi, lo);
                    *(uint32_t*)&Chi[(size_t)gm * N + c0] = hi;
                    *(uint32_t*)&Clo[(size_t)gm * N + c0] = lo;
                } else {
                    if (EPI == 2) {
                        v0 += R[(size_t)gm * N + c0];
                        v1 += R[(size_t)gm * N + c0 + 1];
                    }
                    float2 o; o.x = v0; o.y = v1;
                    *(float2*)&C[(size_t)gm * N + c0] = o;
                }
            }
        }
    }
}

// ---------------- RoPE trig tables (double precision; fast-math-proof) ----------------
__global__ void trig_kernel(float* __restrict__ ct, float* __restrict__ st) {
    int i = blockIdx.x * 256 + threadIdx.x;
    if (i >= TT * 32) return;
    int t = i >> 5, p = i & 31;
    double inv = exp2(-13.287712379549449 * ((double)(2 * p) * (1.0 / 64.0)));
    float invf = (float)inv;
    float angf = (float)((double)t * (double)invf);
    double c, s;
    sincos((double)angf, &s, &c);
    ct[i] = (float)c;
    st[i] = (float)s;
}

// ---------------- embedding ----------------
__global__ void embed_kernel(const int* __restrict__ act, const int* __restrict__ obs,
                             const float* __restrict__ aemb, const float* __restrict__ oemb,
                             const float* __restrict__ temb, float* __restrict__ x) {
    int idx = blockIdx.x * blockDim.x + threadIdx.x;
    if (idx >= BT * DD) return;
    int r = idx / DD, d = idx % DD;
    x[idx] = aemb[(size_t)act[r] * DD + d] + temb[d]
           + oemb[(size_t)obs[r] * DD + d] + temb[DD + d];
}

// ---------------- layernorm -> fp16 hi/lo split directly ----------------
__global__ void ln_kernel(const float* __restrict__ x, const float* __restrict__ g,
                          const float* __restrict__ b, __half* __restrict__ yh,
                          __half* __restrict__ yl) {
    int r = blockIdx.x;
    const float* xr = x + (size_t)r * DD;
    float v[4];
    float s = 0.f, ss = 0.f;
#pragma unroll
    for (int i = 0; i < 4; i++) {
        float t = xr[threadIdx.x + i * 256];
        v[i] = t; s += t; ss += t * t;
    }
#pragma unroll
    for (int o = 16; o > 0; o >>= 1) {
        s  += __shfl_xor_sync(0xffffffffu, s,  o);
        ss += __shfl_xor_sync(0xffffffffu, ss, o);
    }
    __shared__ float rs[8], rss[8];
    int w = threadIdx.x >> 5;
    if ((threadIdx.x & 31) == 0) { rs[w] = s; rss[w] = ss; }
    __syncthreads();
    if (threadIdx.x == 0) {
        float a = 0.f, c = 0.f;
#pragma unroll
        for (int i = 0; i < 8; i++) { a += rs[i]; c += rss[i]; }
        rs[0] = a; rss[0] = c;
    }
    __syncthreads();
    float mean = rs[0] * (1.f / DD);
    float var  = rss[0] * (1.f / DD) - mean * mean;
    float inv  = rsqrtf(var + 1e-5f);
#pragma unroll
    for (int i = 0; i < 4; i++) {
        int d = threadIdx.x + i * 256;
        float val = (v[i] - mean) * inv * g[d] + b[d];
        __half h = __float2half_rn(val);
        yh[(size_t)r * DD + d] = h;
        yl[(size_t)r * DD + d] = __float2half_rn(val - __half2float(h));
    }
}

// ---------------- RoPE + bf16 hi/lo split from fused QKV buffer [BT,3072] -------------
__global__ void rope_split_kernel(const float* __restrict__ QKV,
                                  const float* __restrict__ ct, const float* __restrict__ st,
                                  __nv_bfloat16* __restrict__ qh, __nv_bfloat16* __restrict__ ql,
                                  __nv_bfloat16* __restrict__ kh, __nv_bfloat16* __restrict__ kl) {
    int idx = blockIdx.x * 256 + threadIdx.x;
    if (idx >= BT * (DD / 2)) return;
    int r  = idx >> 9;
    int c2 = idx & 511;
    int hh = c2 >> 5, p = c2 & 31;
    int b = r >> 11, t = r & (TT - 1);
    float c = ct[t * 32 + p];
    float s = st[t * 32 + p];
    size_t ib = (size_t)r * (3 * DD) + hh * 64 + 2 * p;
    size_t ob = ((size_t)(b * HH + hh) * TT + t) * 64 + 2 * p;

    float q0 = QKV[ib], q1 = QKV[ib + 1];
    float o0 = q0 * c - q1 * s, o1 = q0 * s + q1 * c;
    __nv_bfloat16 h0 = __float2bfloat16_rn(o0), h1 = __float2bfloat16_rn(o1);
    qh[ob] = h0; qh[ob + 1] = h1;
    ql[ob]     = __float2bfloat16_rn(o0 - __bfloat162float(h0));
    ql[ob + 1] = __float2bfloat16_rn(o1 - __bfloat162float(h1));

    float k0 = QKV[ib + DD], k1 = QKV[ib + DD + 1];
    float e0 = k0 * c - k1 * s, e1 = k0 * s + k1 * c;
    __nv_bfloat16 g0 = __float2bfloat16_rn(e0), g1 = __float2bfloat16_rn(e1);
    kh[ob] = g0; kh[ob + 1] = g1;
    kl[ob]     = __float2bfloat16_rn(e0 - __bfloat162float(g0));
    kl[ob + 1] = __float2bfloat16_rn(e1 - __bfloat162float(g1));
}

// ---------------- V split + transpose into [bh][d][t] (from fused QKV) ----------------
__global__ void vsplit_kernel(const float* __restrict__ QKV,
                              __nv_bfloat16* __restrict__ vh, __nv_bfloat16* __restrict__ vl) {
    __shared__ float ts[32][33];
    int t0 = blockIdx.x * 32, d0 = blockIdx.y * 32, b = blockIdx.z;
    int tx = threadIdx.x & 31, ty = threadIdx.x >> 5;
#pragma unroll
    for (int i = ty; i < 32; i += 8)
        ts[i][tx] = QKV[((size_t)b * TT + t0 + i) * (3 * DD) + 2 * DD + d0 + tx];
    __syncthreads();
    int hh = d0 >> 6, dl0 = d0 & 63;
#pragma unroll
    for (int i = ty; i < 32; i += 8) {
        float v = ts[tx][i];
        size_t o = ((size_t)(b * HH + hh) * 64 + dl0 + i) * TT + t0 + tx;
        __nv_bfloat16 h = __float2bfloat16_rn(v);
        vh[o] = h;
        vl[o] = __float2bfloat16_rn(v - __bfloat162float(h));
    }
}

// ================= fused flash attention (bf16 3-pass internally; fp16 output) ========
#define FQ_H 0
#define FQ_L 18432
#define FK_H(st) (36864 + (st)*36864)
#define FK_L(st) (FK_H(st) + 18432)
#define FV_H(st) (110592 + (st)*34816)
#define FV_L(st) (FV_H(st) + 17408)
#define FSMEM 180224

__global__ __launch_bounds__(256)
void flash_attn(const __nv_bfloat16* __restrict__ Qh, const __nv_bfloat16* __restrict__ Ql,
                const __nv_bfloat16* __restrict__ Kh, const __nv_bfloat16* __restrict__ Kl,
                const __nv_bfloat16* __restrict__ Vh, const __nv_bfloat16* __restrict__ Vl,
                __half* __restrict__ Oh, __half* __restrict__ Ol) {
    int qt = gridDim.x - 1 - blockIdx.x;
    int bh = blockIdx.y;
    int b = bh >> 4, hh = bh & 15;
    extern __shared__ __align__(16) char smem[];
    const uint32_t sb = smem_u32(smem);
    int tid = threadIdx.x, lane = tid & 31, w = tid >> 5;

    {
        int row = tid >> 1, segb = (tid & 1) * 4;
        size_t qg = ((size_t)bh * TT + qt * 128 + row) * 64 + segb * 8;
#pragma unroll
        for (int s = 0; s < 4; s++) {
            uint32_t so = (uint32_t)(row * 144 + (segb + s) * 16);
            *(uint4*)(smem + FQ_H + so) = *(const uint4*)(Qh + qg + s * 8);
            *(uint4*)(smem + FQ_L + so) = *(const uint4*)(Ql + qg + s * 8);
        }
    }

    auto issueKV = [&](int kt, int st) {
        int row = tid >> 1, segb = (tid & 1) * 4;
        size_t kg = ((size_t)bh * TT + kt * 128 + row) * 64 + segb * 8;
#pragma unroll
        for (int s = 0; s < 4; s++) {
            uint32_t so = (uint32_t)(row * 144 + (segb + s) * 16);
            CPA(sb + FK_H(st) + so, Kh + kg + s * 8);
            CPA(sb + FK_L(st) + so, Kl + kg + s * 8);
        }
        int vrow = tid >> 2, vsegb = (tid & 3) * 4;
        size_t vg = ((size_t)bh * 64 + vrow) * TT + kt * 128 + vsegb * 8;
#pragma unroll
        for (int s = 0; s < 4; s++) {
            uint32_t so = (uint32_t)(vrow * 272 + (vsegb + s) * 16);
            CPA(sb + FV_H(st) + so, Vh + vg + s * 8);
            CPA(sb + FV_L(st) + so, Vl + vg + s * 8);
        }
        CPC();
    };
    issueKV(0, 0);
    __syncthreads();

    uint32_t qfh[4][4], qfl[4][4];
    {
        int a_row = w * 16 + (lane & 15), a_col = (lane >> 4) << 3;
        uint32_t qa = (uint32_t)(a_row * 144 + a_col * 2);
#pragma unroll
        for (int ks = 0; ks < 4; ks++) {
            ldm4(qfh[ks], sb + FQ_H + qa + ks * 32);
            ldm4(qfl[ks], sb + FQ_L + qa + ks * 32);
        }
    }

    float m0 = -3.0e38f, m1 = -3.0e38f, l0 = 0.f, l1 = 0.f;
    float O[8][4];
#pragma unroll
    for (int i = 0; i < 8; i++)
#pragma unroll
        for (int z = 0; z < 4; z++) O[i][z] = 0.f;

    int b_rowi = ((lane >> 4) << 3) + (lane & 7);
    int b_colb = (((lane >> 3) & 1) << 3) * 2;

    for (int kt = 0; kt <= qt; kt++) {
        if (kt < qt) { issueKV(kt + 1, (kt + 1) & 1); CPW(1); }
        else         { CPW(0); }
        __syncthreads();
        uint32_t kb_h = sb + FK_H(kt & 1), kb_l = sb + FK_L(kt & 1);
        uint32_t vb_h = sb + FV_H(kt & 1), vb_l = sb + FV_L(kt & 1);

        float P[16][4];
#pragma unroll
        for (int i = 0; i < 16; i++)
#pragma unroll
            for (int z = 0; z < 4; z++) P[i][z] = 0.f;
#pragma unroll
        for (int ks = 0; ks < 4; ks++) {
            uint32_t kso = (uint32_t)(ks * 32);
#pragma unroll
            for (int nb = 0; nb < 8; nb++) {
                uint32_t addr = (uint32_t)((nb * 16 + b_rowi) * 144) + b_colb + kso;
                uint32_t kf[4], kfl[4];
                ldm4(kf, kb_h + addr);
                mma16816(P[2*nb],   qfh[ks], &kf[0]);
                mma16816(P[2*nb+1], qfh[ks], &kf[2]);
                mma16816(P[2*nb],   qfl[ks], &kf[0]);
                mma16816(P[2*nb+1], qfl[ks], &kf[2]);
                ldm4(kfl, kb_l + addr);
                mma16816(P[2*nb],   qfh[ks], &kfl[0]);
                mma16816(P[2*nb+1], qfh[ks], &kfl[2]);
            }
        }
#pragma unroll
        for (int i = 0; i < 16; i++)
#pragma unroll
            for (int z = 0; z < 4; z++) P[i][z] *= 0.125f;
        if (kt == qt) {
            int r0 = w * 16 + (lane >> 2);
#pragma unroll
            for (int i = 0; i < 16; i++) {
#pragma unroll
                for (int z = 0; z < 4; z++) {
                    int col = i * 8 + ((lane & 3) << 1) + (z & 1);
                    int row = r0 + ((z >> 1) << 3);
                    if (col > row) P[i][z] = -3.0e38f;
                }
            }
        }
        float mx0 = -3.0e38f, mx1 = -3.0e38f;
#pragma unroll
        for (int i = 0; i < 16; i++) {
            mx0 = fmaxf(mx0, fmaxf(P[i][0], P[i][1]));
            mx1 = fmaxf(mx1, fmaxf(P[i][2], P[i][3]));
        }
        mx0 = fmaxf(mx0, __shfl_xor_sync(0xffffffffu, mx0, 1));
        mx0 = fmaxf(mx0, __shfl_xor_sync(0xffffffffu, mx0, 2));
        mx1 = fmaxf(mx1, __shfl_xor_sync(0xffffffffu, mx1, 1));
        mx1 = fmaxf(mx1, __shfl_xor_sync(0xffffffffu, mx1, 2));
        float mn0 = fmaxf(m0, mx0), mn1 = fmaxf(m1, mx1);
        float al0 = expf(m0 - mn0), al1 = expf(m1 - mn1);
        m0 = mn0; m1 = mn1;
        float s0 = 0.f, s1 = 0.f;
#pragma unroll
        for (int i = 0; i < 16; i++) {
            P[i][0] = expf(P[i][0] - m0); s0 += P[i][0];
            P[i][1] = expf(P[i][1] - m0); s0 += P[i][1];
            P[i][2] = expf(P[i][2] - m1); s1 += P[i][2];
            P[i][3] = expf(P[i][3] - m1); s1 += P[i][3];
        }
        s0 += __shfl_xor_sync(0xffffffffu, s0, 1);
        s0 += __shfl_xor_sync(0xffffffffu, s0, 2);
        s1 += __shfl_xor_sync(0xffffffffu, s1, 1);
        s1 += __shfl_xor_sync(0xffffffffu, s1, 2);
        l0 = l0 * al0 + s0;
        l1 = l1 * al1 + s1;
#pragma unroll
        for (int i = 0; i < 8; i++) {
            O[i][0] *= al0; O[i][1] *= al0;
            O[i][2] *= al1; O[i][3] *= al1;
        }
#pragma unroll
        for (int ks = 0; ks < 8; ks++) {
            uint32_t pah[4], pal[4];
            bfsplit2(P[2*ks][0],   P[2*ks][1],   pah[0], pal[0]);
            bfsplit2(P[2*ks][2],   P[2*ks][3],   pah[1], pal[1]);
            bfsplit2(P[2*ks+1][0], P[2*ks+1][1], pah[2], pal[2]);
            bfsplit2(P[2*ks+1][2], P[2*ks+1][3], pah[3], pal[3]);
            uint32_t kso = (uint32_t)(ks * 32);
#pragma unroll
            for (int nb = 0; nb < 4; nb++) {
                uint32_t addr = (uint32_t)((nb * 16 + b_rowi) * 272) + b_colb + kso;
                uint32_t vf[4], vfl[4];
                ldm4(vf, vb_h + addr);
                mma16816(O[2*nb],   pah, &vf[0]);
                mma16816(O[2*nb+1], pah, &vf[2]);
                mma16816(O[2*nb],   pal, &vf[0]);
                mma16816(O[2*nb+1], pal, &vf[2]);
                ldm4(vfl, vb_l + addr);
                mma16816(O[2*nb],   pah, &vfl[0]);
                mma16816(O[2*nb+1], pah, &vfl[2]);
            }
        }
        __syncthreads();
    }

    float i0 = 1.f / l0, i1 = 1.f / l1;
    int r0 = qt * 128 + w * 16 + (lane >> 2);
    int c0 = hh * 64 + ((lane & 3) << 1);
#pragma unroll
    for (int nj = 0; nj < 8; nj++) {
        int cc = c0 + nj * 8;
        uint32_t hi, lo;
        hsplit2(O[nj][0] * i0, O[nj][1] * i0, hi, lo);
        size_t o0 = ((size_t)b * TT + r0) * DD + cc;
        *(uint32_t*)&Oh[o0] = hi;
        *(uint32_t*)&Ol[o0] = lo;
        hsplit2(O[nj][2] * i1, O[nj][3] * i1, hi, lo);
        size_t o1 = ((size_t)b * TT + r0 + 8) * DD + cc;
        *(uint32_t*)&Oh[o1] = hi;
        *(uint32_t*)&Ol[o1] = lo;
    }
}

// ---------------- host-side helpers ----------------
static void conv_B(const float* W, __half* bw, int K, int N) {
    convT_kernel<<<dim3(N / 32, K / 64), 256>>>(W, bw, K, N);
}
template <int EPI>
static void gemm(const __half* ah, const __half* al, const __half* bw,
                 const float* bias, const float* R, float* C,
                 __half* Chi, __half* Clo, int M, int N, int K) {
    static bool cfg = false;
    if (!cfg) {
        cudaFuncSetAttribute(gemm_mma<EPI>, cudaFuncAttributeMaxDynamicSharedMemorySize, GSMEM);
        cfg = true;
    }
    gemm_mma<EPI><<<dim3(N / 128, M / 128), 256, GSMEM>>>(ah, al, bw, bias, R, C, Chi, Clo, M, N, K);
}

// ---------------- launch sequence ----------------
extern "C" void kernel_launch(void* const* d_in, const int* in_sizes, int n_in,
                              void* d_out, int out_size) {
    const int*   actions = (const int*)d_in[0];
    const int*   observ  = (const int*)d_in[1];
    const float* aemb    = (const float*)d_in[2];
    const float* oemb    = (const float*)d_in[3];
    const float* temb    = (const float*)d_in[4];
    const float* Wq      = (const float*)d_in[5];
    const float* bq      = (const float*)d_in[6];
    const float* Wk      = (const float*)d_in[7];
    const float* bk      = (const float*)d_in[8];
    const float* Wv      = (const float*)d_in[9];
    const float* bv      = (const float*)d_in[10];
    const float* Wo      = (const float*)d_in[11];
    const float* bo      = (const float*)d_in[12];
    const float* ln1_g   = (const float*)d_in[13];
    const float* ln1_b   = (const float*)d_in[14];
    const float* ln2_g   = (const float*)d_in[15];
    const float* ln2_b   = (const float*)d_in[16];
    const float* W1      = (const float*)d_in[17];
    const float* b1      = (const float*)d_in[18];
    const float* W2      = (const float*)d_in[19];
    const float* b2      = (const float*)d_in[20];
    const float* out_g   = (const float*)d_in[21];
    const float* out_b   = (const float*)d_in[22];
    const float* Wout    = (const float*)d_in[23];
    const float* bout    = (const float*)d_in[24];

    float *x, *qkv, *b3, *ct, *st;
    __half *ah, *al, *fh, *fl, *bw;
    __nv_bfloat16 *qh, *ql, *kh, *kl, *vh, *vl;
    cudaGetSymbolAddress((void**)&x,   g_x);
    cudaGetSymbolAddress((void**)&qkv, g_qkv);
    cudaGetSymbolAddress((void**)&b3,  g_b3);
    cudaGetSymbolAddress((void**)&ct,  g_cos);
    cudaGetSymbolAddress((void**)&st,  g_sin);
    cudaGetSymbolAddress((void**)&ah,  g_ah);
    cudaGetSymbolAddress((void**)&al,  g_al);
    cudaGetSymbolAddress((void**)&fh,  g_fh);
    cudaGetSymbolAddress((void**)&fl,  g_fl);
    cudaGetSymbolAddress((void**)&bw,  g_bw);
    cudaGetSymbolAddress((void**)&qh,  g_qh);
    cudaGetSymbolAddress((void**)&ql,  g_ql);
    cudaGetSymbolAddress((void**)&kh,  g_kh);
    cudaGetSymbolAddress((void**)&kl,  g_kl);
    cudaGetSymbolAddress((void**)&vh,  g_vh);
    cudaGetSymbolAddress((void**)&vl,  g_vl);

    static bool fcfg = false;
    if (!fcfg) {
        cudaFuncSetAttribute(flash_attn, cudaFuncAttributeMaxDynamicSharedMemorySize, FSMEM);
        fcfg = true;
    }

    trig_kernel<<<(TT * 32 + 255) / 256, 256>>>(ct, st);
    embed_kernel<<<(BT * DD + 255) / 256, 256>>>(actions, observ, aemb, oemb, temb, x);

    for (int i = 0; i < LL; i++) {
        ln_kernel<<<BT, 256>>>(x, ln1_g + (size_t)i * DD, ln1_b + (size_t)i * DD, ah, al);

        // fused QKV: Bt rows [0,1024)=Wq^T, [1024,2048)=Wk^T, [2048,3072)=Wv^T
        conv_B(Wq + (size_t)i * DD * DD, bw,                       DD, DD);
        conv_B(Wk + (size_t)i * DD * DD, bw + (size_t)DD * DD,     DD, DD);
        conv_B(Wv + (size_t)i * DD * DD, bw + (size_t)2 * DD * DD, DD, DD);
        cudaMemcpyAsync(b3,            bq + (size_t)i * DD, DD * 4, cudaMemcpyDeviceToDevice);
        cudaMemcpyAsync(b3 + DD,       bk + (size_t)i * DD, DD * 4, cudaMemcpyDeviceToDevice);
        cudaMemcpyAsync(b3 + 2 * DD,   bv + (size_t)i * DD, DD * 4, cudaMemcpyDeviceToDevice);
        gemm<0>(ah, al, bw, b3, nullptr, qkv, nullptr, nullptr, BT, 3 * DD, DD);

        rope_split_kernel<<<(BT * (DD / 2) + 255) / 256, 256>>>(qkv, ct, st, qh, ql, kh, kl);
        vsplit_kernel<<<dim3(TT / 32, DD / 32, BB), 256>>>(qkv, vh, vl);

        flash_attn<<<dim3(TT / 128, BB * HH), 256, FSMEM>>>(qh, ql, kh, kl, vh, vl, ah, al);

        conv_B(Wo + (size_t)i * DD * DD, bw, DD, DD);
        gemm<2>(ah, al, bw, bo + (size_t)i * DD, x, x, nullptr, nullptr, BT, DD, DD);

        ln_kernel<<<BT, 256>>>(x, ln2_g + (size_t)i * DD, ln2_b + (size_t)i * DD, ah, al);
        conv_B(W1 + (size_t)i * DD * DFF, bw, DD, DFF);
        gemm<1>(ah, al, bw, b1 + (size_t)i * DFF, nullptr, nullptr, fh, fl, BT, DFF, DD);

        conv_B(W2 + (size_t)i * DFF * DD, bw, DFF, DD);
        gemm<2>(fh, fl, bw, b2 + (size_t)i * DD, x, x, nullptr, nullptr, BT, DD, DFF);
    }

    ln_kernel<<<BT, 256>>>(x, out_g, out_b, ah, al);
    conv_B(Wout, bw, DD, OV);
    gemm<0>(ah, al, bw, bout, nullptr, (float*)d_out, nullptr, nullptr, BT, OV, DD);
}

// round 15
// speedup vs baseline: 1.7124x; 1.1503x over previous
#include <cuda_runtime.h>
#include <cuda_bf16.h>
#include <cuda_fp16.h>
#include <math.h>
#include <stdint.h>

#define LL 2
#define DD 1024
#define HH 16
#define DHH 64
#define DFF 4096
#define BB 2
#define TT 2048
#define OV 4096
#define BT (BB*TT)   // 4096

// ---------------- scratch (device globals; no runtime allocation) ----------------
__device__ float g_x  [BT*DD];
__device__ float g_qkv[(size_t)BT*DD];     // V part only (fp32), written by QKV epilogue
__device__ float g_b3 [3*DD];
__device__ float g_cos[TT*32];
__device__ float g_sin[TT*32];
// fp16 GEMM operands (16B-aligned)
__device__ __align__(16) __half g_ah[(size_t)BT*DD];    // activation hi [BT,DD]
__device__ __align__(16) __half g_al[(size_t)BT*DD];
__device__ __align__(16) __half g_fh[(size_t)BT*DFF];   // gelu(ff) fp16 [BT,DFF]
__device__ __align__(16) __half g_bw[(size_t)DFF*DD];   // B^T fp16 [N,K] (max 4096x1024)
// attention split operands (bf16)
__device__ __align__(16) __nv_bfloat16 g_qh[(size_t)BB*HH*TT*DHH];  // [bh][t][d]
__device__ __align__(16) __nv_bfloat16 g_ql[(size_t)BB*HH*TT*DHH];
__device__ __align__(16) __nv_bfloat16 g_kh[(size_t)BB*HH*TT*DHH];
__device__ __align__(16) __nv_bfloat16 g_kl[(size_t)BB*HH*TT*DHH];
__device__ __align__(16) __nv_bfloat16 g_vh[(size_t)BB*HH*DHH*TT];  // [bh][d][t]
__device__ __align__(16) __nv_bfloat16 g_vl[(size_t)BB*HH*DHH*TT];

// ---------------- warp-MMA primitives (baseline PTX; no sm_103a features) ----------
__device__ __forceinline__ uint32_t smem_u32(const void* p) {
    uint32_t a;
    asm("{ .reg .u64 t; cvta.to.shared.u64 t, %1; cvt.u32.u64 %0, t; }" : "=r"(a) : "l"(p));
    return a;
}
__device__ __forceinline__ void ldm4(uint32_t* r, uint32_t addr) {
    asm volatile("ldmatrix.sync.aligned.m8n8.x4.shared.b16 {%0,%1,%2,%3}, [%4];"
                 : "=r"(r[0]), "=r"(r[1]), "=r"(r[2]), "=r"(r[3]) : "r"(addr));
}
// bf16 mma (flash attention)
__device__ __forceinline__ void mma16816(float* d, const uint32_t* a, const uint32_t* b) {
    asm volatile("mma.sync.aligned.m16n8k16.row.col.f32.bf16.bf16.f32 "
                 "{%0,%1,%2,%3}, {%4,%5,%6,%7}, {%8,%9}, {%0,%1,%2,%3};"
                 : "+f"(d[0]), "+f"(d[1]), "+f"(d[2]), "+f"(d[3])
                 : "r"(a[0]), "r"(a[1]), "r"(a[2]), "r"(a[3]), "r"(b[0]), "r"(b[1]));
}
// fp16 mma (GEMMs)
__device__ __forceinline__ void mma16816h(float* d, const uint32_t* a, const uint32_t* b) {
    asm volatile("mma.sync.aligned.m16n8k16.row.col.f32.f16.f16.f32 "
                 "{%0,%1,%2,%3}, {%4,%5,%6,%7}, {%8,%9}, {%0,%1,%2,%3};"
                 : "+f"(d[0]), "+f"(d[1]), "+f"(d[2]), "+f"(d[3])
                 : "r"(a[0]), "r"(a[1]), "r"(a[2]), "r"(a[3]), "r"(b[0]), "r"(b[1]));
}
#define CPA(dst, src) asm volatile("cp.async.cg.shared.global [%0], [%1], 16;" :: "r"(dst), "l"(src))
#define CPC()         asm volatile("cp.async.commit_group;")
#define CPW(n)        asm volatile("cp.async.wait_group %0;" :: "n"(n))

__device__ __forceinline__ uint32_t bfpack(float x, float y) {
    __nv_bfloat162 t;
    t.x = __float2bfloat16_rn(x);
    t.y = __float2bfloat16_rn(y);
    return *(uint32_t*)&t;
}
__device__ __forceinline__ void bfsplit2(float x, float y, uint32_t& hi, uint32_t& lo) {
    __nv_bfloat16 hx = __float2bfloat16_rn(x), hy = __float2bfloat16_rn(y);
    __nv_bfloat162 H; H.x = hx; H.y = hy;
    hi = *(uint32_t*)&H;
    lo = bfpack(x - __bfloat162float(hx), y - __bfloat162float(hy));
}
// fp16 hi/lo split of a float pair
__device__ __forceinline__ void hsplit2(float x, float y, uint32_t& hi, uint32_t& lo) {
    __half hx = __float2half_rn(x), hy = __float2half_rn(y);
    __half2 H; H.x = hx; H.y = hy;
    hi = *(uint32_t*)&H;
    __half2 L;
    L.x = __float2half_rn(x - __half2float(hx));
    L.y = __float2half_rn(y - __half2float(hy));
    lo = *(uint32_t*)&L;
}

// ---------------- transpose + fp16 round: W[K,N] -> Bt[N,K] ----------------
__global__ void convT_kernel(const float* __restrict__ W, __half* __restrict__ ht,
                             int K, int N) {
    __shared__ float t[64][33];
    int n0 = blockIdx.x * 32, k0 = blockIdx.y * 64;
    int tx = threadIdx.x & 31, ty = threadIdx.x >> 5;
#pragma unroll
    for (int ky = 0; ky < 64; ky += 8)
        t[ky + ty][tx] = W[(size_t)(k0 + ky + ty) * N + n0 + tx];
    __syncthreads();
    int kl = threadIdx.x & 63, nb = threadIdx.x >> 6;
#pragma unroll
    for (int n = nb; n < 32; n += 4) {
        float v = t[kl][n];
        ht[(size_t)(n0 + n) * K + k0 + kl] = __float2half_rn(v);
    }
}

// ---------------- fp16 GEMM: 2-stage cp.async, 2 CTAs/SM, 1 or 2 A-passes ------------
// EPI: 0 = bias -> fp32 C
//      1 = bias + GELU -> fp16 Chi only
//      2 = bias + residual -> fp32 C
//      3 = QKV epilogue: Q/K rope+bf16 split, V fp32
#define TROW 72
#define TBYTES (128*TROW*2)      // 18432 per tile
#define GSMEM (2*3*TBYTES)       // 110592 (2 stages x 3 tiles) -> 2 CTAs/SM

template <int EPI, int PASSES>
__global__ __launch_bounds__(256, 2)
void gemm_mma(const __half* __restrict__ Ahi, const __half* __restrict__ Alo,
              const __half* __restrict__ Bw,
              const float* __restrict__ bias, const float* __restrict__ R,
              float* __restrict__ C, __half* __restrict__ Chi,
              __half* __restrict__ Clo,
              const float* __restrict__ CT, const float* __restrict__ ST,
              __nv_bfloat16* __restrict__ Kh, __nv_bfloat16* __restrict__ Kl,
              float* __restrict__ Vb, int M, int N, int K) {
    extern __shared__ __align__(16) char smem[];
    const uint32_t sb = smem_u32(smem);
    int tid = threadIdx.x, lane = tid & 31, w = tid >> 5;
    int wm = w >> 2, wn = w & 3;
    int bm = blockIdx.y << 7, bn = blockIdx.x << 7;

    float acc[4][4][4];
#pragma unroll
    for (int i = 0; i < 4; i++)
#pragma unroll
        for (int j = 0; j < 4; j++)
#pragma unroll
            for (int z = 0; z < 4; z++) acc[i][j][z] = 0.f;

    int lrow = tid >> 3, lseg = tid & 7;
    auto issue = [&](int kc, int st) {
        int kb = kc << 6;
        uint32_t base = sb + st * 3 * TBYTES;
#pragma unroll
        for (int i = 0; i < 4; i++) {
            int row = lrow + i * 32;
            uint32_t so = base + (uint32_t)(row * 144 + lseg * 16);
            size_t ga = (size_t)(bm + row) * K + kb + lseg * 8;
            size_t gb = (size_t)(bn + row) * K + kb + lseg * 8;
            CPA(so, Ahi + ga);
            if (PASSES == 2) CPA(so + TBYTES, Alo + ga);
            CPA(so + 2*TBYTES, Bw + gb);
        }
        CPC();
    };

    const int nch = K >> 6;
    issue(0, 0);

    int a_row = wm * 64 + (lane & 15), a_col = (lane >> 4) << 3;
    int b_row = wn * 32 + ((lane >> 4) << 3) + (lane & 7), b_col = ((lane >> 3) & 1) << 3;
    uint32_t aoff = (uint32_t)(a_row * TROW + a_col) * 2;
    uint32_t boff = (uint32_t)(b_row * TROW + b_col) * 2 + 2 * TBYTES;

    for (int kc = 0; kc < nch; kc++) {
        if (kc + 1 < nch) { issue(kc + 1, (kc + 1) & 1); CPW(1); }
        else              { CPW(0); }
        __syncthreads();

        uint32_t base = sb + (uint32_t)((kc & 1) * 3 * TBYTES);
        uint32_t aoff_h = base + aoff, aoff_l = aoff_h + TBYTES;
        uint32_t boff_b = base + boff;
#pragma unroll
        for (int ks = 0; ks < 4; ks++) {
            uint32_t ah[4][4], bw[8];
            uint32_t kso = (uint32_t)(ks * 32);
#pragma unroll
            for (int mi = 0; mi < 4; mi++)
                ldm4(ah[mi], aoff_h + (uint32_t)(mi * 16 * TROW * 2) + kso);
            ldm4(&bw[0], boff_b + kso);
            ldm4(&bw[4], boff_b + (uint32_t)(16 * TROW * 2) + kso);
#pragma unroll
            for (int mi = 0; mi < 4; mi++)
#pragma unroll
                for (int ni = 0; ni < 4; ni++)
                    mma16816h(acc[mi][ni], ah[mi], &bw[ni * 2]);
            if (PASSES == 2) {
                uint32_t al[4][4];
#pragma unroll
                for (int mi = 0; mi < 4; mi++)
                    ldm4(al[mi], aoff_l + (uint32_t)(mi * 16 * TROW * 2) + kso);
#pragma unroll
                for (int mi = 0; mi < 4; mi++)
#pragma unroll
                    for (int ni = 0; ni < 4; ni++)
                        mma16816h(acc[mi][ni], al[mi], &bw[ni * 2]);
            }
        }
        __syncthreads();
    }

    // ---- epilogue ----
#pragma unroll
    for (int mi = 0; mi < 4; mi++) {
#pragma unroll
        for (int ni = 0; ni < 4; ni++) {
            int r0 = bm + wm * 64 + mi * 16 + (lane >> 2);
            int c0 = bn + wn * 32 + ni * 8 + ((lane & 3) << 1);
#pragma unroll
            for (int half = 0; half < 2; half++) {
                int gm = r0 + half * 8;
                float v0 = acc[mi][ni][half * 2]     + bias[c0];
                float v1 = acc[mi][ni][half * 2 + 1] + bias[c0 + 1];
                if (EPI == 1) {
                    v0 *= normcdff(v0); v1 *= normcdff(v1);
                    __half2 H;
                    H.x = __float2half_rn(v0); H.y = __float2half_rn(v1);
                    *(uint32_t*)&Chi[(size_t)gm * N + c0] = *(uint32_t*)&H;
                } else if (EPI == 3) {
                    int region = c0 >> 10;
                    if (region < 2) {
                        int d = c0 & 63, hhh = (c0 & 1023) >> 6, p = d >> 1;
                        int t = gm & (TT - 1), bb = gm >> 11;
                        float cc = CT[t * 32 + p], ss = ST[t * 32 + p];
                        float o0 = v0 * cc - v1 * ss;
                        float o1 = v0 * ss + v1 * cc;
                        uint32_t hi, lo;
                        bfsplit2(o0, o1, hi, lo);
                        size_t ob = (((size_t)(bb * HH + hhh) * TT) + t) * 64 + d;
                        if (region == 0) {
                            *(uint32_t*)&Chi[ob] = hi;   // qh (bf16 bits)
                            *(uint32_t*)&Clo[ob] = lo;   // ql
                        } else {
                            *(uint32_t*)&Kh[ob] = hi;
                            *(uint32_t*)&Kl[ob] = lo;
                        }
                    } else {
                        float2 o; o.x = v0; o.y = v1;
                        *(float2*)&Vb[(size_t)gm * DD + (c0 & 1023)] = o;
                    }
                } else {
                    if (EPI == 2) {
                        v0 += R[(size_t)gm * N + c0];
                        v1 += R[(size_t)gm * N + c0 + 1];
                    }
                    float2 o; o.x = v0; o.y = v1;
                    *(float2*)&C[(size_t)gm * N + c0] = o;
                }
            }
        }
    }
}

// ---------------- RoPE trig tables (double precision; fast-math-proof) ----------------
__global__ void trig_kernel(float* __restrict__ ct, float* __restrict__ st) {
    int i = blockIdx.x * 256 + threadIdx.x;
    if (i >= TT * 32) return;
    int t = i >> 5, p = i & 31;
    double inv = exp2(-13.287712379549449 * ((double)(2 * p) * (1.0 / 64.0)));
    float invf = (float)inv;
    float angf = (float)((double)t * (double)invf);
    double c, s;
    sincos((double)angf, &s, &c);
    ct[i] = (float)c;
    st[i] = (float)s;
}

// ---------------- embedding ----------------
__global__ void embed_kernel(const int* __restrict__ act, const int* __restrict__ obs,
                             const float* __restrict__ aemb, const float* __restrict__ oemb,
                             const float* __restrict__ temb, float* __restrict__ x) {
    int idx = blockIdx.x * blockDim.x + threadIdx.x;
    if (idx >= BT * DD) return;
    int r = idx / DD, d = idx % DD;
    x[idx] = aemb[(size_t)act[r] * DD + d] + temb[d]
           + oemb[(size_t)obs[r] * DD + d] + temb[DD + d];
}

// ---------------- layernorm -> fp16 hi/lo split directly ----------------
__global__ void ln_kernel(const float* __restrict__ x, const float* __restrict__ g,
                          const float* __restrict__ b, __half* __restrict__ yh,
                          __half* __restrict__ yl) {
    int r = blockIdx.x;
    const float* xr = x + (size_t)r * DD;
    float v[4];
    float s = 0.f, ss = 0.f;
#pragma unroll
    for (int i = 0; i < 4; i++) {
        float t = xr[threadIdx.x + i * 256];
        v[i] = t; s += t; ss += t * t;
    }
#pragma unroll
    for (int o = 16; o > 0; o >>= 1) {
        s  += __shfl_xor_sync(0xffffffffu, s,  o);
        ss += __shfl_xor_sync(0xffffffffu, ss, o);
    }
    __shared__ float rs[8], rss[8];
    int w = threadIdx.x >> 5;
    if ((threadIdx.x & 31) == 0) { rs[w] = s; rss[w] = ss; }
    __syncthreads();
    if (threadIdx.x == 0) {
        float a = 0.f, c = 0.f;
#pragma unroll
        for (int i = 0; i < 8; i++) { a += rs[i]; c += rss[i]; }
        rs[0] = a; rss[0] = c;
    }
    __syncthreads();
    float mean = rs[0] * (1.f / DD);
    float var  = rss[0] * (1.f / DD) - mean * mean;
    float inv  = rsqrtf(var + 1e-5f);
#pragma unroll
    for (int i = 0; i < 4; i++) {
        int d = threadIdx.x + i * 256;
        float val = (v[i] - mean) * inv * g[d] + b[d];
        __half h = __float2half_rn(val);
        yh[(size_t)r * DD + d] = h;
        yl[(size_t)r * DD + d] = __float2half_rn(val - __half2float(h));
    }
}

// ---------------- V split + transpose into [bh][d][t] (from fp32 V buffer) -----------
__global__ void vsplit_kernel(const float* __restrict__ V,
                              __nv_bfloat16* __restrict__ vh, __nv_bfloat16* __restrict__ vl) {
    __shared__ float ts[32][33];
    int t0 = blockIdx.x * 32, d0 = blockIdx.y * 32, b = blockIdx.z;
    int tx = threadIdx.x & 31, ty = threadIdx.x >> 5;
#pragma unroll
    for (int i = ty; i < 32; i += 8)
        ts[i][tx] = V[((size_t)b * TT + t0 + i) * DD + d0 + tx];
    __syncthreads();
    int hh = d0 >> 6, dl0 = d0 & 63;
#pragma unroll
    for (int i = ty; i < 32; i += 8) {
        float v = ts[tx][i];
        size_t o = ((size_t)(b * HH + hh) * 64 + dl0 + i) * TT + t0 + tx;
        __nv_bfloat16 h = __float2bfloat16_rn(v);
        vh[o] = h;
        vl[o] = __float2bfloat16_rn(v - __bfloat162float(h));
    }
}

// ================= fused flash attention (bf16 3-pass internally; fp16 output) ========
#define FQ_H 0
#define FQ_L 18432
#define FK_H(st) (36864 + (st)*36864)
#define FK_L(st) (FK_H(st) + 18432)
#define FV_H(st) (110592 + (st)*34816)
#define FV_L(st) (FV_H(st) + 17408)
#define FSMEM 180224

__global__ __launch_bounds__(256)
void flash_attn(const __nv_bfloat16* __restrict__ Qh, const __nv_bfloat16* __restrict__ Ql,
                const __nv_bfloat16* __restrict__ Kh, const __nv_bfloat16* __restrict__ Kl,
                const __nv_bfloat16* __restrict__ Vh, const __nv_bfloat16* __restrict__ Vl,
                __half* __restrict__ Oh, __half* __restrict__ Ol) {
    int qt = gridDim.x - 1 - blockIdx.x;
    int bh = blockIdx.y;
    int b = bh >> 4, hh = bh & 15;
    extern __shared__ __align__(16) char smem[];
    const uint32_t sb = smem_u32(smem);
    int tid = threadIdx.x, lane = tid & 31, w = tid >> 5;

    {
        int row = tid >> 1, segb = (tid & 1) * 4;
        size_t qg = ((size_t)bh * TT + qt * 128 + row) * 64 + segb * 8;
#pragma unroll
        for (int s = 0; s < 4; s++) {
            uint32_t so = (uint32_t)(row * 144 + (segb + s) * 16);
            *(uint4*)(smem + FQ_H + so) = *(const uint4*)(Qh + qg + s * 8);
            *(uint4*)(smem + FQ_L + so) = *(const uint4*)(Ql + qg + s * 8);
        }
    }

    auto issueKV = [&](int kt, int st) {
        int row = tid >> 1, segb = (tid & 1) * 4;
        size_t kg = ((size_t)bh * TT + kt * 128 + row) * 64 + segb * 8;
#pragma unroll
        for (int s = 0; s < 4; s++) {
            uint32_t so = (uint32_t)(row * 144 + (segb + s) * 16);
            CPA(sb + FK_H(st) + so, Kh + kg + s * 8);
            CPA(sb + FK_L(st) + so, Kl + kg + s * 8);
        }
        int vrow = tid >> 2, vsegb = (tid & 3) * 4;
        size_t vg = ((size_t)bh * 64 + vrow) * TT + kt * 128 + vsegb * 8;
#pragma unroll
        for (int s = 0; s < 4; s++) {
            uint32_t so = (uint32_t)(vrow * 272 + (vsegb + s) * 16);
            CPA(sb + FV_H(st) + so, Vh + vg + s * 8);
            CPA(sb + FV_L(st) + so, Vl + vg + s * 8);
        }
        CPC();
    };
    issueKV(0, 0);
    __syncthreads();

    uint32_t qfh[4][4], qfl[4][4];
    {
        int a_row = w * 16 + (lane & 15), a_col = (lane >> 4) << 3;
        uint32_t qa = (uint32_t)(a_row * 144 + a_col * 2);
#pragma unroll
        for (int ks = 0; ks < 4; ks++) {
            ldm4(qfh[ks], sb + FQ_H + qa + ks * 32);
            ldm4(qfl[ks], sb + FQ_L + qa + ks * 32);
        }
    }

    float m0 = -3.0e38f, m1 = -3.0e38f, l0 = 0.f, l1 = 0.f;
    float O[8][4];
#pragma unroll
    for (int i = 0; i < 8; i++)
#pragma unroll
        for (int z = 0; z < 4; z++) O[i][z] = 0.f;

    int b_rowi = ((lane >> 4) << 3) + (lane & 7);
    int b_colb = (((lane >> 3) & 1) << 3) * 2;

    for (int kt = 0; kt <= qt; kt++) {
        if (kt < qt) { issueKV(kt + 1, (kt + 1) & 1); CPW(1); }
        else         { CPW(0); }
        __syncthreads();
        uint32_t kb_h = sb + FK_H(kt & 1), kb_l = sb + FK_L(kt & 1);
        uint32_t vb_h = sb + FV_H(kt & 1), vb_l = sb + FV_L(kt & 1);

        float P[16][4];
#pragma unroll
        for (int i = 0; i < 16; i++)
#pragma unroll
            for (int z = 0; z < 4; z++) P[i][z] = 0.f;
#pragma unroll
        for (int ks = 0; ks < 4; ks++) {
            uint32_t kso = (uint32_t)(ks * 32);
#pragma unroll
            for (int nb = 0; nb < 8; nb++) {
                uint32_t addr = (uint32_t)((nb * 16 + b_rowi) * 144) + b_colb + kso;
                uint32_t kf[4], kfl[4];
                ldm4(kf, kb_h + addr);
                mma16816(P[2*nb],   qfh[ks], &kf[0]);
                mma16816(P[2*nb+1], qfh[ks], &kf[2]);
                mma16816(P[2*nb],   qfl[ks], &kf[0]);
                mma16816(P[2*nb+1], qfl[ks], &kf[2]);
                ldm4(kfl, kb_l + addr);
                mma16816(P[2*nb],   qfh[ks], &kfl[0]);
                mma16816(P[2*nb+1], qfh[ks], &kfl[2]);
            }
        }
#pragma unroll
        for (int i = 0; i < 16; i++)
#pragma unroll
            for (int z = 0; z < 4; z++) P[i][z] *= 0.125f;
        if (kt == qt) {
            int r0 = w * 16 + (lane >> 2);
#pragma unroll
            for (int i = 0; i < 16; i++) {
#pragma unroll
                for (int z = 0; z < 4; z++) {
                    int col = i * 8 + ((lane & 3) << 1) + (z & 1);
                    int row = r0 + ((z >> 1) << 3);
                    if (col > row) P[i][z] = -3.0e38f;
                }
            }
        }
        float mx0 = -3.0e38f, mx1 = -3.0e38f;
#pragma unroll
        for (int i = 0; i < 16; i++) {
            mx0 = fmaxf(mx0, fmaxf(P[i][0], P[i][1]));
            mx1 = fmaxf(mx1, fmaxf(P[i][2], P[i][3]));
        }
        mx0 = fmaxf(mx0, __shfl_xor_sync(0xffffffffu, mx0, 1));
        mx0 = fmaxf(mx0, __shfl_xor_sync(0xffffffffu, mx0, 2));
        mx1 = fmaxf(mx1, __shfl_xor_sync(0xffffffffu, mx1, 1));
        mx1 = fmaxf(mx1, __shfl_xor_sync(0xffffffffu, mx1, 2));
        float mn0 = fmaxf(m0, mx0), mn1 = fmaxf(m1, mx1);
        float al0 = expf(m0 - mn0), al1 = expf(m1 - mn1);
        m0 = mn0; m1 = mn1;
        float s0 = 0.f, s1 = 0.f;
#pragma unroll
        for (int i = 0; i < 16; i++) {
            P[i][0] = expf(P[i][0] - m0); s0 += P[i][0];
            P[i][1] = expf(P[i][1] - m0); s0 += P[i][1];
            P[i][2] = expf(P[i][2] - m1); s1 += P[i][2];
            P[i][3] = expf(P[i][3] - m1); s1 += P[i][3];
        }
        s0 += __shfl_xor_sync(0xffffffffu, s0, 1);
        s0 += __shfl_xor_sync(0xffffffffu, s0, 2);
        s1 += __shfl_xor_sync(0xffffffffu, s1, 1);
        s1 += __shfl_xor_sync(0xffffffffu, s1, 2);
        l0 = l0 * al0 + s0;
        l1 = l1 * al1 + s1;
#pragma unroll
        for (int i = 0; i < 8; i++) {
            O[i][0] *= al0; O[i][1] *= al0;
            O[i][2] *= al1; O[i][3] *= al1;
        }
#pragma unroll
        for (int ks = 0; ks < 8; ks++) {
            uint32_t pah[4], pal[4];
            bfsplit2(P[2*ks][0],   P[2*ks][1],   pah[0], pal[0]);
            bfsplit2(P[2*ks][2],   P[2*ks][3],   pah[1], pal[1]);
            bfsplit2(P[2*ks+1][0], P[2*ks+1][1], pah[2], pal[2]);
            bfsplit2(P[2*ks+1][2], P[2*ks+1][3], pah[3], pal[3]);
            uint32_t kso = (uint32_t)(ks * 32);
#pragma unroll
            for (int nb = 0; nb < 4; nb++) {
                uint32_t addr = (uint32_t)((nb * 16 + b_rowi) * 272) + b_colb + kso;
                uint32_t vf[4], vfl[4];
                ldm4(vf, vb_h + addr);
                mma16816(O[2*nb],   pah, &vf[0]);
                mma16816(O[2*nb+1], pah, &vf[2]);
                mma16816(O[2*nb],   pal, &vf[0]);
                mma16816(O[2*nb+1], pal, &vf[2]);
                ldm4(vfl, vb_l + addr);
                mma16816(O[2*nb],   pah, &vfl[0]);
                mma16816(O[2*nb+1], pah, &vfl[2]);
            }
        }
        __syncthreads();
    }

    float i0 = 1.f / l0, i1 = 1.f / l1;
    int r0 = qt * 128 + w * 16 + (lane >> 2);
    int c0 = hh * 64 + ((lane & 3) << 1);
#pragma unroll
    for (int nj = 0; nj < 8; nj++) {
        int cc = c0 + nj * 8;
        uint32_t hi, lo;
        hsplit2(O[nj][0] * i0, O[nj][1] * i0, hi, lo);
        size_t o0 = ((size_t)b * TT + r0) * DD + cc;
        *(uint32_t*)&Oh[o0] = hi;
        *(uint32_t*)&Ol[o0] = lo;
        hsplit2(O[nj][2] * i1, O[nj][3] * i1, hi, lo);
        size_t o1 = ((size_t)b * TT + r0 + 8) * DD + cc;
        *(uint32_t*)&Oh[o1] = hi;
        *(uint32_t*)&Ol[o1] = lo;
    }
}

// ---------------- host-side helpers ----------------
static void conv_B(const float* W, __half* bw, int K, int N) {
    convT_kernel<<<dim3(N / 32, K / 64), 256>>>(W, bw, K, N);
}
template <int EPI, int PASSES>
static void gemm(const __half* ah, const __half* al, const __half* bw,
                 const float* bias, const float* R, float* C,
                 __half* Chi, __half* Clo,
                 const float* ct, const float* st,
                 __nv_bfloat16* kh, __nv_bfloat16* kl, float* vb,
                 int M, int N, int K) {
    static bool cfg = false;
    if (!cfg) {
        cudaFuncSetAttribute(gemm_mma<EPI, PASSES>, cudaFuncAttributeMaxDynamicSharedMemorySize, GSMEM);
        cfg = true;
    }
    gemm_mma<EPI, PASSES><<<dim3(N / 128, M / 128), 256, GSMEM>>>(
        ah, al, bw, bias, R, C, Chi, Clo, ct, st, kh, kl, vb, M, N, K);
}

// ---------------- launch sequence ----------------
extern "C" void kernel_launch(void* const* d_in, const int* in_sizes, int n_in,
                              void* d_out, int out_size) {
    const int*   actions = (const int*)d_in[0];
    const int*   observ  = (const int*)d_in[1];
    const float* aemb    = (const float*)d_in[2];
    const float* oemb    = (const float*)d_in[3];
    const float* temb    = (const float*)d_in[4];
    const float* Wq      = (const float*)d_in[5];
    const float* bq      = (const float*)d_in[6];
    const float* Wk      = (const float*)d_in[7];
    const float* bk      = (const float*)d_in[8];
    const float* Wv      = (const float*)d_in[9];
    const float* bv      = (const float*)d_in[10];
    const float* Wo      = (const float*)d_in[11];
    const float* bo      = (const float*)d_in[12];
    const float* ln1_g   = (const float*)d_in[13];
    const float* ln1_b   = (const float*)d_in[14];
    const float* ln2_g   = (const float*)d_in[15];
    const float* ln2_b   = (const float*)d_in[16];
    const float* W1      = (const float*)d_in[17];
    const float* b1      = (const float*)d_in[18];
    const float* W2      = (const float*)d_in[19];
    const float* b2      = (const float*)d_in[20];
    const float* out_g   = (const float*)d_in[21];
    const float* out_b   = (const float*)d_in[22];
    const float* Wout    = (const float*)d_in[23];
    const float* bout    = (const float*)d_in[24];

    float *x, *qkv, *b3, *ct, *st;
    __half *ah, *al, *fh, *bw;
    __nv_bfloat16 *qh, *ql, *kh, *kl, *vh, *vl;
    cudaGetSymbolAddress((void**)&x,   g_x);
    cudaGetSymbolAddress((void**)&qkv, g_qkv);
    cudaGetSymbolAddress((void**)&b3,  g_b3);
    cudaGetSymbolAddress((void**)&ct,  g_cos);
    cudaGetSymbolAddress((void**)&st,  g_sin);
    cudaGetSymbolAddress((void**)&ah,  g_ah);
    cudaGetSymbolAddress((void**)&al,  g_al);
    cudaGetSymbolAddress((void**)&fh,  g_fh);
    cudaGetSymbolAddress((void**)&bw,  g_bw);
    cudaGetSymbolAddress((void**)&qh,  g_qh);
    cudaGetSymbolAddress((void**)&ql,  g_ql);
    cudaGetSymbolAddress((void**)&kh,  g_kh);
    cudaGetSymbolAddress((void**)&kl,  g_kl);
    cudaGetSymbolAddress((void**)&vh,  g_vh);
    cudaGetSymbolAddress((void**)&vl,  g_vl);

    static bool fcfg = false;
    if (!fcfg) {
        cudaFuncSetAttribute(flash_attn, cudaFuncAttributeMaxDynamicSharedMemorySize, FSMEM);
        fcfg = true;
    }

    trig_kernel<<<(TT * 32 + 255) / 256, 256>>>(ct, st);
    embed_kernel<<<(BT * DD + 255) / 256, 256>>>(actions, observ, aemb, oemb, temb, x);

    for (int i = 0; i < LL; i++) {
        ln_kernel<<<BT, 256>>>(x, ln1_g + (size_t)i * DD, ln1_b + (size_t)i * DD, ah, al);

        // fused QKV with rope epilogue: Bt rows [0,1024)=Wq^T, [1024,2048)=Wk^T, [2048,3072)=Wv^T
        conv_B(Wq + (size_t)i * DD * DD, bw,                       DD, DD);
        conv_B(Wk + (size_t)i * DD * DD, bw + (size_t)DD * DD,     DD, DD);
        conv_B(Wv + (size_t)i * DD * DD, bw + (size_t)2 * DD * DD, DD, DD);
        cudaMemcpyAsync(b3,            bq + (size_t)i * DD, DD * 4, cudaMemcpyDeviceToDevice);
        cudaMemcpyAsync(b3 + DD,       bk + (size_t)i * DD, DD * 4, cudaMemcpyDeviceToDevice);
        cudaMemcpyAsync(b3 + 2 * DD,   bv + (size_t)i * DD, DD * 4, cudaMemcpyDeviceToDevice);
        gemm<3, 2>(ah, al, bw, b3, nullptr, nullptr,
                   (__half*)qh, (__half*)ql, ct, st, kh, kl, qkv, BT, 3 * DD, DD);

        vsplit_kernel<<<dim3(TT / 32, DD / 32, BB), 256>>>(qkv, vh, vl);

        flash_attn<<<dim3(TT / 128, BB * HH), 256, FSMEM>>>(qh, ql, kh, kl, vh, vl, ah, al);

        conv_B(Wo + (size_t)i * DD * DD, bw, DD, DD);
        gemm<2, 2>(ah, al, bw, bo + (size_t)i * DD, x, x,
                   nullptr, nullptr, nullptr, nullptr, nullptr, nullptr, nullptr, BT, DD, DD);

        ln_kernel<<<BT, 256>>>(x, ln2_g + (size_t)i * DD, ln2_b + (size_t)i * DD, ah, al);
        conv_B(W1 + (size_t)i * DD * DFF, bw, DD, DFF);
        gemm<1, 2>(ah, al, bw, b1 + (size_t)i * DFF, nullptr, nullptr,
                   fh, nullptr, nullptr, nullptr, nullptr, nullptr, nullptr, BT, DFF, DD);

        conv_B(W2 + (size_t)i * DFF * DD, bw, DFF, DD);
        gemm<2, 1>(fh, nullptr, bw, b2 + (size_t)i * DD, x, x,
                   nullptr, nullptr, nullptr, nullptr, nullptr, nullptr, nullptr, BT, DD, DFF);
    }

    ln_kernel<<<BT, 256>>>(x, out_g, out_b, ah, al);
    conv_B(Wout, bw, DD, OV);
    gemm<0, 1>(ah, nullptr, bw, bout, nullptr, (float*)d_out,
               nullptr, nullptr, nullptr, nullptr, nullptr, nullptr, nullptr, BT, OV, DD);
}

// round 16
// speedup vs baseline: 1.7835x; 1.0416x over previous
#include <cuda_runtime.h>
#include <cuda_bf16.h>
#include <cuda_fp16.h>
#include <math.h>
#include <stdint.h>

#define LL 2
#define DD 1024
#define HH 16
#define DHH 64
#define DFF 4096
#define BB 2
#define TT 2048
#define OV 4096
#define BT (BB*TT)   // 4096

// ---------------- scratch (device globals; no runtime allocation) ----------------
__device__ float g_x  [BT*DD];
__device__ float g_qkv[(size_t)BT*DD];     // V part only (fp32), written by QKV epilogue
__device__ float g_b3a[3*DD];
__device__ float g_b3b[3*DD];
__device__ float g_cos[TT*32];
__device__ float g_sin[TT*32];
// fp16 activations
__device__ __align__(16) __half g_ah[(size_t)BT*DD];    // activation hi [BT,DD]
__device__ __align__(16) __half g_al[(size_t)BT*DD];
__device__ __align__(16) __half g_fh[(size_t)BT*DFF];   // gelu(ff) fp16 [BT,DFF]
// per-layer pre-converted weights (fp16, transposed [N,K])
__device__ __align__(16) __half g_wqkv0[(size_t)3*DD*DD];
__device__ __align__(16) __half g_wqkv1[(size_t)3*DD*DD];
__device__ __align__(16) __half g_wo0[(size_t)DD*DD];
__device__ __align__(16) __half g_wo1[(size_t)DD*DD];
__device__ __align__(16) __half g_w10[(size_t)DFF*DD];
__device__ __align__(16) __half g_w11[(size_t)DFF*DD];
__device__ __align__(16) __half g_w20[(size_t)DFF*DD];
__device__ __align__(16) __half g_w21[(size_t)DFF*DD];
__device__ __align__(16) __half g_wout[(size_t)OV*DD];
// attention split operands (bf16)
__device__ __align__(16) __nv_bfloat16 g_qh[(size_t)BB*HH*TT*DHH];  // [bh][t][d]
__device__ __align__(16) __nv_bfloat16 g_ql[(size_t)BB*HH*TT*DHH];
__device__ __align__(16) __nv_bfloat16 g_kh[(size_t)BB*HH*TT*DHH];
__device__ __align__(16) __nv_bfloat16 g_kl[(size_t)BB*HH*TT*DHH];
__device__ __align__(16) __nv_bfloat16 g_vh[(size_t)BB*HH*DHH*TT];  // [bh][d][t]
__device__ __align__(16) __nv_bfloat16 g_vl[(size_t)BB*HH*DHH*TT];

// ---------------- warp-MMA primitives (baseline PTX; no sm_103a features) ----------
__device__ __forceinline__ uint32_t smem_u32(const void* p) {
    uint32_t a;
    asm("{ .reg .u64 t; cvta.to.shared.u64 t, %1; cvt.u32.u64 %0, t; }" : "=r"(a) : "l"(p));
    return a;
}
__device__ __forceinline__ void ldm4(uint32_t* r, uint32_t addr) {
    asm volatile("ldmatrix.sync.aligned.m8n8.x4.shared.b16 {%0,%1,%2,%3}, [%4];"
                 : "=r"(r[0]), "=r"(r[1]), "=r"(r[2]), "=r"(r[3]) : "r"(addr));
}
// bf16 mma (flash attention)
__device__ __forceinline__ void mma16816(float* d, const uint32_t* a, const uint32_t* b) {
    asm volatile("mma.sync.aligned.m16n8k16.row.col.f32.bf16.bf16.f32 "
                 "{%0,%1,%2,%3}, {%4,%5,%6,%7}, {%8,%9}, {%0,%1,%2,%3};"
                 : "+f"(d[0]), "+f"(d[1]), "+f"(d[2]), "+f"(d[3])
                 : "r"(a[0]), "r"(a[1]), "r"(a[2]), "r"(a[3]), "r"(b[0]), "r"(b[1]));
}
// fp16 mma (GEMMs)
__device__ __forceinline__ void mma16816h(float* d, const uint32_t* a, const uint32_t* b) {
    asm volatile("mma.sync.aligned.m16n8k16.row.col.f32.f16.f16.f32 "
                 "{%0,%1,%2,%3}, {%4,%5,%6,%7}, {%8,%9}, {%0,%1,%2,%3};"
                 : "+f"(d[0]), "+f"(d[1]), "+f"(d[2]), "+f"(d[3])
                 : "r"(a[0]), "r"(a[1]), "r"(a[2]), "r"(a[3]), "r"(b[0]), "r"(b[1]));
}
#define CPA(dst, src) asm volatile("cp.async.cg.shared.global [%0], [%1], 16;" :: "r"(dst), "l"(src))
#define CPC()         asm volatile("cp.async.commit_group;")
#define CPW(n)        asm volatile("cp.async.wait_group %0;" :: "n"(n))

__device__ __forceinline__ uint32_t bfpack(float x, float y) {
    __nv_bfloat162 t;
    t.x = __float2bfloat16_rn(x);
    t.y = __float2bfloat16_rn(y);
    return *(uint32_t*)&t;
}
__device__ __forceinline__ void bfsplit2(float x, float y, uint32_t& hi, uint32_t& lo) {
    __nv_bfloat16 hx = __float2bfloat16_rn(x), hy = __float2bfloat16_rn(y);
    __nv_bfloat162 H; H.x = hx; H.y = hy;
    hi = *(uint32_t*)&H;
    lo = bfpack(x - __bfloat162float(hx), y - __bfloat162float(hy));
}

// ---------------- transpose + fp16 round: W[K,N] -> Bt[N,K] ----------------
__global__ void convT_kernel(const float* __restrict__ W, __half* __restrict__ ht,
                             int K, int N) {
    __shared__ float t[64][33];
    int n0 = blockIdx.x * 32, k0 = blockIdx.y * 64;
    int tx = threadIdx.x & 31, ty = threadIdx.x >> 5;
#pragma unroll
    for (int ky = 0; ky < 64; ky += 8)
        t[ky + ty][tx] = W[(size_t)(k0 + ky + ty) * N + n0 + tx];
    __syncthreads();
    int kl = threadIdx.x & 63, nb = threadIdx.x >> 6;
#pragma unroll
    for (int n = nb; n < 32; n += 4) {
        float v = t[kl][n];
        ht[(size_t)(n0 + n) * K + k0 + kl] = __float2half_rn(v);
    }
}

// ---------------- batched QKV transpose+round (3 weights -> one [3N,K] buffer) --------
__global__ void qkvconvT_kernel(const float* __restrict__ Wq, const float* __restrict__ Wk,
                                const float* __restrict__ Wv, __half* __restrict__ ht) {
    __shared__ float t[64][33];
    const float* W = blockIdx.z == 0 ? Wq : (blockIdx.z == 1 ? Wk : Wv);
    __half* out = ht + (size_t)blockIdx.z * DD * DD;
    int n0 = blockIdx.x * 32, k0 = blockIdx.y * 64;
    int tx = threadIdx.x & 31, ty = threadIdx.x >> 5;
#pragma unroll
    for (int ky = 0; ky < 64; ky += 8)
        t[ky + ty][tx] = W[(size_t)(k0 + ky + ty) * DD + n0 + tx];
    __syncthreads();
    int kl = threadIdx.x & 63, nb = threadIdx.x >> 6;
#pragma unroll
    for (int n = nb; n < 32; n += 4) {
        float v = t[kl][n];
        out[(size_t)(n0 + n) * DD + k0 + kl] = __float2half_rn(v);
    }
}

// ---------------- bias concat ----------------
__global__ void b3_kernel(const float* __restrict__ bq, const float* __restrict__ bk,
                          const float* __restrict__ bv, float* __restrict__ b3) {
    int i = blockIdx.x * 256 + threadIdx.x;
    if (i >= 3 * DD) return;
    b3[i] = i < DD ? bq[i] : (i < 2 * DD ? bk[i - DD] : bv[i - 2 * DD]);
}

// ---------------- fp16 GEMM: 2-stage cp.async, 2 CTAs/SM, 1 or 2 A-passes ------------
// EPI: 0 = bias -> fp32 C
//      1 = bias + GELU -> fp16 Chi only
//      2 = bias + residual -> fp32 C
//      3 = QKV epilogue: Q/K rope+bf16 split, V fp32
#define TROW 72
#define TBYTES (128*TROW*2)      // 18432 per tile
#define GSMEM (2*3*TBYTES)       // 110592 (2 stages x 3 tiles) -> 2 CTAs/SM

template <int EPI, int PASSES>
__global__ __launch_bounds__(256, 2)
void gemm_mma(const __half* __restrict__ Ahi, const __half* __restrict__ Alo,
              const __half* __restrict__ Bw,
              const float* __restrict__ bias, const float* __restrict__ R,
              float* __restrict__ C, __half* __restrict__ Chi,
              __half* __restrict__ Clo,
              const float* __restrict__ CT, const float* __restrict__ ST,
              __nv_bfloat16* __restrict__ Kh, __nv_bfloat16* __restrict__ Kl,
              float* __restrict__ Vb, int M, int N, int K) {
    extern __shared__ __align__(16) char smem[];
    const uint32_t sb = smem_u32(smem);
    int tid = threadIdx.x, lane = tid & 31, w = tid >> 5;
    int wm = w >> 2, wn = w & 3;
    int bm = blockIdx.y << 7, bn = blockIdx.x << 7;

    float acc[4][4][4];
#pragma unroll
    for (int i = 0; i < 4; i++)
#pragma unroll
        for (int j = 0; j < 4; j++)
#pragma unroll
            for (int z = 0; z < 4; z++) acc[i][j][z] = 0.f;

    int lrow = tid >> 3, lseg = tid & 7;
    auto issue = [&](int kc, int st) {
        int kb = kc << 6;
        uint32_t base = sb + st * 3 * TBYTES;
#pragma unroll
        for (int i = 0; i < 4; i++) {
            int row = lrow + i * 32;
            uint32_t so = base + (uint32_t)(row * 144 + lseg * 16);
            size_t ga = (size_t)(bm + row) * K + kb + lseg * 8;
            size_t gb = (size_t)(bn + row) * K + kb + lseg * 8;
            CPA(so, Ahi + ga);
            if (PASSES == 2) CPA(so + TBYTES, Alo + ga);
            CPA(so + 2*TBYTES, Bw + gb);
        }
        CPC();
    };

    const int nch = K >> 6;
    issue(0, 0);

    int a_row = wm * 64 + (lane & 15), a_col = (lane >> 4) << 3;
    int b_row = wn * 32 + ((lane >> 4) << 3) + (lane & 7), b_col = ((lane >> 3) & 1) << 3;
    uint32_t aoff = (uint32_t)(a_row * TROW + a_col) * 2;
    uint32_t boff = (uint32_t)(b_row * TROW + b_col) * 2 + 2 * TBYTES;

    for (int kc = 0; kc < nch; kc++) {
        if (kc + 1 < nch) { issue(kc + 1, (kc + 1) & 1); CPW(1); }
        else              { CPW(0); }
        __syncthreads();

        uint32_t base = sb + (uint32_t)((kc & 1) * 3 * TBYTES);
        uint32_t aoff_h = base + aoff, aoff_l = aoff_h + TBYTES;
        uint32_t boff_b = base + boff;
#pragma unroll
        for (int ks = 0; ks < 4; ks++) {
            uint32_t ah[4][4], bw[8];
            uint32_t kso = (uint32_t)(ks * 32);
#pragma unroll
            for (int mi = 0; mi < 4; mi++)
                ldm4(ah[mi], aoff_h + (uint32_t)(mi * 16 * TROW * 2) + kso);
            ldm4(&bw[0], boff_b + kso);
            ldm4(&bw[4], boff_b + (uint32_t)(16 * TROW * 2) + kso);
#pragma unroll
            for (int mi = 0; mi < 4; mi++)
#pragma unroll
                for (int ni = 0; ni < 4; ni++)
                    mma16816h(acc[mi][ni], ah[mi], &bw[ni * 2]);
            if (PASSES == 2) {
                uint32_t al[4][4];
#pragma unroll
                for (int mi = 0; mi < 4; mi++)
                    ldm4(al[mi], aoff_l + (uint32_t)(mi * 16 * TROW * 2) + kso);
#pragma unroll
                for (int mi = 0; mi < 4; mi++)
#pragma unroll
                    for (int ni = 0; ni < 4; ni++)
                        mma16816h(acc[mi][ni], al[mi], &bw[ni * 2]);
            }
        }
        __syncthreads();
    }

    // ---- epilogue ----
#pragma unroll
    for (int mi = 0; mi < 4; mi++) {
#pragma unroll
        for (int ni = 0; ni < 4; ni++) {
            int r0 = bm + wm * 64 + mi * 16 + (lane >> 2);
            int c0 = bn + wn * 32 + ni * 8 + ((lane & 3) << 1);
#pragma unroll
            for (int half = 0; half < 2; half++) {
                int gm = r0 + half * 8;
                float v0 = acc[mi][ni][half * 2]     + bias[c0];
                float v1 = acc[mi][ni][half * 2 + 1] + bias[c0 + 1];
                if (EPI == 1) {
                    v0 *= normcdff(v0); v1 *= normcdff(v1);
                    __half2 H;
                    H.x = __float2half_rn(v0); H.y = __float2half_rn(v1);
                    *(uint32_t*)&Chi[(size_t)gm * N + c0] = *(uint32_t*)&H;
                } else if (EPI == 3) {
                    int region = c0 >> 10;
                    if (region < 2) {
                        int d = c0 & 63, hhh = (c0 & 1023) >> 6, p = d >> 1;
                        int t = gm & (TT - 1), bb = gm >> 11;
                        float cc = CT[t * 32 + p], ss = ST[t * 32 + p];
                        float o0 = v0 * cc - v1 * ss;
                        float o1 = v0 * ss + v1 * cc;
                        uint32_t hi, lo;
                        bfsplit2(o0, o1, hi, lo);
                        size_t ob = (((size_t)(bb * HH + hhh) * TT) + t) * 64 + d;
                        if (region == 0) {
                            *(uint32_t*)&Chi[ob] = hi;   // qh (bf16 bits)
                            *(uint32_t*)&Clo[ob] = lo;   // ql
                        } else {
                            *(uint32_t*)&Kh[ob] = hi;
                            *(uint32_t*)&Kl[ob] = lo;
                        }
                    } else {
                        float2 o; o.x = v0; o.y = v1;
                        *(float2*)&Vb[(size_t)gm * DD + (c0 & 1023)] = o;
                    }
                } else {
                    if (EPI == 2) {
                        v0 += R[(size_t)gm * N + c0];
                        v1 += R[(size_t)gm * N + c0 + 1];
                    }
                    float2 o; o.x = v0; o.y = v1;
                    *(float2*)&C[(size_t)gm * N + c0] = o;
                }
            }
        }
    }
}

// ---------------- RoPE trig tables (double precision; fast-math-proof) ----------------
__global__ void trig_kernel(float* __restrict__ ct, float* __restrict__ st) {
    int i = blockIdx.x * 256 + threadIdx.x;
    if (i >= TT * 32) return;
    int t = i >> 5, p = i & 31;
    double inv = exp2(-13.287712379549449 * ((double)(2 * p) * (1.0 / 64.0)));
    float invf = (float)inv;
    float angf = (float)((double)t * (double)invf);
    double c, s;
    sincos((double)angf, &s, &c);
    ct[i] = (float)c;
    st[i] = (float)s;
}

// ---------------- embedding ----------------
__global__ void embed_kernel(const int* __restrict__ act, const int* __restrict__ obs,
                             const float* __restrict__ aemb, const float* __restrict__ oemb,
                             const float* __restrict__ temb, float* __restrict__ x) {
    int idx = blockIdx.x * blockDim.x + threadIdx.x;
    if (idx >= BT * DD) return;
    int r = idx / DD, d = idx % DD;
    x[idx] = aemb[(size_t)act[r] * DD + d] + temb[d]
           + oemb[(size_t)obs[r] * DD + d] + temb[DD + d];
}

// ---------------- layernorm -> fp16 hi/lo split directly ----------------
__global__ void ln_kernel(const float* __restrict__ x, const float* __restrict__ g,
                          const float* __restrict__ b, __half* __restrict__ yh,
                          __half* __restrict__ yl) {
    int r = blockIdx.x;
    const float* xr = x + (size_t)r * DD;
    float v[4];
    float s = 0.f, ss = 0.f;
#pragma unroll
    for (int i = 0; i < 4; i++) {
        float t = xr[threadIdx.x + i * 256];
        v[i] = t; s += t; ss += t * t;
    }
#pragma unroll
    for (int o = 16; o > 0; o >>= 1) {
        s  += __shfl_xor_sync(0xffffffffu, s,  o);
        ss += __shfl_xor_sync(0xffffffffu, ss, o);
    }
    __shared__ float rs[8], rss[8];
    int w = threadIdx.x >> 5;
    if ((threadIdx.x & 31) == 0) { rs[w] = s; rss[w] = ss; }
    __syncthreads();
    if (threadIdx.x == 0) {
        float a = 0.f, c = 0.f;
#pragma unroll
        for (int i = 0; i < 8; i++) { a += rs[i]; c += rss[i]; }
        rs[0] = a; rss[0] = c;
    }
    __syncthreads();
    float mean = rs[0] * (1.f / DD);
    float var  = rss[0] * (1.f / DD) - mean * mean;
    float inv  = rsqrtf(var + 1e-5f);
#pragma unroll
    for (int i = 0; i < 4; i++) {
        int d = threadIdx.x + i * 256;
        float val = (v[i] - mean) * inv * g[d] + b[d];
        __half h = __float2half_rn(val);
        yh[(size_t)r * DD + d] = h;
        yl[(size_t)r * DD + d] = __float2half_rn(val - __half2float(h));
    }
}

// ---------------- V split + transpose into [bh][d][t] (from fp32 V buffer) -----------
__global__ void vsplit_kernel(const float* __restrict__ V,
                              __nv_bfloat16* __restrict__ vh, __nv_bfloat16* __restrict__ vl) {
    __shared__ float ts[32][33];
    int t0 = blockIdx.x * 32, d0 = blockIdx.y * 32, b = blockIdx.z;
    int tx = threadIdx.x & 31, ty = threadIdx.x >> 5;
#pragma unroll
    for (int i = ty; i < 32; i += 8)
        ts[i][tx] = V[((size_t)b * TT + t0 + i) * DD + d0 + tx];
    __syncthreads();
    int hh = d0 >> 6, dl0 = d0 & 63;
#pragma unroll
    for (int i = ty; i < 32; i += 8) {
        float v = ts[tx][i];
        size_t o = ((size_t)(b * HH + hh) * 64 + dl0 + i) * TT + t0 + tx;
        __nv_bfloat16 h = __float2bfloat16_rn(v);
        vh[o] = h;
        vl[o] = __float2bfloat16_rn(v - __bfloat162float(h));
    }
}

// ================= fused flash attention (bf16 3-pass internally; fp16 output) ========
#define FQ_H 0
#define FQ_L 18432
#define FK_H(st) (36864 + (st)*36864)
#define FK_L(st) (FK_H(st) + 18432)
#define FV_H(st) (110592 + (st)*34816)
#define FV_L(st) (FV_H(st) + 17408)
#define FSMEM 180224

__global__ __launch_bounds__(256)
void flash_attn(const __nv_bfloat16* __restrict__ Qh, const __nv_bfloat16* __restrict__ Ql,
                const __nv_bfloat16* __restrict__ Kh, const __nv_bfloat16* __restrict__ Kl,
                const __nv_bfloat16* __restrict__ Vh, const __nv_bfloat16* __restrict__ Vl,
                __half* __restrict__ Oh) {
    int qt = gridDim.x - 1 - blockIdx.x;
    int bh = blockIdx.y;
    int b = bh >> 4, hh = bh & 15;
    extern __shared__ __align__(16) char smem[];
    const uint32_t sb = smem_u32(smem);
    int tid = threadIdx.x, lane = tid & 31, w = tid >> 5;

    {
        int row = tid >> 1, segb = (tid & 1) * 4;
        size_t qg = ((size_t)bh * TT + qt * 128 + row) * 64 + segb * 8;
#pragma unroll
        for (int s = 0; s < 4; s++) {
            uint32_t so = (uint32_t)(row * 144 + (segb + s) * 16);
            *(uint4*)(smem + FQ_H + so) = *(const uint4*)(Qh + qg + s * 8);
            *(uint4*)(smem + FQ_L + so) = *(const uint4*)(Ql + qg + s * 8);
        }
    }

    auto issueKV = [&](int kt, int st) {
        int row = tid >> 1, segb = (tid & 1) * 4;
        size_t kg = ((size_t)bh * TT + kt * 128 + row) * 64 + segb * 8;
#pragma unroll
        for (int s = 0; s < 4; s++) {
            uint32_t so = (uint32_t)(row * 144 + (segb + s) * 16);
            CPA(sb + FK_H(st) + so, Kh + kg + s * 8);
            CPA(sb + FK_L(st) + so, Kl + kg + s * 8);
        }
        int vrow = tid >> 2, vsegb = (tid & 3) * 4;
        size_t vg = ((size_t)bh * 64 + vrow) * TT + kt * 128 + vsegb * 8;
#pragma unroll
        for (int s = 0; s < 4; s++) {
            uint32_t so = (uint32_t)(vrow * 272 + (vsegb + s) * 16);
            CPA(sb + FV_H(st) + so, Vh + vg + s * 8);
            CPA(sb + FV_L(st) + so, Vl + vg + s * 8);
        }
        CPC();
    };
    issueKV(0, 0);
    __syncthreads();

    uint32_t qfh[4][4], qfl[4][4];
    {
        int a_row = w * 16 + (lane & 15), a_col = (lane >> 4) << 3;
        uint32_t qa = (uint32_t)(a_row * 144 + a_col * 2);
#pragma unroll
        for (int ks = 0; ks < 4; ks++) {
            ldm4(qfh[ks], sb + FQ_H + qa + ks * 32);
            ldm4(qfl[ks], sb + FQ_L + qa + ks * 32);
        }
    }

    float m0 = -3.0e38f, m1 = -3.0e38f, l0 = 0.f, l1 = 0.f;
    float O[8][4];
#pragma unroll
    for (int i = 0; i < 8; i++)
#pragma unroll
        for (int z = 0; z < 4; z++) O[i][z] = 0.f;

    int b_rowi = ((lane >> 4) << 3) + (lane & 7);
    int b_colb = (((lane >> 3) & 1) << 3) * 2;

    for (int kt = 0; kt <= qt; kt++) {
        if (kt < qt) { issueKV(kt + 1, (kt + 1) & 1); CPW(1); }
        else         { CPW(0); }
        __syncthreads();
        uint32_t kb_h = sb + FK_H(kt & 1), kb_l = sb + FK_L(kt & 1);
        uint32_t vb_h = sb + FV_H(kt & 1), vb_l = sb + FV_L(kt & 1);

        float P[16][4];
#pragma unroll
        for (int i = 0; i < 16; i++)
#pragma unroll
            for (int z = 0; z < 4; z++) P[i][z] = 0.f;
#pragma unroll
        for (int ks = 0; ks < 4; ks++) {
            uint32_t kso = (uint32_t)(ks * 32);
#pragma unroll
            for (int nb = 0; nb < 8; nb++) {
                uint32_t addr = (uint32_t)((nb * 16 + b_rowi) * 144) + b_colb + kso;
                uint32_t kf[4], kfl[4];
                ldm4(kf, kb_h + addr);
                mma16816(P[2*nb],   qfh[ks], &kf[0]);
                mma16816(P[2*nb+1], qfh[ks], &kf[2]);
                mma16816(P[2*nb],   qfl[ks], &kf[0]);
                mma16816(P[2*nb+1], qfl[ks], &kf[2]);
                ldm4(kfl, kb_l + addr);
                mma16816(P[2*nb],   qfh[ks], &kfl[0]);
                mma16816(P[2*nb+1], qfh[ks], &kfl[2]);
            }
        }
#pragma unroll
        for (int i = 0; i < 16; i++)
#pragma unroll
            for (int z = 0; z < 4; z++) P[i][z] *= 0.125f;
        if (kt == qt) {
            int r0 = w * 16 + (lane >> 2);
#pragma unroll
            for (int i = 0; i < 16; i++) {
#pragma unroll
                for (int z = 0; z < 4; z++) {
                    int col = i * 8 + ((lane & 3) << 1) + (z & 1);
                    int row = r0 + ((z >> 1) << 3);
                    if (col > row) P[i][z] = -3.0e38f;
                }
            }
        }
        float mx0 = -3.0e38f, mx1 = -3.0e38f;
#pragma unroll
        for (int i = 0; i < 16; i++) {
            mx0 = fmaxf(mx0, fmaxf(P[i][0], P[i][1]));
            mx1 = fmaxf(mx1, fmaxf(P[i][2], P[i][3]));
        }
        mx0 = fmaxf(mx0, __shfl_xor_sync(0xffffffffu, mx0, 1));
        mx0 = fmaxf(mx0, __shfl_xor_sync(0xffffffffu, mx0, 2));
        mx1 = fmaxf(mx1, __shfl_xor_sync(0xffffffffu, mx1, 1));
        mx1 = fmaxf(mx1, __shfl_xor_sync(0xffffffffu, mx1, 2));
        float mn0 = fmaxf(m0, mx0), mn1 = fmaxf(m1, mx1);
        float al0 = expf(m0 - mn0), al1 = expf(m1 - mn1);
        m0 = mn0; m1 = mn1;
        float s0 = 0.f, s1 = 0.f;
#pragma unroll
        for (int i = 0; i < 16; i++) {
            P[i][0] = expf(P[i][0] - m0); s0 += P[i][0];
            P[i][1] = expf(P[i][1] - m0); s0 += P[i][1];
            P[i][2] = expf(P[i][2] - m1); s1 += P[i][2];
            P[i][3] = expf(P[i][3] - m1); s1 += P[i][3];
        }
        s0 += __shfl_xor_sync(0xffffffffu, s0, 1);
        s0 += __shfl_xor_sync(0xffffffffu, s0, 2);
        s1 += __shfl_xor_sync(0xffffffffu, s1, 1);
        s1 += __shfl_xor_sync(0xffffffffu, s1, 2);
        l0 = l0 * al0 + s0;
        l1 = l1 * al1 + s1;
#pragma unroll
        for (int i = 0; i < 8; i++) {
            O[i][0] *= al0; O[i][1] *= al0;
            O[i][2] *= al1; O[i][3] *= al1;
        }
#pragma unroll
        for (int ks = 0; ks < 8; ks++) {
            uint32_t pah[4], pal[4];
            bfsplit2(P[2*ks][0],   P[2*ks][1],   pah[0], pal[0]);
            bfsplit2(P[2*ks][2],   P[2*ks][3],   pah[1], pal[1]);
            bfsplit2(P[2*ks+1][0], P[2*ks+1][1], pah[2], pal[2]);
            bfsplit2(P[2*ks+1][2], P[2*ks+1][3], pah[3], pal[3]);
            uint32_t kso = (uint32_t)(ks * 32);
#pragma unroll
            for (int nb = 0; nb < 4; nb++) {
                uint32_t addr = (uint32_t)((nb * 16 + b_rowi) * 272) + b_colb + kso;
                uint32_t vf[4], vfl[4];
                ldm4(vf, vb_h + addr);
                mma16816(O[2*nb],   pah, &vf[0]);
                mma16816(O[2*nb+1], pah, &vf[2]);
                mma16816(O[2*nb],   pal, &vf[0]);
                mma16816(O[2*nb+1], pal, &vf[2]);
                ldm4(vfl, vb_l + addr);
                mma16816(O[2*nb],   pah, &vfl[0]);
                mma16816(O[2*nb+1], pah, &vfl[2]);
            }
        }
        __syncthreads();
    }

    float i0 = 1.f / l0, i1 = 1.f / l1;
    int r0 = qt * 128 + w * 16 + (lane >> 2);
    int c0 = hh * 64 + ((lane & 3) << 1);
#pragma unroll
    for (int nj = 0; nj < 8; nj++) {
        int cc = c0 + nj * 8;
        __half2 H;
        H.x = __float2half_rn(O[nj][0] * i0);
        H.y = __float2half_rn(O[nj][1] * i0);
        *(uint32_t*)&Oh[((size_t)b * TT + r0) * DD + cc] = *(uint32_t*)&H;
        H.x = __float2half_rn(O[nj][2] * i1);
        H.y = __float2half_rn(O[nj][3] * i1);
        *(uint32_t*)&Oh[((size_t)b * TT + r0 + 8) * DD + cc] = *(uint32_t*)&H;
    }
}

// ---------------- host-side helpers ----------------
template <int EPI, int PASSES>
static void gemm(const __half* ah, const __half* al, const __half* bw,
                 const float* bias, const float* R, float* C,
                 __half* Chi, __half* Clo,
                 const float* ct, const float* st,
                 __nv_bfloat16* kh, __nv_bfloat16* kl, float* vb,
                 int M, int N, int K) {
    static bool cfg = false;
    if (!cfg) {
        cudaFuncSetAttribute(gemm_mma<EPI, PASSES>, cudaFuncAttributeMaxDynamicSharedMemorySize, GSMEM);
        cfg = true;
    }
    gemm_mma<EPI, PASSES><<<dim3(N / 128, M / 128), 256, GSMEM>>>(
        ah, al, bw, bias, R, C, Chi, Clo, ct, st, kh, kl, vb, M, N, K);
}

// ---------------- launch sequence ----------------
extern "C" void kernel_launch(void* const* d_in, const int* in_sizes, int n_in,
                              void* d_out, int out_size) {
    const int*   actions = (const int*)d_in[0];
    const int*   observ  = (const int*)d_in[1];
    const float* aemb    = (const float*)d_in[2];
    const float* oemb    = (const float*)d_in[3];
    const float* temb    = (const float*)d_in[4];
    const float* Wq      = (const float*)d_in[5];
    const float* bq      = (const float*)d_in[6];
    const float* Wk      = (const float*)d_in[7];
    const float* bk      = (const float*)d_in[8];
    const float* Wv      = (const float*)d_in[9];
    const float* bv      = (const float*)d_in[10];
    const float* Wo      = (const float*)d_in[11];
    const float* bo      = (const float*)d_in[12];
    const float* ln1_g   = (const float*)d_in[13];
    const float* ln1_b   = (const float*)d_in[14];
    const float* ln2_g   = (const float*)d_in[15];
    const float* ln2_b   = (const float*)d_in[16];
    const float* W1      = (const float*)d_in[17];
    const float* b1      = (const float*)d_in[18];
    const float* W2      = (const float*)d_in[19];
    const float* b2      = (const float*)d_in[20];
    const float* out_g   = (const float*)d_in[21];
    const float* out_b   = (const float*)d_in[22];
    const float* Wout    = (const float*)d_in[23];
    const float* bout    = (const float*)d_in[24];

    float *x, *qkv, *ct, *st;
    float *b3[2];
    __half *ah, *al, *fh;
    __half *wqkv[2], *wo[2], *w1[2], *w2[2], *wout;
    __nv_bfloat16 *qh, *ql, *kh, *kl, *vh, *vl;
    cudaGetSymbolAddress((void**)&x,   g_x);
    cudaGetSymbolAddress((void**)&qkv, g_qkv);
    cudaGetSymbolAddress((void**)&b3[0], g_b3a);
    cudaGetSymbolAddress((void**)&b3[1], g_b3b);
    cudaGetSymbolAddress((void**)&ct,  g_cos);
    cudaGetSymbolAddress((void**)&st,  g_sin);
    cudaGetSymbolAddress((void**)&ah,  g_ah);
    cudaGetSymbolAddress((void**)&al,  g_al);
    cudaGetSymbolAddress((void**)&fh,  g_fh);
    cudaGetSymbolAddress((void**)&wqkv[0], g_wqkv0);
    cudaGetSymbolAddress((void**)&wqkv[1], g_wqkv1);
    cudaGetSymbolAddress((void**)&wo[0], g_wo0);
    cudaGetSymbolAddress((void**)&wo[1], g_wo1);
    cudaGetSymbolAddress((void**)&w1[0], g_w10);
    cudaGetSymbolAddress((void**)&w1[1], g_w11);
    cudaGetSymbolAddress((void**)&w2[0], g_w20);
    cudaGetSymbolAddress((void**)&w2[1], g_w21);
    cudaGetSymbolAddress((void**)&wout, g_wout);
    cudaGetSymbolAddress((void**)&qh,  g_qh);
    cudaGetSymbolAddress((void**)&ql,  g_ql);
    cudaGetSymbolAddress((void**)&kh,  g_kh);
    cudaGetSymbolAddress((void**)&kl,  g_kl);
    cudaGetSymbolAddress((void**)&vh,  g_vh);
    cudaGetSymbolAddress((void**)&vl,  g_vl);

    static bool fcfg = false;
    static cudaStream_t s2 = nullptr;
    static cudaEvent_t evF, evW[9];
    if (!fcfg) {
        cudaFuncSetAttribute(flash_attn, cudaFuncAttributeMaxDynamicSharedMemorySize, FSMEM);
        cudaStreamCreateWithFlags(&s2, cudaStreamNonBlocking);
        cudaEventCreateWithFlags(&evF, cudaEventDisableTiming);
        for (int i = 0; i < 9; i++) cudaEventCreateWithFlags(&evW[i], cudaEventDisableTiming);
        fcfg = true;
    }

    // ---- fork: all weight conversions + trig + bias concats on side stream ----
    cudaEventRecord(evF, 0);
    cudaStreamWaitEvent(s2, evF, 0);
    trig_kernel<<<(TT * 32 + 255) / 256, 256, 0, s2>>>(ct, st);
    for (int i = 0; i < LL; i++) {
        b3_kernel<<<12, 256, 0, s2>>>(bq + (size_t)i * DD, bk + (size_t)i * DD,
                                      bv + (size_t)i * DD, b3[i]);
        qkvconvT_kernel<<<dim3(DD / 32, DD / 64, 3), 256, 0, s2>>>(
            Wq + (size_t)i * DD * DD, Wk + (size_t)i * DD * DD,
            Wv + (size_t)i * DD * DD, wqkv[i]);
        cudaEventRecord(evW[i * 4 + 0], s2);
        convT_kernel<<<dim3(DD / 32, DD / 64), 256, 0, s2>>>(Wo + (size_t)i * DD * DD, wo[i], DD, DD);
        cudaEventRecord(evW[i * 4 + 1], s2);
        convT_kernel<<<dim3(DFF / 32, DD / 64), 256, 0, s2>>>(W1 + (size_t)i * DD * DFF, w1[i], DD, DFF);
        cudaEventRecord(evW[i * 4 + 2], s2);
        convT_kernel<<<dim3(DD / 32, DFF / 64), 256, 0, s2>>>(W2 + (size_t)i * DFF * DD, w2[i], DFF, DD);
        cudaEventRecord(evW[i * 4 + 3], s2);
    }
    convT_kernel<<<dim3(OV / 32, DD / 64), 256, 0, s2>>>(Wout, wout, DD, OV);
    cudaEventRecord(evW[8], s2);

    // ---- main stream: forward pass ----
    embed_kernel<<<(BT * DD + 255) / 256, 256>>>(actions, observ, aemb, oemb, temb, x);

    for (int i = 0; i < LL; i++) {
        ln_kernel<<<BT, 256>>>(x, ln1_g + (size_t)i * DD, ln1_b + (size_t)i * DD, ah, al);

        cudaStreamWaitEvent(0, evW[i * 4 + 0], 0);
        gemm<3, 2>(ah, al, wqkv[i], b3[i], nullptr, nullptr,
                   (__half*)qh, (__half*)ql, ct, st, kh, kl, qkv, BT, 3 * DD, DD);

        vsplit_kernel<<<dim3(TT / 32, DD / 32, BB), 256>>>(qkv, vh, vl);

        flash_attn<<<dim3(TT / 128, BB * HH), 256, FSMEM>>>(qh, ql, kh, kl, vh, vl, ah);

        cudaStreamWaitEvent(0, evW[i * 4 + 1], 0);
        gemm<2, 1>(ah, nullptr, wo[i], bo + (size_t)i * DD, x, x,
                   nullptr, nullptr, nullptr, nullptr, nullptr, nullptr, nullptr, BT, DD, DD);

        ln_kernel<<<BT, 256>>>(x, ln2_g + (size_t)i * DD, ln2_b + (size_t)i * DD, ah, al);
        cudaStreamWaitEvent(0, evW[i * 4 + 2], 0);
        gemm<1, 2>(ah, al, w1[i], b1 + (size_t)i * DFF, nullptr, nullptr,
                   fh, nullptr, nullptr, nullptr, nullptr, nullptr, nullptr, BT, DFF, DD);

        cudaStreamWaitEvent(0, evW[i * 4 + 3], 0);
        gemm<2, 1>(fh, nullptr, w2[i], b2 + (size_t)i * DD, x, x,
                   nullptr, nullptr, nullptr, nullptr, nullptr, nullptr, nullptr, BT, DD, DFF);
    }

    ln_kernel<<<BT, 256>>>(x, out_g, out_b, ah, al);
    cudaStreamWaitEvent(0, evW[8], 0);
    gemm<0, 1>(ah, nullptr, wout, bout, nullptr, (float*)d_out,
               nullptr, nullptr, nullptr, nullptr, nullptr, nullptr, nullptr, BT, OV, DD);
}

// round 17
// speedup vs baseline: 1.9419x; 1.0888x over previous
#include <cuda_runtime.h>
#include <cuda_bf16.h>
#include <cuda_fp16.h>
#include <math.h>
#include <stdint.h>

#define LL 2
#define DD 1024
#define HH 16
#define DHH 64
#define DFF 4096
#define BB 2
#define TT 2048
#define OV 4096
#define BT (BB*TT)   // 4096

// ---------------- scratch (device globals; no runtime allocation) ----------------
__device__ float g_x  [BT*DD];
__device__ float g_qkv[(size_t)BT*DD];     // V part only (fp32), written by QKV epilogue
__device__ float g_b3a[3*DD];
__device__ float g_b3b[3*DD];
__device__ float g_cos[TT*32];
__device__ float g_sin[TT*32];
// fp16 activations
__device__ __align__(16) __half g_ah[(size_t)BT*DD];    // activation hi [BT,DD]
__device__ __align__(16) __half g_al[(size_t)BT*DD];
__device__ __align__(16) __half g_fh[(size_t)BT*DFF];   // gelu(ff) fp16 [BT,DFF]
// per-layer pre-converted weights (fp16, transposed [N,K])
__device__ __align__(16) __half g_wqkv0[(size_t)3*DD*DD];
__device__ __align__(16) __half g_wqkv1[(size_t)3*DD*DD];
__device__ __align__(16) __half g_wo0[(size_t)DD*DD];
__device__ __align__(16) __half g_wo1[(size_t)DD*DD];
__device__ __align__(16) __half g_w10[(size_t)DFF*DD];
__device__ __align__(16) __half g_w11[(size_t)DFF*DD];
__device__ __align__(16) __half g_w20[(size_t)DFF*DD];
__device__ __align__(16) __half g_w21[(size_t)DFF*DD];
__device__ __align__(16) __half g_wout[(size_t)OV*DD];
// attention split operands (bf16)
__device__ __align__(16) __nv_bfloat16 g_qh[(size_t)BB*HH*TT*DHH];  // [bh][t][d]
__device__ __align__(16) __nv_bfloat16 g_ql[(size_t)BB*HH*TT*DHH];
__device__ __align__(16) __nv_bfloat16 g_kh[(size_t)BB*HH*TT*DHH];
__device__ __align__(16) __nv_bfloat16 g_kl[(size_t)BB*HH*TT*DHH];
__device__ __align__(16) __nv_bfloat16 g_vh[(size_t)BB*HH*DHH*TT];  // [bh][d][t]
__device__ __align__(16) __nv_bfloat16 g_vl[(size_t)BB*HH*DHH*TT];

// ---------------- warp-MMA primitives (baseline PTX; no sm_103a features) ----------
__device__ __forceinline__ uint32_t smem_u32(const void* p) {
    uint32_t a;
    asm("{ .reg .u64 t; cvta.to.shared.u64 t, %1; cvt.u32.u64 %0, t; }" : "=r"(a) : "l"(p));
    return a;
}
__device__ __forceinline__ void ldm4(uint32_t* r, uint32_t addr) {
    asm volatile("ldmatrix.sync.aligned.m8n8.x4.shared.b16 {%0,%1,%2,%3}, [%4];"
                 : "=r"(r[0]), "=r"(r[1]), "=r"(r[2]), "=r"(r[3]) : "r"(addr));
}
// bf16 mma (flash attention)
__device__ __forceinline__ void mma16816(float* d, const uint32_t* a, const uint32_t* b) {
    asm volatile("mma.sync.aligned.m16n8k16.row.col.f32.bf16.bf16.f32 "
                 "{%0,%1,%2,%3}, {%4,%5,%6,%7}, {%8,%9}, {%0,%1,%2,%3};"
                 : "+f"(d[0]), "+f"(d[1]), "+f"(d[2]), "+f"(d[3])
                 : "r"(a[0]), "r"(a[1]), "r"(a[2]), "r"(a[3]), "r"(b[0]), "r"(b[1]));
}
// fp16 mma (GEMMs)
__device__ __forceinline__ void mma16816h(float* d, const uint32_t* a, const uint32_t* b) {
    asm volatile("mma.sync.aligned.m16n8k16.row.col.f32.f16.f16.f32 "
                 "{%0,%1,%2,%3}, {%4,%5,%6,%7}, {%8,%9}, {%0,%1,%2,%3};"
                 : "+f"(d[0]), "+f"(d[1]), "+f"(d[2]), "+f"(d[3])
                 : "r"(a[0]), "r"(a[1]), "r"(a[2]), "r"(a[3]), "r"(b[0]), "r"(b[1]));
}
#define CPA(dst, src) asm volatile("cp.async.cg.shared.global [%0], [%1], 16;" :: "r"(dst), "l"(src))
#define CPC()         asm volatile("cp.async.commit_group;")
#define CPW(n)        asm volatile("cp.async.wait_group %0;" :: "n"(n))

__device__ __forceinline__ uint32_t bfpack(float x, float y) {
    __nv_bfloat162 t;
    t.x = __float2bfloat16_rn(x);
    t.y = __float2bfloat16_rn(y);
    return *(uint32_t*)&t;
}
__device__ __forceinline__ void bfsplit2(float x, float y, uint32_t& hi, uint32_t& lo) {
    __nv_bfloat16 hx = __float2bfloat16_rn(x), hy = __float2bfloat16_rn(y);
    __nv_bfloat162 H; H.x = hx; H.y = hy;
    hi = *(uint32_t*)&H;
    lo = bfpack(x - __bfloat162float(hx), y - __bfloat162float(hy));
}

// ---------------- transpose + fp16 round: W[K,N] -> Bt[N,K] ----------------
__global__ void convT_kernel(const float* __restrict__ W, __half* __restrict__ ht,
                             int K, int N) {
    __shared__ float t[64][33];
    int n0 = blockIdx.x * 32, k0 = blockIdx.y * 64;
    int tx = threadIdx.x & 31, ty = threadIdx.x >> 5;
#pragma unroll
    for (int ky = 0; ky < 64; ky += 8)
        t[ky + ty][tx] = W[(size_t)(k0 + ky + ty) * N + n0 + tx];
    __syncthreads();
    int kl = threadIdx.x & 63, nb = threadIdx.x >> 6;
#pragma unroll
    for (int n = nb; n < 32; n += 4) {
        float v = t[kl][n];
        ht[(size_t)(n0 + n) * K + k0 + kl] = __float2half_rn(v);
    }
}

// ---------------- batched QKV transpose+round (3 weights -> one [3N,K] buffer) --------
__global__ void qkvconvT_kernel(const float* __restrict__ Wq, const float* __restrict__ Wk,
                                const float* __restrict__ Wv, __half* __restrict__ ht) {
    __shared__ float t[64][33];
    const float* W = blockIdx.z == 0 ? Wq : (blockIdx.z == 1 ? Wk : Wv);
    __half* out = ht + (size_t)blockIdx.z * DD * DD;
    int n0 = blockIdx.x * 32, k0 = blockIdx.y * 64;
    int tx = threadIdx.x & 31, ty = threadIdx.x >> 5;
#pragma unroll
    for (int ky = 0; ky < 64; ky += 8)
        t[ky + ty][tx] = W[(size_t)(k0 + ky + ty) * DD + n0 + tx];
    __syncthreads();
    int kl = threadIdx.x & 63, nb = threadIdx.x >> 6;
#pragma unroll
    for (int n = nb; n < 32; n += 4) {
        float v = t[kl][n];
        out[(size_t)(n0 + n) * DD + k0 + kl] = __float2half_rn(v);
    }
}

// ---------------- bias concat ----------------
__global__ void b3_kernel(const float* __restrict__ bq, const float* __restrict__ bk,
                          const float* __restrict__ bv, float* __restrict__ b3) {
    int i = blockIdx.x * 256 + threadIdx.x;
    if (i >= 3 * DD) return;
    b3[i] = i < DD ? bq[i] : (i < 2 * DD ? bk[i - DD] : bv[i - 2 * DD]);
}

// ---------------- fp16 GEMM: 2-stage cp.async, 2 CTAs/SM, 1 or 2 A-passes ------------
// EPI: 0 = bias -> fp32 C
//      1 = bias + GELU -> fp16 Chi only
//      2 = bias + residual -> fp32 C
//      3 = QKV epilogue: Q/K rope+bf16 split, V fp32
#define TROW 72
#define TBYTES (128*TROW*2)      // 18432 per tile
#define GSMEM (2*3*TBYTES)       // 110592 (2 stages x 3 tiles) -> 2 CTAs/SM

template <int EPI, int PASSES>
__global__ __launch_bounds__(256, 2)
void gemm_mma(const __half* __restrict__ Ahi, const __half* __restrict__ Alo,
              const __half* __restrict__ Bw,
              const float* __restrict__ bias, const float* __restrict__ R,
              float* __restrict__ C, __half* __restrict__ Chi,
              __half* __restrict__ Clo,
              const float* __restrict__ CT, const float* __restrict__ ST,
              __nv_bfloat16* __restrict__ Kh, __nv_bfloat16* __restrict__ Kl,
              float* __restrict__ Vb, int M, int N, int K) {
    extern __shared__ __align__(16) char smem[];
    const uint32_t sb = smem_u32(smem);
    int tid = threadIdx.x, lane = tid & 31, w = tid >> 5;
    int wm = w >> 2, wn = w & 3;
    int bm = blockIdx.y << 7, bn = blockIdx.x << 7;

    float acc[4][4][4];
#pragma unroll
    for (int i = 0; i < 4; i++)
#pragma unroll
        for (int j = 0; j < 4; j++)
#pragma unroll
            for (int z = 0; z < 4; z++) acc[i][j][z] = 0.f;

    int lrow = tid >> 3, lseg = tid & 7;
    auto issue = [&](int kc, int st) {
        int kb = kc << 6;
        uint32_t base = sb + st * 3 * TBYTES;
#pragma unroll
        for (int i = 0; i < 4; i++) {
            int row = lrow + i * 32;
            uint32_t so = base + (uint32_t)(row * 144 + lseg * 16);
            size_t ga = (size_t)(bm + row) * K + kb + lseg * 8;
            size_t gb = (size_t)(bn + row) * K + kb + lseg * 8;
            CPA(so, Ahi + ga);
            if (PASSES == 2) CPA(so + TBYTES, Alo + ga);
            CPA(so + 2*TBYTES, Bw + gb);
        }
        CPC();
    };

    const int nch = K >> 6;
    issue(0, 0);

    int a_row = wm * 64 + (lane & 15), a_col = (lane >> 4) << 3;
    int b_row = wn * 32 + ((lane >> 4) << 3) + (lane & 7), b_col = ((lane >> 3) & 1) << 3;
    uint32_t aoff = (uint32_t)(a_row * TROW + a_col) * 2;
    uint32_t boff = (uint32_t)(b_row * TROW + b_col) * 2 + 2 * TBYTES;

    for (int kc = 0; kc < nch; kc++) {
        if (kc + 1 < nch) { issue(kc + 1, (kc + 1) & 1); CPW(1); }
        else              { CPW(0); }
        __syncthreads();

        uint32_t base = sb + (uint32_t)((kc & 1) * 3 * TBYTES);
        uint32_t aoff_h = base + aoff, aoff_l = aoff_h + TBYTES;
        uint32_t boff_b = base + boff;
#pragma unroll
        for (int ks = 0; ks < 4; ks++) {
            uint32_t ah[4][4], bw[8];
            uint32_t kso = (uint32_t)(ks * 32);
#pragma unroll
            for (int mi = 0; mi < 4; mi++)
                ldm4(ah[mi], aoff_h + (uint32_t)(mi * 16 * TROW * 2) + kso);
            ldm4(&bw[0], boff_b + kso);
            ldm4(&bw[4], boff_b + (uint32_t)(16 * TROW * 2) + kso);
#pragma unroll
            for (int mi = 0; mi < 4; mi++)
#pragma unroll
                for (int ni = 0; ni < 4; ni++)
                    mma16816h(acc[mi][ni], ah[mi], &bw[ni * 2]);
            if (PASSES == 2) {
                uint32_t al[4][4];
#pragma unroll
                for (int mi = 0; mi < 4; mi++)
                    ldm4(al[mi], aoff_l + (uint32_t)(mi * 16 * TROW * 2) + kso);
#pragma unroll
                for (int mi = 0; mi < 4; mi++)
#pragma unroll
                    for (int ni = 0; ni < 4; ni++)
                        mma16816h(acc[mi][ni], al[mi], &bw[ni * 2]);
            }
        }
        __syncthreads();
    }

    // ---- epilogue ----
#pragma unroll
    for (int mi = 0; mi < 4; mi++) {
#pragma unroll
        for (int ni = 0; ni < 4; ni++) {
            int r0 = bm + wm * 64 + mi * 16 + (lane >> 2);
            int c0 = bn + wn * 32 + ni * 8 + ((lane & 3) << 1);
#pragma unroll
            for (int half = 0; half < 2; half++) {
                int gm = r0 + half * 8;
                float v0 = acc[mi][ni][half * 2]     + bias[c0];
                float v1 = acc[mi][ni][half * 2 + 1] + bias[c0 + 1];
                if (EPI == 1) {
                    v0 *= normcdff(v0); v1 *= normcdff(v1);
                    __half2 H;
                    H.x = __float2half_rn(v0); H.y = __float2half_rn(v1);
                    *(uint32_t*)&Chi[(size_t)gm * N + c0] = *(uint32_t*)&H;
                } else if (EPI == 3) {
                    int region = c0 >> 10;
                    if (region < 2) {
                        int d = c0 & 63, hhh = (c0 & 1023) >> 6, p = d >> 1;
                        int t = gm & (TT - 1), bb = gm >> 11;
                        float cc = CT[t * 32 + p], ss = ST[t * 32 + p];
                        float o0 = v0 * cc - v1 * ss;
                        float o1 = v0 * ss + v1 * cc;
                        uint32_t hi, lo;
                        bfsplit2(o0, o1, hi, lo);
                        size_t ob = (((size_t)(bb * HH + hhh) * TT) + t) * 64 + d;
                        if (region == 0) {
                            *(uint32_t*)&Chi[ob] = hi;   // qh (bf16 bits)
                            *(uint32_t*)&Clo[ob] = lo;   // ql
                        } else {
                            *(uint32_t*)&Kh[ob] = hi;
                            *(uint32_t*)&Kl[ob] = lo;
                        }
                    } else {
                        float2 o; o.x = v0; o.y = v1;
                        *(float2*)&Vb[(size_t)gm * DD + (c0 & 1023)] = o;
                    }
                } else {
                    if (EPI == 2) {
                        v0 += R[(size_t)gm * N + c0];
                        v1 += R[(size_t)gm * N + c0 + 1];
                    }
                    float2 o; o.x = v0; o.y = v1;
                    *(float2*)&C[(size_t)gm * N + c0] = o;
                }
            }
        }
    }
}

// ---------------- RoPE trig tables (double precision; fast-math-proof) ----------------
__global__ void trig_kernel(float* __restrict__ ct, float* __restrict__ st) {
    int i = blockIdx.x * 256 + threadIdx.x;
    if (i >= TT * 32) return;
    int t = i >> 5, p = i & 31;
    double inv = exp2(-13.287712379549449 * ((double)(2 * p) * (1.0 / 64.0)));
    float invf = (float)inv;
    float angf = (float)((double)t * (double)invf);
    double c, s;
    sincos((double)angf, &s, &c);
    ct[i] = (float)c;
    st[i] = (float)s;
}

// ---------------- embedding ----------------
__global__ void embed_kernel(const int* __restrict__ act, const int* __restrict__ obs,
                             const float* __restrict__ aemb, const float* __restrict__ oemb,
                             const float* __restrict__ temb, float* __restrict__ x) {
    int idx = blockIdx.x * blockDim.x + threadIdx.x;
    if (idx >= BT * DD) return;
    int r = idx / DD, d = idx % DD;
    x[idx] = aemb[(size_t)act[r] * DD + d] + temb[d]
           + oemb[(size_t)obs[r] * DD + d] + temb[DD + d];
}

// ---------------- layernorm -> fp16 (hi always; lo optional) ----------------
template <bool WRITE_LO>
__global__ void ln_kernel(const float* __restrict__ x, const float* __restrict__ g,
                          const float* __restrict__ b, __half* __restrict__ yh,
                          __half* __restrict__ yl) {
    int r = blockIdx.x;
    const float* xr = x + (size_t)r * DD;
    float v[4];
    float s = 0.f, ss = 0.f;
#pragma unroll
    for (int i = 0; i < 4; i++) {
        float t = xr[threadIdx.x + i * 256];
        v[i] = t; s += t; ss += t * t;
    }
#pragma unroll
    for (int o = 16; o > 0; o >>= 1) {
        s  += __shfl_xor_sync(0xffffffffu, s,  o);
        ss += __shfl_xor_sync(0xffffffffu, ss, o);
    }
    __shared__ float rs[8], rss[8];
    int w = threadIdx.x >> 5;
    if ((threadIdx.x & 31) == 0) { rs[w] = s; rss[w] = ss; }
    __syncthreads();
    if (threadIdx.x == 0) {
        float a = 0.f, c = 0.f;
#pragma unroll
        for (int i = 0; i < 8; i++) { a += rs[i]; c += rss[i]; }
        rs[0] = a; rss[0] = c;
    }
    __syncthreads();
    float mean = rs[0] * (1.f / DD);
    float var  = rss[0] * (1.f / DD) - mean * mean;
    float inv  = rsqrtf(var + 1e-5f);
#pragma unroll
    for (int i = 0; i < 4; i++) {
        int d = threadIdx.x + i * 256;
        float val = (v[i] - mean) * inv * g[d] + b[d];
        __half h = __float2half_rn(val);
        yh[(size_t)r * DD + d] = h;
        if (WRITE_LO)
            yl[(size_t)r * DD + d] = __float2half_rn(val - __half2float(h));
    }
}

// ---------------- V split + transpose into [bh][d][t] (from fp32 V buffer) -----------
__global__ void vsplit_kernel(const float* __restrict__ V,
                              __nv_bfloat16* __restrict__ vh, __nv_bfloat16* __restrict__ vl) {
    __shared__ float ts[32][33];
    int t0 = blockIdx.x * 32, d0 = blockIdx.y * 32, b = blockIdx.z;
    int tx = threadIdx.x & 31, ty = threadIdx.x >> 5;
#pragma unroll
    for (int i = ty; i < 32; i += 8)
        ts[i][tx] = V[((size_t)b * TT + t0 + i) * DD + d0 + tx];
    __syncthreads();
    int hh = d0 >> 6, dl0 = d0 & 63;
#pragma unroll
    for (int i = ty; i < 32; i += 8) {
        float v = ts[tx][i];
        size_t o = ((size_t)(b * HH + hh) * 64 + dl0 + i) * TT + t0 + tx;
        __nv_bfloat16 h = __float2bfloat16_rn(v);
        vh[o] = h;
        vl[o] = __float2bfloat16_rn(v - __bfloat162float(h));
    }
}

// ================= fused flash attention (bf16 3-pass internally; fp16 output) ========
#define FQ_H 0
#define FQ_L 18432
#define FK_H(st) (36864 + (st)*36864)
#define FK_L(st) (FK_H(st) + 18432)
#define FV_H(st) (110592 + (st)*34816)
#define FV_L(st) (FV_H(st) + 17408)
#define FSMEM 180224

__global__ __launch_bounds__(256)
void flash_attn(const __nv_bfloat16* __restrict__ Qh, const __nv_bfloat16* __restrict__ Ql,
                const __nv_bfloat16* __restrict__ Kh, const __nv_bfloat16* __restrict__ Kl,
                const __nv_bfloat16* __restrict__ Vh, const __nv_bfloat16* __restrict__ Vl,
                __half* __restrict__ Oh) {
    int qt = gridDim.x - 1 - blockIdx.x;
    int bh = blockIdx.y;
    int b = bh >> 4, hh = bh & 15;
    extern __shared__ __align__(16) char smem[];
    const uint32_t sb = smem_u32(smem);
    int tid = threadIdx.x, lane = tid & 31, w = tid >> 5;

    {
        int row = tid >> 1, segb = (tid & 1) * 4;
        size_t qg = ((size_t)bh * TT + qt * 128 + row) * 64 + segb * 8;
#pragma unroll
        for (int s = 0; s < 4; s++) {
            uint32_t so = (uint32_t)(row * 144 + (segb + s) * 16);
            *(uint4*)(smem + FQ_H + so) = *(const uint4*)(Qh + qg + s * 8);
            *(uint4*)(smem + FQ_L + so) = *(const uint4*)(Ql + qg + s * 8);
        }
    }

    auto issueKV = [&](int kt, int st) {
        int row = tid >> 1, segb = (tid & 1) * 4;
        size_t kg = ((size_t)bh * TT + kt * 128 + row) * 64 + segb * 8;
#pragma unroll
        for (int s = 0; s < 4; s++) {
            uint32_t so = (uint32_t)(row * 144 + (segb + s) * 16);
            CPA(sb + FK_H(st) + so, Kh + kg + s * 8);
            CPA(sb + FK_L(st) + so, Kl + kg + s * 8);
        }
        int vrow = tid >> 2, vsegb = (tid & 3) * 4;
        size_t vg = ((size_t)bh * 64 + vrow) * TT + kt * 128 + vsegb * 8;
#pragma unroll
        for (int s = 0; s < 4; s++) {
            uint32_t so = (uint32_t)(vrow * 272 + (vsegb + s) * 16);
            CPA(sb + FV_H(st) + so, Vh + vg + s * 8);
            CPA(sb + FV_L(st) + so, Vl + vg + s * 8);
        }
        CPC();
    };
    issueKV(0, 0);
    __syncthreads();

    uint32_t qfh[4][4], qfl[4][4];
    {
        int a_row = w * 16 + (lane & 15), a_col = (lane >> 4) << 3;
        uint32_t qa = (uint32_t)(a_row * 144 + a_col * 2);
#pragma unroll
        for (int ks = 0; ks < 4; ks++) {
            ldm4(qfh[ks], sb + FQ_H + qa + ks * 32);
            ldm4(qfl[ks], sb + FQ_L + qa + ks * 32);
        }
    }

    float m0 = -3.0e38f, m1 = -3.0e38f, l0 = 0.f, l1 = 0.f;
    float O[8][4];
#pragma unroll
    for (int i = 0; i < 8; i++)
#pragma unroll
        for (int z = 0; z < 4; z++) O[i][z] = 0.f;

    int b_rowi = ((lane >> 4) << 3) + (lane & 7);
    int b_colb = (((lane >> 3) & 1) << 3) * 2;

    for (int kt = 0; kt <= qt; kt++) {
        if (kt < qt) { issueKV(kt + 1, (kt + 1) & 1); CPW(1); }
        else         { CPW(0); }
        __syncthreads();
        uint32_t kb_h = sb + FK_H(kt & 1), kb_l = sb + FK_L(kt & 1);
        uint32_t vb_h = sb + FV_H(kt & 1), vb_l = sb + FV_L(kt & 1);

        float P[16][4];
#pragma unroll
        for (int i = 0; i < 16; i++)
#pragma unroll
            for (int z = 0; z < 4; z++) P[i][z] = 0.f;
#pragma unroll
        for (int ks = 0; ks < 4; ks++) {
            uint32_t kso = (uint32_t)(ks * 32);
#pragma unroll
            for (int nb = 0; nb < 8; nb++) {
                uint32_t addr = (uint32_t)((nb * 16 + b_rowi) * 144) + b_colb + kso;
                uint32_t kf[4], kfl[4];
                ldm4(kf, kb_h + addr);
                mma16816(P[2*nb],   qfh[ks], &kf[0]);
                mma16816(P[2*nb+1], qfh[ks], &kf[2]);
                mma16816(P[2*nb],   qfl[ks], &kf[0]);
                mma16816(P[2*nb+1], qfl[ks], &kf[2]);
                ldm4(kfl, kb_l + addr);
                mma16816(P[2*nb],   qfh[ks], &kfl[0]);
                mma16816(P[2*nb+1], qfh[ks], &kfl[2]);
            }
        }
#pragma unroll
        for (int i = 0; i < 16; i++)
#pragma unroll
            for (int z = 0; z < 4; z++) P[i][z] *= 0.125f;
        if (kt == qt) {
            int r0 = w * 16 + (lane >> 2);
#pragma unroll
            for (int i = 0; i < 16; i++) {
#pragma unroll
                for (int z = 0; z < 4; z++) {
                    int col = i * 8 + ((lane & 3) << 1) + (z & 1);
                    int row = r0 + ((z >> 1) << 3);
                    if (col > row) P[i][z] = -3.0e38f;
                }
            }
        }
        float mx0 = -3.0e38f, mx1 = -3.0e38f;
#pragma unroll
        for (int i = 0; i < 16; i++) {
            mx0 = fmaxf(mx0, fmaxf(P[i][0], P[i][1]));
            mx1 = fmaxf(mx1, fmaxf(P[i][2], P[i][3]));
        }
        mx0 = fmaxf(mx0, __shfl_xor_sync(0xffffffffu, mx0, 1));
        mx0 = fmaxf(mx0, __shfl_xor_sync(0xffffffffu, mx0, 2));
        mx1 = fmaxf(mx1, __shfl_xor_sync(0xffffffffu, mx1, 1));
        mx1 = fmaxf(mx1, __shfl_xor_sync(0xffffffffu, mx1, 2));
        float mn0 = fmaxf(m0, mx0), mn1 = fmaxf(m1, mx1);
        float al0 = expf(m0 - mn0), al1 = expf(m1 - mn1);
        m0 = mn0; m1 = mn1;
        float s0 = 0.f, s1 = 0.f;
#pragma unroll
        for (int i = 0; i < 16; i++) {
            P[i][0] = expf(P[i][0] - m0); s0 += P[i][0];
            P[i][1] = expf(P[i][1] - m0); s0 += P[i][1];
            P[i][2] = expf(P[i][2] - m1); s1 += P[i][2];
            P[i][3] = expf(P[i][3] - m1); s1 += P[i][3];
        }
        s0 += __shfl_xor_sync(0xffffffffu, s0, 1);
        s0 += __shfl_xor_sync(0xffffffffu, s0, 2);
        s1 += __shfl_xor_sync(0xffffffffu, s1, 1);
        s1 += __shfl_xor_sync(0xffffffffu, s1, 2);
        l0 = l0 * al0 + s0;
        l1 = l1 * al1 + s1;
#pragma unroll
        for (int i = 0; i < 8; i++) {
            O[i][0] *= al0; O[i][1] *= al0;
            O[i][2] *= al1; O[i][3] *= al1;
        }
#pragma unroll
        for (int ks = 0; ks < 8; ks++) {
            uint32_t pah[4], pal[4];
            bfsplit2(P[2*ks][0],   P[2*ks][1],   pah[0], pal[0]);
            bfsplit2(P[2*ks][2],   P[2*ks][3],   pah[1], pal[1]);
            bfsplit2(P[2*ks+1][0], P[2*ks+1][1], pah[2], pal[2]);
            bfsplit2(P[2*ks+1][2], P[2*ks+1][3], pah[3], pal[3]);
            uint32_t kso = (uint32_t)(ks * 32);
#pragma unroll
            for (int nb = 0; nb < 4; nb++) {
                uint32_t addr = (uint32_t)((nb * 16 + b_rowi) * 272) + b_colb + kso;
                uint32_t vf[4], vfl[4];
                ldm4(vf, vb_h + addr);
                mma16816(O[2*nb],   pah, &vf[0]);
                mma16816(O[2*nb+1], pah, &vf[2]);
                mma16816(O[2*nb],   pal, &vf[0]);
                mma16816(O[2*nb+1], pal, &vf[2]);
                ldm4(vfl, vb_l + addr);
                mma16816(O[2*nb],   pah, &vfl[0]);
                mma16816(O[2*nb+1], pah, &vfl[2]);
            }
        }
        __syncthreads();
    }

    float i0 = 1.f / l0, i1 = 1.f / l1;
    int r0 = qt * 128 + w * 16 + (lane >> 2);
    int c0 = hh * 64 + ((lane & 3) << 1);
#pragma unroll
    for (int nj = 0; nj < 8; nj++) {
        int cc = c0 + nj * 8;
        __half2 H;
        H.x = __float2half_rn(O[nj][0] * i0);
        H.y = __float2half_rn(O[nj][1] * i0);
        *(uint32_t*)&Oh[((size_t)b * TT + r0) * DD + cc] = *(uint32_t*)&H;
        H.x = __float2half_rn(O[nj][2] * i1);
        H.y = __float2half_rn(O[nj][3] * i1);
        *(uint32_t*)&Oh[((size_t)b * TT + r0 + 8) * DD + cc] = *(uint32_t*)&H;
    }
}

// ---------------- host-side helpers ----------------
template <int EPI, int PASSES>
static void gemm(const __half* ah, const __half* al, const __half* bw,
                 const float* bias, const float* R, float* C,
                 __half* Chi, __half* Clo,
                 const float* ct, const float* st,
                 __nv_bfloat16* kh, __nv_bfloat16* kl, float* vb,
                 int M, int N, int K) {
    static bool cfg = false;
    if (!cfg) {
        cudaFuncSetAttribute(gemm_mma<EPI, PASSES>, cudaFuncAttributeMaxDynamicSharedMemorySize, GSMEM);
        cfg = true;
    }
    gemm_mma<EPI, PASSES><<<dim3(N / 128, M / 128), 256, GSMEM>>>(
        ah, al, bw, bias, R, C, Chi, Clo, ct, st, kh, kl, vb, M, N, K);
}

// ---------------- launch sequence ----------------
extern "C" void kernel_launch(void* const* d_in, const int* in_sizes, int n_in,
                              void* d_out, int out_size) {
    const int*   actions = (const int*)d_in[0];
    const int*   observ  = (const int*)d_in[1];
    const float* aemb    = (const float*)d_in[2];
    const float* oemb    = (const float*)d_in[3];
    const float* temb    = (const float*)d_in[4];
    const float* Wq      = (const float*)d_in[5];
    const float* bq      = (const float*)d_in[6];
    const float* Wk      = (const float*)d_in[7];
    const float* bk      = (const float*)d_in[8];
    const float* Wv      = (const float*)d_in[9];
    const float* bv      = (const float*)d_in[10];
    const float* Wo      = (const float*)d_in[11];
    const float* bo      = (const float*)d_in[12];
    const float* ln1_g   = (const float*)d_in[13];
    const float* ln1_b   = (const float*)d_in[14];
    const float* ln2_g   = (const float*)d_in[15];
    const float* ln2_b   = (const float*)d_in[16];
    const float* W1      = (const float*)d_in[17];
    const float* b1      = (const float*)d_in[18];
    const float* W2      = (const float*)d_in[19];
    const float* b2      = (const float*)d_in[20];
    const float* out_g   = (const float*)d_in[21];
    const float* out_b   = (const float*)d_in[22];
    const float* Wout    = (const float*)d_in[23];
    const float* bout    = (const float*)d_in[24];

    float *x, *qkv, *ct, *st;
    float *b3[2];
    __half *ah, *al, *fh;
    __half *wqkv[2], *wo[2], *w1[2], *w2[2], *wout;
    __nv_bfloat16 *qh, *ql, *kh, *kl, *vh, *vl;
    cudaGetSymbolAddress((void**)&x,   g_x);
    cudaGetSymbolAddress((void**)&qkv, g_qkv);
    cudaGetSymbolAddress((void**)&b3[0], g_b3a);
    cudaGetSymbolAddress((void**)&b3[1], g_b3b);
    cudaGetSymbolAddress((void**)&ct,  g_cos);
    cudaGetSymbolAddress((void**)&st,  g_sin);
    cudaGetSymbolAddress((void**)&ah,  g_ah);
    cudaGetSymbolAddress((void**)&al,  g_al);
    cudaGetSymbolAddress((void**)&fh,  g_fh);
    cudaGetSymbolAddress((void**)&wqkv[0], g_wqkv0);
    cudaGetSymbolAddress((void**)&wqkv[1], g_wqkv1);
    cudaGetSymbolAddress((void**)&wo[0], g_wo0);
    cudaGetSymbolAddress((void**)&wo[1], g_wo1);
    cudaGetSymbolAddress((void**)&w1[0], g_w10);
    cudaGetSymbolAddress((void**)&w1[1], g_w11);
    cudaGetSymbolAddress((void**)&w2[0], g_w20);
    cudaGetSymbolAddress((void**)&w2[1], g_w21);
    cudaGetSymbolAddress((void**)&wout, g_wout);
    cudaGetSymbolAddress((void**)&qh,  g_qh);
    cudaGetSymbolAddress((void**)&ql,  g_ql);
    cudaGetSymbolAddress((void**)&kh,  g_kh);
    cudaGetSymbolAddress((void**)&kl,  g_kl);
    cudaGetSymbolAddress((void**)&vh,  g_vh);
    cudaGetSymbolAddress((void**)&vl,  g_vl);

    static bool fcfg = false;
    static cudaStream_t s2 = nullptr;
    static cudaEvent_t evF, evW[9];
    if (!fcfg) {
        cudaFuncSetAttribute(flash_attn, cudaFuncAttributeMaxDynamicSharedMemorySize, FSMEM);
        cudaStreamCreateWithFlags(&s2, cudaStreamNonBlocking);
        cudaEventCreateWithFlags(&evF, cudaEventDisableTiming);
        for (int i = 0; i < 9; i++) cudaEventCreateWithFlags(&evW[i], cudaEventDisableTiming);
        fcfg = true;
    }

    // ---- fork: all weight conversions + trig + bias concats on side stream ----
    cudaEventRecord(evF, 0);
    cudaStreamWaitEvent(s2, evF, 0);
    trig_kernel<<<(TT * 32 + 255) / 256, 256, 0, s2>>>(ct, st);
    for (int i = 0; i < LL; i++) {
        b3_kernel<<<12, 256, 0, s2>>>(bq + (size_t)i * DD, bk + (size_t)i * DD,
                                      bv + (size_t)i * DD, b3[i]);
        qkvconvT_kernel<<<dim3(DD / 32, DD / 64, 3), 256, 0, s2>>>(
            Wq + (size_t)i * DD * DD, Wk + (size_t)i * DD * DD,
            Wv + (size_t)i * DD * DD, wqkv[i]);
        cudaEventRecord(evW[i * 4 + 0], s2);
        convT_kernel<<<dim3(DD / 32, DD / 64), 256, 0, s2>>>(Wo + (size_t)i * DD * DD, wo[i], DD, DD);
        cudaEventRecord(evW[i * 4 + 1], s2);
        convT_kernel<<<dim3(DFF / 32, DD / 64), 256, 0, s2>>>(W1 + (size_t)i * DD * DFF, w1[i], DD, DFF);
        cudaEventRecord(evW[i * 4 + 2], s2);
        convT_kernel<<<dim3(DD / 32, DFF / 64), 256, 0, s2>>>(W2 + (size_t)i * DFF * DD, w2[i], DFF, DD);
        cudaEventRecord(evW[i * 4 + 3], s2);
    }
    convT_kernel<<<dim3(OV / 32, DD / 64), 256, 0, s2>>>(Wout, wout, DD, OV);
    cudaEventRecord(evW[8], s2);

    // ---- main stream: forward pass ----
    embed_kernel<<<(BT * DD + 255) / 256, 256>>>(actions, observ, aemb, oemb, temb, x);

    for (int i = 0; i < LL; i++) {
        ln_kernel<true><<<BT, 256>>>(x, ln1_g + (size_t)i * DD, ln1_b + (size_t)i * DD, ah, al);

        cudaStreamWaitEvent(0, evW[i * 4 + 0], 0);
        gemm<3, 2>(ah, al, wqkv[i], b3[i], nullptr, nullptr,
                   (__half*)qh, (__half*)ql, ct, st, kh, kl, qkv, BT, 3 * DD, DD);

        vsplit_kernel<<<dim3(TT / 32, DD / 32, BB), 256>>>(qkv, vh, vl);

        flash_attn<<<dim3(TT / 128, BB * HH), 256, FSMEM>>>(qh, ql, kh, kl, vh, vl, ah);

        cudaStreamWaitEvent(0, evW[i * 4 + 1], 0);
        gemm<2, 1>(ah, nullptr, wo[i], bo + (size_t)i * DD, x, x,
                   nullptr, nullptr, nullptr, nullptr, nullptr, nullptr, nullptr, BT, DD, DD);

        ln_kernel<false><<<BT, 256>>>(x, ln2_g + (size_t)i * DD, ln2_b + (size_t)i * DD, ah, nullptr);
        cudaStreamWaitEvent(0, evW[i * 4 + 2], 0);
        gemm<1, 1>(ah, nullptr, w1[i], b1 + (size_t)i * DFF, nullptr, nullptr,
                   fh, nullptr, nullptr, nullptr, nullptr, nullptr, nullptr, BT, DFF, DD);

        cudaStreamWaitEvent(0, evW[i * 4 + 3], 0);
        gemm<2, 1>(fh, nullptr, w2[i], b2 + (size_t)i * DD, x, x,
                   nullptr, nullptr, nullptr, nullptr, nullptr, nullptr, nullptr, BT, DD, DFF);
    }

    ln_kernel<false><<<BT, 256>>>(x, out_g, out_b, ah, nullptr);
    cudaStreamWaitEvent(0, evW[8], 0);
    gemm<0, 1>(ah, nullptr, wout, bout, nullptr, (float*)d_out,
               nullptr, nullptr, nullptr, nullptr, nullptr, nullptr, nullptr, BT, OV, DD);
}